// round 3
// baseline (speedup 1.0000x reference)
#include <cuda_runtime.h>
#include <math.h>

#define NNODES 262144
#define NPS 32
#define TS 8192
#define BB 64
#define LL 128
#define EE 128
#define HH 128
#define DLN 20
#define AP 132   // padded smem pitch

// scratch (device globals: no allocation allowed)
__device__ float g_stmt_h[TS * EE];        // 4 MB
__device__ float g_gi[TS * 768];           // 25 MB  [row][f gates 0..383 | b gates 384..767]
__device__ float g_pooled[BB * 256];

// subtree sizes of the 32-node binary heap (children of p: 2p+1, 2p+2 if <32)
__constant__ int c_csz[32] = {32,16,15,8,7,7,7,4,3,3,3,3,3,3,3,2,
                              1,1,1,1,1,1,1,1,1,1,1,1,1,1,1,1};

typedef unsigned long long ull;

__device__ __forceinline__ void ffma2(ull& d, ull a, ull b){
    asm("fma.rn.f32x2 %0, %1, %2, %0;" : "+l"(d) : "l"(a), "l"(b));
}
__device__ __forceinline__ ull dup2(float x){
    ull r; asm("mov.b64 %0, {%1, %1};" : "=l"(r) : "f"(x)); return r;
}
__device__ __forceinline__ float2 ull2f2(ull v){
    float2 f; asm("mov.b64 {%0, %1}, %2;" : "=f"(f.x), "=f"(f.y) : "l"(v)); return f;
}

// ---------------------------------------------------------------------------
// K1: per 4 statements: gather 32 embeddings each, subtree-sum in smem,
//     GEMM (128x128x128) vs Wc^T, add c(v)*bc, column-max over nodes, relu.
// ---------------------------------------------------------------------------
__global__ __launch_bounds__(256) void k1_stmt(
    const float* __restrict__ emb, const float* __restrict__ Wc,
    const float* __restrict__ bc, const int* __restrict__ toks_g)
{
    extern __shared__ float sm[];
    float* As = sm;              // [128 k][AP] : As[k][row] = subtree-summed emb
    float* Bs = sm + 128 * AP;   // [128 k][AP] : Bs[k][j]  = Wc[j][k]
    __shared__ int toks[128];
    __shared__ int smax[4 * 128];
    __shared__ float bcs[128];

    const int t = threadIdx.x;
    const int s0 = blockIdx.x * 4;

    if (t < 128) { toks[t] = toks_g[s0 * NPS + t] + 1; bcs[t] = bc[t]; }
    smax[t] = 0; smax[256 + t] = 0;
    __syncthreads();

    // load Wc transposed (lanes over j -> conflict-free STS)
    #pragma unroll
    for (int i = 0; i < 16; i++) {
        int idx = i * 256 + t;
        int j = idx & 127, kq = idx >> 7;
        float4 w = *(const float4*)(Wc + j * 128 + kq * 4);
        Bs[(kq * 4 + 0) * AP + j] = w.x;
        Bs[(kq * 4 + 1) * AP + j] = w.y;
        Bs[(kq * 4 + 2) * AP + j] = w.z;
        Bs[(kq * 4 + 3) * AP + j] = w.w;
    }
    // gather embeddings (transposed store)
    #pragma unroll
    for (int i = 0; i < 16; i++) {
        int idx = i * 256 + t;
        int r = idx & 127, kq = idx >> 7;
        float4 v = *(const float4*)(emb + toks[r] * 128 + kq * 4);
        As[(kq * 4 + 0) * AP + r] = v.x;
        As[(kq * 4 + 1) * AP + r] = v.y;
        As[(kq * 4 + 2) * AP + r] = v.z;
        As[(kq * 4 + 3) * AP + r] = v.w;
    }
    __syncthreads();

    // subtree sums, bottom-up by TRUE heap level (node j at level floor(log2(j+1))):
    // L4 parent {15} (child 31), L3 parents {7..14}, L2 {3..6}, L1 {1..2}, L0 {0}.
    // (Processing 15 together with 7..14 raced: 15 is a child of 7.)
    {
        // L4: p = 15, single child 31
        for (int idx = t; idx < 4 * 128; idx += 256) {
            int k = idx & 127, tt = idx >> 7;
            int base = k * AP + tt * 32;
            As[base + 15] += As[base + 31];
        }
        __syncthreads();
        // L3: p = 7..14
        for (int idx = t; idx < 8 * 4 * 128; idx += 256) {
            int k = idx & 127, q = idx >> 7, tt = q & 3, p = 7 + (q >> 2);
            int base = k * AP + tt * 32;
            As[base + p] += As[base + 2 * p + 1] + As[base + 2 * p + 2];
        }
        __syncthreads();
        // L2: p = 3..6
        for (int idx = t; idx < 4 * 4 * 128; idx += 256) {
            int k = idx & 127, q = idx >> 7, tt = q & 3, p = 3 + (q >> 2);
            int base = k * AP + tt * 32;
            As[base + p] += As[base + 2 * p + 1] + As[base + 2 * p + 2];
        }
        __syncthreads();
        // L1: p = 1..2
        for (int idx = t; idx < 2 * 4 * 128; idx += 256) {
            int k = idx & 127, q = idx >> 7, tt = q & 3, p = 1 + (q >> 2);
            int base = k * AP + tt * 32;
            As[base + p] += As[base + 2 * p + 1] + As[base + 2 * p + 2];
        }
        __syncthreads();
        // L0: p = 0
        for (int idx = t; idx < 1 * 4 * 128; idx += 256) {
            int k = idx & 127, q = idx >> 7, tt = q & 3;
            int base = k * AP + tt * 32;
            As[base + 0] += As[base + 1] + As[base + 2];
        }
        __syncthreads();
    }

    // GEMM: out[r][j] = sum_k As[k][r] * Bs[k][j]  (FFMA2 packed, 8x8 micro)
    const int tx = t & 15, ty = t >> 4;
    const int r0 = ty * 4, r1 = 64 + ty * 4;
    const int c0 = tx * 4, c1 = 64 + tx * 4;
    ull acc[8][4];
    #pragma unroll
    for (int ri = 0; ri < 8; ri++)
        #pragma unroll
        for (int cp = 0; cp < 4; cp++) acc[ri][cp] = 0ULL;

    #pragma unroll 8
    for (int k = 0; k < 128; k++) {
        const float* ar = As + k * AP;
        float4 a0 = *(const float4*)(ar + r0);
        float4 a1 = *(const float4*)(ar + r1);
        const float* br = Bs + k * AP;
        ulonglong2 b0 = *(const ulonglong2*)(br + c0);
        ulonglong2 b1 = *(const ulonglong2*)(br + c1);
        float a[8] = {a0.x, a0.y, a0.z, a0.w, a1.x, a1.y, a1.z, a1.w};
        #pragma unroll
        for (int ri = 0; ri < 8; ri++) {
            ull ad = dup2(a[ri]);
            ffma2(acc[ri][0], ad, b0.x);
            ffma2(acc[ri][1], ad, b0.y);
            ffma2(acc[ri][2], ad, b1.x);
            ffma2(acc[ri][3], ad, b1.y);
        }
    }

    // epilogue: + c(v)*bc[j], per-statement column max (int atomicMax, init 0 == relu)
    const int sA = (ty >> 3), sB = 2 + (ty >> 3);
    #pragma unroll
    for (int cp = 0; cp < 4; cp++) {
        int jb = (cp < 2) ? (c0 + cp * 2) : (c1 + (cp - 2) * 2);
        float blo = bcs[jb], bhi = bcs[jb + 1];
        float mAlo = -3e38f, mAhi = -3e38f, mBlo = -3e38f, mBhi = -3e38f;
        #pragma unroll
        for (int ri = 0; ri < 4; ri++) {
            float cs = (float)c_csz[(r0 + ri) & 31];  // same node id for both row groups
            float2 fa = ull2f2(acc[ri][cp]);
            mAlo = fmaxf(mAlo, fa.x + cs * blo);
            mAhi = fmaxf(mAhi, fa.y + cs * bhi);
            float2 fb = ull2f2(acc[4 + ri][cp]);
            mBlo = fmaxf(mBlo, fb.x + cs * blo);
            mBhi = fmaxf(mBhi, fb.y + cs * bhi);
        }
        atomicMax(&smax[sA * 128 + jb],     __float_as_int(mAlo));
        atomicMax(&smax[sA * 128 + jb + 1], __float_as_int(mAhi));
        atomicMax(&smax[sB * 128 + jb],     __float_as_int(mBlo));
        atomicMax(&smax[sB * 128 + jb + 1], __float_as_int(mBhi));
    }
    __syncthreads();
    g_stmt_h[s0 * 128 + t]       = __int_as_float(smax[t]);
    g_stmt_h[s0 * 128 + 256 + t] = __int_as_float(smax[256 + t]);
}

// ---------------------------------------------------------------------------
// K1b: gi = stmt_h[8192,128] @ [Wih_f;Wih_b]^T  -> g_gi[8192][768]
// ---------------------------------------------------------------------------
__global__ __launch_bounds__(256) void k1b_gi(
    const float* __restrict__ Wih_f, const float* __restrict__ Wih_b)
{
    extern __shared__ float sm[];
    float* As = sm;
    float* Bs = sm + 128 * AP;
    const int t = threadIdx.x;
    const int row0 = blockIdx.x * 128;
    const int cbase = blockIdx.y * 128;
    const float* Wsel = (cbase < 384) ? (Wih_f + cbase * 128)
                                      : (Wih_b + (cbase - 384) * 128);
    #pragma unroll
    for (int i = 0; i < 16; i++) {
        int idx = i * 256 + t;
        int j = idx & 127, kq = idx >> 7;
        float4 w = *(const float4*)(Wsel + j * 128 + kq * 4);
        Bs[(kq * 4 + 0) * AP + j] = w.x;
        Bs[(kq * 4 + 1) * AP + j] = w.y;
        Bs[(kq * 4 + 2) * AP + j] = w.z;
        Bs[(kq * 4 + 3) * AP + j] = w.w;
        float4 a = *(const float4*)(g_stmt_h + (row0 + j) * 128 + kq * 4);
        As[(kq * 4 + 0) * AP + j] = a.x;
        As[(kq * 4 + 1) * AP + j] = a.y;
        As[(kq * 4 + 2) * AP + j] = a.z;
        As[(kq * 4 + 3) * AP + j] = a.w;
    }
    __syncthreads();

    const int tx = t & 15, ty = t >> 4;
    const int r0 = ty * 4, r1 = 64 + ty * 4;
    const int c0 = tx * 4, c1 = 64 + tx * 4;
    ull acc[8][4];
    #pragma unroll
    for (int ri = 0; ri < 8; ri++)
        #pragma unroll
        for (int cp = 0; cp < 4; cp++) acc[ri][cp] = 0ULL;

    #pragma unroll 8
    for (int k = 0; k < 128; k++) {
        const float* ar = As + k * AP;
        float4 a0 = *(const float4*)(ar + r0);
        float4 a1 = *(const float4*)(ar + r1);
        const float* br = Bs + k * AP;
        ulonglong2 b0 = *(const ulonglong2*)(br + c0);
        ulonglong2 b1 = *(const ulonglong2*)(br + c1);
        float a[8] = {a0.x, a0.y, a0.z, a0.w, a1.x, a1.y, a1.z, a1.w};
        #pragma unroll
        for (int ri = 0; ri < 8; ri++) {
            ull ad = dup2(a[ri]);
            ffma2(acc[ri][0], ad, b0.x);
            ffma2(acc[ri][1], ad, b0.y);
            ffma2(acc[ri][2], ad, b1.x);
            ffma2(acc[ri][3], ad, b1.y);
        }
    }
    #pragma unroll
    for (int ri = 0; ri < 8; ri++) {
        int row = row0 + ((ri < 4) ? (r0 + ri) : (r1 + ri - 4));
        #pragma unroll
        for (int cp = 0; cp < 4; cp++) {
            int jb = (cp < 2) ? (c0 + cp * 2) : (c1 + (cp - 2) * 2);
            float2 f = ull2f2(acc[ri][cp]);
            *(float2*)(g_gi + row * 768 + cbase + jb) = f;
        }
    }
}

// ---------------------------------------------------------------------------
// K2: GRU recurrence. 128 CTAs, one per (batch, dir). Whh rows in registers
//     (768 thr x 64 wt), h broadcast from smem, gi double-buffered.
// ---------------------------------------------------------------------------
__global__ __launch_bounds__(768) void k2_gru(
    const float* __restrict__ Whh_f, const float* __restrict__ bih_f, const float* __restrict__ bhh_f,
    const float* __restrict__ Whh_b, const float* __restrict__ bih_b, const float* __restrict__ bhh_b)
{
    __shared__ float h_s[128];
    __shared__ float part[768];
    __shared__ float gi_buf[2][384];

    const int t = threadIdx.x;
    const int b = blockIdx.x >> 1, dir = blockIdx.x & 1;
    const float* Whh = dir ? Whh_b : Whh_f;
    const float* bih = dir ? bih_b : bih_f;
    const float* bhh = dir ? bhh_b : bhh_f;
    const int goff = dir * 384;

    const int j = t % 384;
    const int half = t / 384;

    ull w2[32];
    {
        const ulonglong2* wp = (const ulonglong2*)(Whh + j * 128 + half * 64);
        #pragma unroll
        for (int i = 0; i < 16; i++) { ulonglong2 v = wp[i]; w2[2*i] = v.x; w2[2*i+1] = v.y; }
    }
    float bir = 0, biz = 0, bin = 0, bhr = 0, bhz = 0, bhn = 0;
    float hmax = -3e38f;
    if (t < 128) {
        bir = bih[t]; biz = bih[128 + t]; bin = bih[256 + t];
        bhr = bhh[t]; bhz = bhh[128 + t]; bhn = bhh[256 + t];
        h_s[t] = 0.f;
    }
    {
        int r0 = b * LL + (dir ? (LL - 1) : 0);
        if (t < 384) gi_buf[0][t] = g_gi[r0 * 768 + goff + t];
    }
    __syncthreads();

    int cur = 0;
    for (int l = 0; l < LL; l++) {
        float pre = 0.f;
        if (t >= 384 && l + 1 < LL) {
            int rn = b * LL + (dir ? (LL - 2 - l) : (l + 1));
            pre = g_gi[rn * 768 + goff + (t - 384)];
        }
        // matvec: part[t] = sum over half-range of Whh[j,:]*h
        ull acc = 0ULL;
        const ulonglong2* hp = (const ulonglong2*)(h_s + half * 64);
        #pragma unroll
        for (int i = 0; i < 16; i++) {
            ulonglong2 hv = hp[i];
            ffma2(acc, w2[2*i],   hv.x);
            ffma2(acc, w2[2*i+1], hv.y);
        }
        float2 pf = ull2f2(acc);
        part[t] = pf.x + pf.y;
        __syncthreads();

        if (t < 128) {
            float ghr = part[t]       + part[384 + t]       + bhr;
            float ghz = part[128 + t] + part[384 + 128 + t] + bhz;
            float ghn = part[256 + t] + part[384 + 256 + t] + bhn;
            float gir = gi_buf[cur][t]       + bir;
            float giz = gi_buf[cur][128 + t] + biz;
            float gin = gi_buf[cur][256 + t] + bin;
            float r = 1.f / (1.f + expf(-(gir + ghr)));
            float z = 1.f / (1.f + expf(-(giz + ghz)));
            float n = tanhf(gin + r * ghn);
            float hnew = (1.f - z) * n + z * h_s[t];
            h_s[t] = hnew;
            hmax = fmaxf(hmax, hnew);
        }
        if (t >= 384 && l + 1 < LL) gi_buf[cur ^ 1][t - 384] = pre;
        __syncthreads();
        cur ^= 1;
    }
    if (t < 128) g_pooled[b * 256 + dir * 128 + t] = hmax;
}

// ---------------------------------------------------------------------------
// K3: pooled @ lin_W^T + lin_b  and  doc attention. One CTA per batch.
// ---------------------------------------------------------------------------
__global__ __launch_bounds__(128) void k3_out(
    const float* __restrict__ emb, const float* __restrict__ Wb,
    const float* __restrict__ linW, const float* __restrict__ linb,
    const int* __restrict__ doc, float* __restrict__ out)
{
    __shared__ float demb[DLN * 128];
    __shared__ float h0[128];
    __shared__ float u[128];
    __shared__ float sc[DLN];
    __shared__ float ex[DLN];
    __shared__ float pool[256];
    __shared__ int dti[DLN];

    const int t = threadIdx.x, b = blockIdx.x;
    if (t < DLN) dti[t] = doc[b * DLN + t] + 1;
    pool[t] = g_pooled[b * 256 + t];
    pool[128 + t] = g_pooled[b * 256 + 128 + t];
    __syncthreads();
    for (int l = 0; l < DLN; l++) demb[l * 128 + t] = emb[dti[l] * 128 + t];
    __syncthreads();
    {
        float s = 0.f;
        for (int l = 0; l < DLN; l++) s += demb[l * 128 + t];
        h0[t] = s / (float)DLN;
    }
    __syncthreads();
    {
        float s = 0.f;
        const float* wr = Wb + t * 128;
        for (int f = 0; f < 128; f++) s += wr[f] * h0[f];
        u[t] = s;
    }
    __syncthreads();
    if (t < DLN) {
        float s = 0.f;
        for (int e = 0; e < 128; e++) s += demb[t * 128 + e] * u[e];
        sc[t] = s;
    }
    __syncthreads();
    if (t < DLN) {
        float mx = sc[0];
        for (int l = 1; l < DLN; l++) mx = fmaxf(mx, sc[l]);
        ex[t] = expf(sc[t] - mx);
    }
    __syncthreads();
    {
        float sum = 0.f, rv = 0.f;
        for (int l = 0; l < DLN; l++) sum += ex[l];
        for (int l = 0; l < DLN; l++) rv += ex[l] * demb[l * 128 + t];
        out[BB * 128 + b * 128 + t] = rv / sum;     // rvec
    }
    {
        float a = linb[t];
        const float* wr = linW + t * 256;
        for (int q = 0; q < 256; q++) a += wr[q] * pool[q];
        out[b * 128 + t] = a;                       // lvec
    }
}

// ---------------------------------------------------------------------------
extern "C" void kernel_launch(void* const* d_in, const int* in_sizes, int n_in,
                              void* d_out, int out_size)
{
    const float* emb   = (const float*)d_in[0];
    const float* Wc    = (const float*)d_in[1];
    const float* bc    = (const float*)d_in[2];
    const float* Wb    = (const float*)d_in[3];
    const float* Wih_f = (const float*)d_in[4];
    const float* Whh_f = (const float*)d_in[5];
    const float* bih_f = (const float*)d_in[6];
    const float* bhh_f = (const float*)d_in[7];
    const float* Wih_b = (const float*)d_in[8];
    const float* Whh_b = (const float*)d_in[9];
    const float* bih_b = (const float*)d_in[10];
    const float* bhh_b = (const float*)d_in[11];
    const float* linW  = (const float*)d_in[12];
    const float* linb  = (const float*)d_in[13];
    const int* node_tokens = (const int*)d_in[14];
    const int* doc_tokens  = (const int*)d_in[15];
    float* out = (float*)d_out;

    const size_t smem = (size_t)2 * 128 * AP * sizeof(float);  // 135168 B
    cudaFuncSetAttribute(k1_stmt, cudaFuncAttributeMaxDynamicSharedMemorySize, (int)smem);
    cudaFuncSetAttribute(k1b_gi,  cudaFuncAttributeMaxDynamicSharedMemorySize, (int)smem);

    k1_stmt<<<TS / 4, 256, smem>>>(emb, Wc, bc, node_tokens);
    dim3 g2(TS / 128, 6);
    k1b_gi<<<g2, 256, smem>>>(Wih_f, Wih_b);
    k2_gru<<<BB * 2, 768>>>(Whh_f, bih_f, bhh_f, Whh_b, bih_b, bhh_b);
    k3_out<<<BB, 128>>>(emb, Wb, linW, linb, doc_tokens, out);
}

// round 5
// speedup vs baseline: 1.3779x; 1.3779x over previous
#include <cuda_runtime.h>
#include <cuda_bf16.h>
#include <math.h>
#include <stdint.h>

#define TS 8192
#define BB 64
#define LL 128
#define DLN 20
#define TP 272      // bf16 tile pitch in BYTES (136 bf16) -> conflict-free ldmatrix
#define SP 132      // fp32 stage pitch in floats

typedef unsigned long long ull;

// ---------------- scratch (device globals; no allocation allowed) ----------
__device__ float g_gi[TS * 768];                     // 25 MB
__device__ float g_pooled[BB * 256];
__device__ __align__(16) __nv_bfloat16 g_Bhi[7 * 16384];  // Wc + 6 Wih row-blocks, [j][k]
__device__ __align__(16) __nv_bfloat16 g_Blo[7 * 16384];
__device__ __align__(16) __nv_bfloat16 g_Ahi[TS * 128];   // stmt_h hi, [stmt][k]
__device__ __align__(16) __nv_bfloat16 g_Alo[TS * 128];

// subtree sizes of the 32-node binary heap
__constant__ float c_cszf[32] = {32,16,15,8,7,7,7,4,3,3,3,3,3,3,3,2,
                                 1,1,1,1,1,1,1,1,1,1,1,1,1,1,1,1};

// ---------------- helpers ---------------------------------------------------
__device__ __forceinline__ uint32_t s2u(const void* p){
    uint32_t a;
    asm("{ .reg .u64 t; cvta.to.shared.u64 t, %1; cvt.u32.u64 %0, t; }" : "=r"(a) : "l"(p));
    return a;
}
__device__ __forceinline__ void ldsm4(uint32_t addr, uint32_t r[4]){
    asm volatile("ldmatrix.sync.aligned.m8n8.x4.shared.b16 {%0,%1,%2,%3}, [%4];"
        : "=r"(r[0]), "=r"(r[1]), "=r"(r[2]), "=r"(r[3]) : "r"(addr));
}
__device__ __forceinline__ void mma_bf16(float d[4], const uint32_t a[4], uint32_t b0, uint32_t b1){
    asm volatile("mma.sync.aligned.m16n8k16.row.col.f32.bf16.bf16.f32 "
        "{%0,%1,%2,%3}, {%4,%5,%6,%7}, {%8,%9}, {%0,%1,%2,%3};"
        : "+f"(d[0]), "+f"(d[1]), "+f"(d[2]), "+f"(d[3])
        : "r"(a[0]), "r"(a[1]), "r"(a[2]), "r"(a[3]), "r"(b0), "r"(b1));
}
__device__ __forceinline__ float4 f4add(float4 a, float4 b){
    return make_float4(a.x + b.x, a.y + b.y, a.z + b.z, a.w + b.w);
}
__device__ __forceinline__ void bsplit(float x, __nv_bfloat16& h, __nv_bfloat16& l){
    h = __float2bfloat16_rn(x);
    l = __float2bfloat16_rn(x - __bfloat162float(h));
}

// smem layout (byte offsets from aligned base). One 128x136 bf16 tile = 34816 B.
#define OFF_AH 0
#define OFF_AL 34816
#define OFF_BH 69632
#define OFF_BL 104448
#define OFF_STG 139264                 // float[128][132] = 67584 B
#define K1_DYN  (1024 + 139264 + 67584)
#define K1B_DYN (1024 + 139264)

// 128x128x128 split-bf16 GEMM: acc[nt][4] += A(16w rows) x B^T, 3 terms.
__device__ __forceinline__ void gemm_tile(
    uint32_t sAH, uint32_t sAL, uint32_t sBH, uint32_t sBL,
    int w, int lane, float acc[16][4])
{
    const uint32_t aOff = (uint32_t)(((lane & 15) + 16 * w) * TP + ((lane >> 4) << 4));
    const uint32_t bOff = (uint32_t)((((lane >> 4) << 3) + (lane & 7)) * TP + (((lane >> 3) & 1) << 4));
    #pragma unroll
    for (int ks = 0; ks < 8; ks++) {
        const uint32_t ko = ks * 32;          // 16 bf16 = 32 B
        uint32_t ah[4], al[4];
        ldsm4(sAH + aOff + ko, ah);
        ldsm4(sAL + aOff + ko, al);
        uint32_t bH = sBH + bOff + ko, bL = sBL + bOff + ko;
        #pragma unroll
        for (int p = 0; p < 8; p++) {
            uint32_t bh[4], bl[4];
            ldsm4(bH, bh);
            ldsm4(bL, bl);
            mma_bf16(acc[2 * p],     ah, bh[0], bh[1]);
            mma_bf16(acc[2 * p],     ah, bl[0], bl[1]);
            mma_bf16(acc[2 * p],     al, bh[0], bh[1]);
            mma_bf16(acc[2 * p + 1], ah, bh[2], bh[3]);
            mma_bf16(acc[2 * p + 1], ah, bl[2], bl[3]);
            mma_bf16(acc[2 * p + 1], al, bh[2], bh[3]);
            bH += 16 * TP; bL += 16 * TP;
        }
    }
}

// ---------------------------------------------------------------------------
// K0: bf16 hi/lo weight staging. tile 0 = Wc; tiles 1..6 = [Wih_f;Wih_b] 128-row blocks
// ---------------------------------------------------------------------------
__global__ __launch_bounds__(256) void k0_prep(
    const float* __restrict__ Wc, const float* __restrict__ Wih_f, const float* __restrict__ Wih_b)
{
    const int i = blockIdx.x;
    const float* src;
    if (i == 0) src = Wc;
    else { int cb = (i - 1) * 128; src = (cb < 384) ? (Wih_f + cb * 128) : (Wih_b + (cb - 384) * 128); }
    for (int p = threadIdx.x; p < 128 * 64; p += 256) {
        int j = p >> 6, kp = (p & 63) * 2;
        float x0 = src[j * 128 + kp], x1 = src[j * 128 + kp + 1];
        __nv_bfloat162 hh, ll;
        bsplit(x0, hh.x, ll.x);
        bsplit(x1, hh.y, ll.y);
        int e = i * 16384 + j * 128 + kp;
        *(__nv_bfloat162*)(g_Bhi + e) = hh;
        *(__nv_bfloat162*)(g_Blo + e) = ll;
    }
}

// ---------------------------------------------------------------------------
// K1: 4 statements/CTA. gather -> heap-level tree reduce (fp32) -> bf16 split
//     -> mma.sync 3-term GEMM vs Wc -> epilogue (c(v)*bc bias, per-stmt max,
//     relu) -> hi/lo staging for K1b.
// ---------------------------------------------------------------------------
__global__ __launch_bounds__(256) void k1_stmt(
    const float* __restrict__ emb, const float* __restrict__ bc,
    const int* __restrict__ toks_g)
{
    extern __shared__ char smraw[];
    __shared__ int toks[128];
    __shared__ float bcs[128];

    const int t = threadIdx.x, w = t >> 5, lane = t & 31;
    const int s0 = blockIdx.x * 4;

    const uint32_t rawu = s2u(smraw);
    const uint32_t alu = (rawu + 1023u) & ~1023u;
    char* base = smraw + (alu - rawu);
    float* stg = (float*)(base + OFF_STG);
    float4* As4 = (float4*)stg;            // pitch 33 float4 (= SP floats)

    if (t < 128) { toks[t] = toks_g[s0 * 32 + t] + 1; bcs[t] = bc[t]; }

    // copy Wc hi/lo tiles global->smem (pitched)
    {
        const float4* sh = (const float4*)g_Bhi;
        const float4* sl = (const float4*)g_Blo;
        #pragma unroll
        for (int i = 0; i < 8; i++) {
            int idx = i * 256 + t;
            int j = idx >> 4, sg = idx & 15;
            *(float4*)(base + OFF_BH + j * TP + sg * 16) = sh[idx];
            *(float4*)(base + OFF_BL + j * TP + sg * 16) = sl[idx];
        }
    }
    __syncthreads();

    // gather 128 embedding rows into fp32 stage [row][k]
    #pragma unroll
    for (int i = 0; i < 16; i++) {
        int idx = i * 256 + t;
        int kq = idx & 31, r = idx >> 5;
        As4[r * 33 + kq] = *(const float4*)(emb + (size_t)toks[r] * 128 + kq * 4);
    }
    __syncthreads();

    // subtree sums, strict heap levels (rows: stmt*32 + node)
    if (t < 128) {   // L4: p=15 (single child 31)
        int tt = t >> 5, k4 = t & 31;
        As4[(tt * 32 + 15) * 33 + k4] = f4add(As4[(tt * 32 + 15) * 33 + k4], As4[(tt * 32 + 31) * 33 + k4]);
    }
    __syncthreads();
    #pragma unroll
    for (int i = 0; i < 4; i++) {   // L3: p=7..14  (8*4*32 = 1024 tasks)
        int idx = i * 256 + t;
        int k4 = idx & 31, q = idx >> 5, tt = q & 3, p = 7 + (q >> 2);
        int br = (tt * 32 + p) * 33;
        As4[br + k4] = f4add(As4[br + k4],
                      f4add(As4[(tt * 32 + 2 * p + 1) * 33 + k4], As4[(tt * 32 + 2 * p + 2) * 33 + k4]));
    }
    __syncthreads();
    #pragma unroll
    for (int i = 0; i < 2; i++) {   // L2: p=3..6
        int idx = i * 256 + t;
        int k4 = idx & 31, q = idx >> 5, tt = q & 3, p = 3 + (q >> 2);
        int br = (tt * 32 + p) * 33;
        As4[br + k4] = f4add(As4[br + k4],
                      f4add(As4[(tt * 32 + 2 * p + 1) * 33 + k4], As4[(tt * 32 + 2 * p + 2) * 33 + k4]));
    }
    __syncthreads();
    {   // L1: p=1..2 (256 tasks)
        int k4 = t & 31, q = t >> 5, tt = q & 3, p = 1 + (q >> 2);
        int br = (tt * 32 + p) * 33;
        As4[br + k4] = f4add(As4[br + k4],
                      f4add(As4[(tt * 32 + 2 * p + 1) * 33 + k4], As4[(tt * 32 + 2 * p + 2) * 33 + k4]));
    }
    __syncthreads();
    if (t < 128) {   // L0: p=0
        int tt = t >> 5, k4 = t & 31;
        int br = (tt * 32) * 33;
        As4[br + k4] = f4add(As4[br + k4], f4add(As4[(tt * 32 + 1) * 33 + k4], As4[(tt * 32 + 2) * 33 + k4]));
    }
    __syncthreads();

    // fp32 -> bf16 hi/lo into pitched A tiles
    #pragma unroll
    for (int i = 0; i < 32; i++) {
        int idx = i * 256 + t;
        int row = idx >> 6, c2 = idx & 63;
        float2 v = *(const float2*)(stg + row * SP + c2 * 2);
        __nv_bfloat162 hh, ll;
        bsplit(v.x, hh.x, ll.x);
        bsplit(v.y, hh.y, ll.y);
        *(__nv_bfloat162*)(base + OFF_AH + row * TP + c2 * 4) = hh;
        *(__nv_bfloat162*)(base + OFF_AL + row * TP + c2 * 4) = ll;
    }
    __syncthreads();

    // GEMM
    float acc[16][4];
    #pragma unroll
    for (int n = 0; n < 16; n++)
        #pragma unroll
        for (int c = 0; c < 4; c++) acc[n][c] = 0.f;
    gemm_tile(alu + OFF_AH, alu + OFF_AL, alu + OFF_BH, alu + OFF_BL, w, lane, acc);

    // write accs to stage (raw, bias added during reduction)
    {
        const int r0 = 16 * w + (lane >> 2);
        const int cb = (lane & 3) * 2;
        #pragma unroll
        for (int nt = 0; nt < 16; nt++) {
            *(float2*)(stg + r0 * SP + nt * 8 + cb)       = make_float2(acc[nt][0], acc[nt][1]);
            *(float2*)(stg + (r0 + 8) * SP + nt * 8 + cb) = make_float2(acc[nt][2], acc[nt][3]);
        }
    }
    __syncthreads();

    // per-(stmt,col): max over 32 nodes of acc + csz[node]*bc[col], relu, split
    #pragma unroll
    for (int rep = 0; rep < 2; rep++) {
        int task = rep * 256 + t;
        int st = task >> 7, col = task & 127;
        float bcv = bcs[col];
        float m = 0.f;   // relu baseline
        #pragma unroll
        for (int r = 0; r < 32; r++)
            m = fmaxf(m, stg[(st * 32 + r) * SP + col] + c_cszf[r] * bcv);
        __nv_bfloat16 hi, lo;
        bsplit(m, hi, lo);
        int e = (s0 + st) * 128 + col;
        g_Ahi[e] = hi; g_Alo[e] = lo;
    }
}

// ---------------------------------------------------------------------------
// K1b: gi tile GEMM. grid (64 row-blocks, 6 gate-blocks).
// ---------------------------------------------------------------------------
__global__ __launch_bounds__(256) void k1b_gi(int dummy)
{
    extern __shared__ char smraw[];
    const int t = threadIdx.x, w = t >> 5, lane = t & 31;
    const int rb = blockIdx.x, by = blockIdx.y;

    const uint32_t rawu = s2u(smraw);
    const uint32_t alu = (rawu + 1023u) & ~1023u;
    char* base = smraw + (alu - rawu);

    {
        const float4* sah = (const float4*)(g_Ahi + rb * 16384);
        const float4* sal = (const float4*)(g_Alo + rb * 16384);
        const float4* sbh = (const float4*)(g_Bhi + (1 + by) * 16384);
        const float4* sbl = (const float4*)(g_Blo + (1 + by) * 16384);
        #pragma unroll
        for (int i = 0; i < 8; i++) {
            int idx = i * 256 + t;
            int j = idx >> 4, sg = idx & 15;
            *(float4*)(base + OFF_AH + j * TP + sg * 16) = sah[idx];
            *(float4*)(base + OFF_AL + j * TP + sg * 16) = sal[idx];
            *(float4*)(base + OFF_BH + j * TP + sg * 16) = sbh[idx];
            *(float4*)(base + OFF_BL + j * TP + sg * 16) = sbl[idx];
        }
    }
    __syncthreads();

    float acc[16][4];
    #pragma unroll
    for (int n = 0; n < 16; n++)
        #pragma unroll
        for (int c = 0; c < 4; c++) acc[n][c] = 0.f;
    gemm_tile(alu + OFF_AH, alu + OFF_AL, alu + OFF_BH, alu + OFF_BL, w, lane, acc);

    const int row = rb * 128 + 16 * w + (lane >> 2);
    float* o0 = g_gi + (size_t)row * 768 + by * 128;
    float* o1 = o0 + 8 * 768;
    const int cb = (lane & 3) * 2;
    #pragma unroll
    for (int nt = 0; nt < 16; nt++) {
        *(float2*)(o0 + nt * 8 + cb) = make_float2(acc[nt][0], acc[nt][1]);
        *(float2*)(o1 + nt * 8 + cb) = make_float2(acc[nt][2], acc[nt][3]);
    }
}

// ---------------------------------------------------------------------------
__device__ __forceinline__ void ffma2(ull& d, ull a, ull b){
    asm("fma.rn.f32x2 %0, %1, %2, %0;" : "+l"(d) : "l"(a), "l"(b));
}
__device__ __forceinline__ float2 ull2f2(ull v){
    float2 f; asm("mov.b64 {%0, %1}, %2;" : "=f"(f.x), "=f"(f.y) : "l"(v)); return f;
}

// ---------------------------------------------------------------------------
// K2: GRU recurrence. 128 CTAs, one per (batch, dir).
// ---------------------------------------------------------------------------
__global__ __launch_bounds__(768) void k2_gru(
    const float* __restrict__ Whh_f, const float* __restrict__ bih_f, const float* __restrict__ bhh_f,
    const float* __restrict__ Whh_b, const float* __restrict__ bih_b, const float* __restrict__ bhh_b)
{
    __shared__ float h_s[128];
    __shared__ float part[768];
    __shared__ float gi_buf[2][384];

    const int t = threadIdx.x;
    const int b = blockIdx.x >> 1, dir = blockIdx.x & 1;
    const float* Whh = dir ? Whh_b : Whh_f;
    const float* bih = dir ? bih_b : bih_f;
    const float* bhh = dir ? bhh_b : bhh_f;
    const int goff = dir * 384;

    const int j = t % 384;
    const int half = t / 384;

    ull w2[32];
    {
        const ulonglong2* wp = (const ulonglong2*)(Whh + j * 128 + half * 64);
        #pragma unroll
        for (int i = 0; i < 16; i++) { ulonglong2 v = wp[i]; w2[2*i] = v.x; w2[2*i+1] = v.y; }
    }
    float bir = 0, biz = 0, bin = 0, bhr = 0, bhz = 0, bhn = 0;
    float hmax = -3e38f;
    if (t < 128) {
        bir = bih[t]; biz = bih[128 + t]; bin = bih[256 + t];
        bhr = bhh[t]; bhz = bhh[128 + t]; bhn = bhh[256 + t];
        h_s[t] = 0.f;
    }
    {
        int r0 = b * LL + (dir ? (LL - 1) : 0);
        if (t < 384) gi_buf[0][t] = g_gi[r0 * 768 + goff + t];
    }
    __syncthreads();

    int cur = 0;
    for (int l = 0; l < LL; l++) {
        float pre = 0.f;
        if (t >= 384 && l + 1 < LL) {
            int rn = b * LL + (dir ? (LL - 2 - l) : (l + 1));
            pre = g_gi[rn * 768 + goff + (t - 384)];
        }
        // matvec with 4 independent accumulators
        ull a0 = 0, a1 = 0, a2 = 0, a3 = 0;
        const ulonglong2* hp = (const ulonglong2*)(h_s + half * 64);
        #pragma unroll
        for (int i = 0; i < 16; i += 2) {
            ulonglong2 h0 = hp[i], h1 = hp[i + 1];
            ffma2(a0, w2[2*i],     h0.x);
            ffma2(a1, w2[2*i + 1], h0.y);
            ffma2(a2, w2[2*i + 2], h1.x);
            ffma2(a3, w2[2*i + 3], h1.y);
        }
        float2 f0 = ull2f2(a0), f1 = ull2f2(a1), f2 = ull2f2(a2), f3 = ull2f2(a3);
        part[t] = ((f0.x + f0.y) + (f1.x + f1.y)) + ((f2.x + f2.y) + (f3.x + f3.y));
        __syncthreads();

        if (t < 128) {
            float ghr = part[t]       + part[384 + t]       + bhr;
            float ghz = part[128 + t] + part[384 + 128 + t] + bhz;
            float ghn = part[256 + t] + part[384 + 256 + t] + bhn;
            float gir = gi_buf[cur][t]       + bir;
            float giz = gi_buf[cur][128 + t] + biz;
            float gin = gi_buf[cur][256 + t] + bin;
            float r = 1.f / (1.f + expf(-(gir + ghr)));
            float z = 1.f / (1.f + expf(-(giz + ghz)));
            float n = tanhf(gin + r * ghn);
            float hnew = (1.f - z) * n + z * h_s[t];
            h_s[t] = hnew;
            hmax = fmaxf(hmax, hnew);
        }
        if (t >= 384 && l + 1 < LL) gi_buf[cur ^ 1][t - 384] = pre;
        __syncthreads();
        cur ^= 1;
    }
    if (t < 128) g_pooled[b * 256 + dir * 128 + t] = hmax;
}

// ---------------------------------------------------------------------------
// K3: lvec = pooled @ linW^T + linb ; rvec = doc attention.
// ---------------------------------------------------------------------------
__global__ __launch_bounds__(256) void k3_out(
    const float* __restrict__ emb, const float* __restrict__ Wb,
    const float* __restrict__ linW, const float* __restrict__ linb,
    const int* __restrict__ doc, float* __restrict__ out)
{
    __shared__ float demb[DLN * 128];
    __shared__ float h0[128];
    __shared__ float u[128];
    __shared__ float sc[DLN];
    __shared__ float ex[DLN];
    __shared__ float inv_s;
    __shared__ float pool[256];
    __shared__ int dti[DLN];

    const int t = threadIdx.x, b = blockIdx.x;
    const int wid = t >> 5, lane = t & 31;

    pool[t] = g_pooled[b * 256 + t];
    if (t < DLN) dti[t] = doc[b * DLN + t] + 1;
    __syncthreads();

    #pragma unroll
    for (int i = 0; i < 10; i++) {
        int idx = i * 256 + t;
        demb[idx] = emb[(size_t)dti[idx >> 7] * 128 + (idx & 127)];
    }
    __syncthreads();

    if (t < 128) {
        float s = 0.f;
        #pragma unroll
        for (int l = 0; l < DLN; l++) s += demb[l * 128 + t];
        h0[t] = s * (1.f / (float)DLN);
    }
    __syncthreads();

    for (int rr = 0; rr < 16; rr++) {
        int row = wid * 16 + rr;
        const float* wr = Wb + row * 128;
        float s = wr[lane] * h0[lane] + wr[lane + 32] * h0[lane + 32]
                + wr[lane + 64] * h0[lane + 64] + wr[lane + 96] * h0[lane + 96];
        #pragma unroll
        for (int o = 16; o > 0; o >>= 1) s += __shfl_xor_sync(0xffffffffu, s, o);
        if (lane == 0) u[row] = s;
    }
    __syncthreads();

    for (int l = wid; l < DLN; l += 8) {
        const float* dr = demb + l * 128;
        float s = dr[lane] * u[lane] + dr[lane + 32] * u[lane + 32]
                + dr[lane + 64] * u[lane + 64] + dr[lane + 96] * u[lane + 96];
        #pragma unroll
        for (int o = 16; o > 0; o >>= 1) s += __shfl_xor_sync(0xffffffffu, s, o);
        if (lane == 0) sc[l] = s;
    }
    __syncthreads();

    if (t == 0) {
        float mx = sc[0];
        #pragma unroll
        for (int l = 1; l < DLN; l++) mx = fmaxf(mx, sc[l]);
        float sum = 0.f;
        #pragma unroll
        for (int l = 0; l < DLN; l++) { float e = expf(sc[l] - mx); ex[l] = e; sum += e; }
        inv_s = 1.f / sum;
    }
    __syncthreads();

    if (t < 128) {
        float rv = 0.f;
        #pragma unroll
        for (int l = 0; l < DLN; l++) rv += ex[l] * demb[l * 128 + t];
        out[BB * 128 + b * 128 + t] = rv * inv_s;
    }

    for (int rr = 0; rr < 16; rr++) {
        int row = wid * 16 + rr;
        const float* wr = linW + row * 256;
        float s = 0.f;
        #pragma unroll
        for (int q = 0; q < 8; q++) s += wr[lane + 32 * q] * pool[lane + 32 * q];
        #pragma unroll
        for (int o = 16; o > 0; o >>= 1) s += __shfl_xor_sync(0xffffffffu, s, o);
        if (lane == 0) out[b * 128 + row] = s + linb[row];
    }
}

// ---------------------------------------------------------------------------
extern "C" void kernel_launch(void* const* d_in, const int* in_sizes, int n_in,
                              void* d_out, int out_size)
{
    const float* emb   = (const float*)d_in[0];
    const float* Wc    = (const float*)d_in[1];
    const float* bc    = (const float*)d_in[2];
    const float* Wb    = (const float*)d_in[3];
    const float* Wih_f = (const float*)d_in[4];
    const float* Whh_f = (const float*)d_in[5];
    const float* bih_f = (const float*)d_in[6];
    const float* bhh_f = (const float*)d_in[7];
    const float* Wih_b = (const float*)d_in[8];
    const float* Whh_b = (const float*)d_in[9];
    const float* bih_b = (const float*)d_in[10];
    const float* bhh_b = (const float*)d_in[11];
    const float* linW  = (const float*)d_in[12];
    const float* linb  = (const float*)d_in[13];
    const int* node_tokens = (const int*)d_in[14];
    const int* doc_tokens  = (const int*)d_in[15];
    float* out = (float*)d_out;

    cudaFuncSetAttribute(k1_stmt, cudaFuncAttributeMaxDynamicSharedMemorySize, K1_DYN);
    cudaFuncSetAttribute(k1b_gi,  cudaFuncAttributeMaxDynamicSharedMemorySize, K1B_DYN);

    k0_prep<<<7, 256>>>(Wc, Wih_f, Wih_b);
    k1_stmt<<<TS / 4, 256, K1_DYN>>>(emb, bc, node_tokens);
    k1b_gi<<<dim3(64, 6), 256, K1B_DYN>>>(0);
    k2_gru<<<BB * 2, 768>>>(Whh_f, bih_f, bhh_f, Whh_b, bih_b, bhh_b);
    k3_out<<<BB, 256>>>(emb, Wb, linW, linb, doc_tokens, out);
}

// round 6
// speedup vs baseline: 1.9204x; 1.3937x over previous
#include <cuda_runtime.h>
#include <cuda_bf16.h>
#include <math.h>
#include <stdint.h>

#define TS 8192
#define BB 64
#define LL 128
#define DLN 20
#define TP 272      // bf16 tile pitch in BYTES (136 bf16)
#define SP 132      // fp32 stage pitch in floats

typedef unsigned long long ull;

// ---------------- scratch (device globals; no allocation allowed) ----------
__device__ float g_gi[TS * 768];                     // 25 MB
__device__ float g_pooled[BB * 256];
__device__ __align__(16) __nv_bfloat16 g_Bhi[7 * 16384];  // Wc + 6 Wih row-blocks, [j][k]
__device__ __align__(16) __nv_bfloat16 g_Blo[7 * 16384];
__device__ __align__(16) __nv_bfloat16 g_Ahi[TS * 128];   // stmt_h hi, [stmt][k]
__device__ __align__(16) __nv_bfloat16 g_Alo[TS * 128];

// subtree sizes of the 32-node binary heap
__constant__ float c_cszf[32] = {32,16,15,8,7,7,7,4,3,3,3,3,3,3,3,2,
                                 1,1,1,1,1,1,1,1,1,1,1,1,1,1,1,1};

// ---------------- helpers ---------------------------------------------------
__device__ __forceinline__ uint32_t s2u(const void* p){
    uint32_t a;
    asm("{ .reg .u64 t; cvta.to.shared.u64 t, %1; cvt.u32.u64 %0, t; }" : "=r"(a) : "l"(p));
    return a;
}
__device__ __forceinline__ void ldsm4(uint32_t addr, uint32_t r[4]){
    asm volatile("ldmatrix.sync.aligned.m8n8.x4.shared.b16 {%0,%1,%2,%3}, [%4];"
        : "=r"(r[0]), "=r"(r[1]), "=r"(r[2]), "=r"(r[3]) : "r"(addr));
}
__device__ __forceinline__ void mma_bf16(float d[4], const uint32_t a[4], uint32_t b0, uint32_t b1){
    asm volatile("mma.sync.aligned.m16n8k16.row.col.f32.bf16.bf16.f32 "
        "{%0,%1,%2,%3}, {%4,%5,%6,%7}, {%8,%9}, {%0,%1,%2,%3};"
        : "+f"(d[0]), "+f"(d[1]), "+f"(d[2]), "+f"(d[3])
        : "r"(a[0]), "r"(a[1]), "r"(a[2]), "r"(a[3]), "r"(b0), "r"(b1));
}
__device__ __forceinline__ float4 f4add(float4 a, float4 b){
    return make_float4(a.x + b.x, a.y + b.y, a.z + b.z, a.w + b.w);
}
__device__ __forceinline__ void bsplit(float x, __nv_bfloat16& h, __nv_bfloat16& l){
    h = __float2bfloat16_rn(x);
    l = __float2bfloat16_rn(x - __bfloat162float(h));
}
__device__ __forceinline__ void cpa16(uint32_t dst, const void* src){
    asm volatile("cp.async.cg.shared.global [%0], [%1], 16;"
        :: "r"(dst), "l"(__cvta_generic_to_global(src)) : "memory");
}
#define CP_COMMIT() asm volatile("cp.async.commit_group;" ::: "memory")
#define CP_WAIT0()  asm volatile("cp.async.wait_group 0;" ::: "memory")
#define CP_WAIT1()  asm volatile("cp.async.wait_group 1;" ::: "memory")

// smem layout (byte offsets from aligned base). One 128x136 bf16 tile = 34816 B.
#define OFF_AH 0
#define OFF_AL 34816
#define OFF_BH 69632
#define OFF_BL 104448
#define OFF_STG 139264                 // float[128][132] = 67584 B
#define K1_DYN  (1024 + 139264 + 67584)
#define K1B_DYN (1024 + 174080 + 34816)

// 128x128x128 split-bf16 GEMM: acc[nt][4] += A(16w rows) x B^T, 3 terms.
__device__ __forceinline__ void gemm_tile(
    uint32_t sAH, uint32_t sAL, uint32_t sBH, uint32_t sBL,
    int w, int lane, float acc[16][4])
{
    const uint32_t aOff = (uint32_t)(((lane & 15) + 16 * w) * TP + ((lane >> 4) << 4));
    const uint32_t bOff = (uint32_t)((((lane >> 4) << 3) + (lane & 7)) * TP + (((lane >> 3) & 1) << 4));
    #pragma unroll
    for (int ks = 0; ks < 8; ks++) {
        const uint32_t ko = ks * 32;          // 16 bf16 = 32 B
        uint32_t ah[4], al[4];
        ldsm4(sAH + aOff + ko, ah);
        ldsm4(sAL + aOff + ko, al);
        uint32_t bH = sBH + bOff + ko, bL = sBL + bOff + ko;
        #pragma unroll
        for (int p = 0; p < 8; p++) {
            uint32_t bh[4], bl[4];
            ldsm4(bH, bh);
            ldsm4(bL, bl);
            mma_bf16(acc[2 * p],     ah, bh[0], bh[1]);
            mma_bf16(acc[2 * p],     ah, bl[0], bl[1]);
            mma_bf16(acc[2 * p],     al, bh[0], bh[1]);
            mma_bf16(acc[2 * p + 1], ah, bh[2], bh[3]);
            mma_bf16(acc[2 * p + 1], ah, bl[2], bl[3]);
            mma_bf16(acc[2 * p + 1], al, bh[2], bh[3]);
            bH += 16 * TP; bL += 16 * TP;
        }
    }
}

// ---------------------------------------------------------------------------
// K0: bf16 hi/lo weight staging. tile 0 = Wc; tiles 1..6 = [Wih_f;Wih_b] blocks
// ---------------------------------------------------------------------------
__global__ __launch_bounds__(256) void k0_prep(
    const float* __restrict__ Wc, const float* __restrict__ Wih_f, const float* __restrict__ Wih_b)
{
    const int i = blockIdx.x;
    const float* src;
    if (i == 0) src = Wc;
    else { int cb = (i - 1) * 128; src = (cb < 384) ? (Wih_f + cb * 128) : (Wih_b + (cb - 384) * 128); }
    for (int p = threadIdx.x; p < 128 * 64; p += 256) {
        int j = p >> 6, kp = (p & 63) * 2;
        float x0 = src[j * 128 + kp], x1 = src[j * 128 + kp + 1];
        __nv_bfloat162 hh, ll;
        bsplit(x0, hh.x, ll.x);
        bsplit(x1, hh.y, ll.y);
        int e = i * 16384 + j * 128 + kp;
        *(__nv_bfloat162*)(g_Bhi + e) = hh;
        *(__nv_bfloat162*)(g_Blo + e) = ll;
    }
}

// issue cp.async gather of 128 embedding rows (512B each) into stage
__device__ __forceinline__ void gather_pref(
    uint32_t stg_u, const float* __restrict__ emb, const int* tk_s, int t)
{
    #pragma unroll
    for (int i = 0; i < 16; i++) {
        int idx = i * 256 + t;
        int row = idx >> 5, ch = idx & 31;
        cpa16(stg_u + (uint32_t)(row * (SP * 4) + ch * 16),
              emb + (size_t)tk_s[row] * 128 + ch * 4);
    }
    CP_COMMIT();
}

// ---------------------------------------------------------------------------
// K1: persistent (grid 148). Per tile (4 statements): prefetched gather ->
//     tree reduce -> bf16 split -> 3-term mma.sync GEMM vs Wc -> shuffle
//     epilogue (c(v)*bc bias, per-stmt max, relu) -> hi/lo staging for K1b.
// ---------------------------------------------------------------------------
__global__ __launch_bounds__(256) void k1_stmt(
    const float* __restrict__ emb, const float* __restrict__ bc,
    const int* __restrict__ toks_g)
{
    extern __shared__ char smraw[];
    __shared__ int tkA[128], tkB[128];
    __shared__ float bcs[128];
    __shared__ float epi[1024];

    const int t = threadIdx.x, w = t >> 5, lane = t & 31;
    const uint32_t rawu = s2u(smraw);
    const uint32_t alu = (rawu + 1023u) & ~1023u;
    char* base = smraw + (alu - rawu);
    float* stg = (float*)(base + OFF_STG);
    float4* As4 = (float4*)stg;
    const uint32_t stg_u = alu + OFF_STG;

    if (t < 128) { bcs[t] = bc[t]; tkA[t] = toks_g[blockIdx.x * 128 + t] + 1; }
    __syncthreads();
    gather_pref(stg_u, emb, tkA, t);
    if ((int)blockIdx.x + 148 < 2048 && t < 128)
        tkB[t] = toks_g[(blockIdx.x + 148) * 128 + t] + 1;

    // Wc hi/lo tiles once
    {
        const float4* sh = (const float4*)g_Bhi;
        const float4* sl = (const float4*)g_Blo;
        #pragma unroll
        for (int i = 0; i < 8; i++) {
            int idx = i * 256 + t, jj = idx >> 4, sg = idx & 15;
            *(float4*)(base + OFF_BH + jj * TP + sg * 16) = sh[idx];
            *(float4*)(base + OFF_BL + jj * TP + sg * 16) = sl[idx];
        }
    }

    int jpar = 0;
    for (int tile = blockIdx.x; tile < 2048; tile += 148, jpar ^= 1) {
        CP_WAIT0();
        __syncthreads();

        // ---- tree reduce, strict heap levels (rows: stmt*32 + node) ----
        if (t < 128) {   // L4: p=15 (single child 31)
            int tt = t >> 5, k4 = t & 31;
            As4[(tt * 32 + 15) * 33 + k4] = f4add(As4[(tt * 32 + 15) * 33 + k4], As4[(tt * 32 + 31) * 33 + k4]);
        }
        __syncthreads();
        #pragma unroll
        for (int i = 0; i < 4; i++) {   // L3: p=7..14
            int idx = i * 256 + t;
            int k4 = idx & 31, q = idx >> 5, tt = q & 3, p = 7 + (q >> 2);
            int br = (tt * 32 + p) * 33;
            As4[br + k4] = f4add(As4[br + k4],
                          f4add(As4[(tt * 32 + 2 * p + 1) * 33 + k4], As4[(tt * 32 + 2 * p + 2) * 33 + k4]));
        }
        __syncthreads();
        #pragma unroll
        for (int i = 0; i < 2; i++) {   // L2: p=3..6
            int idx = i * 256 + t;
            int k4 = idx & 31, q = idx >> 5, tt = q & 3, p = 3 + (q >> 2);
            int br = (tt * 32 + p) * 33;
            As4[br + k4] = f4add(As4[br + k4],
                          f4add(As4[(tt * 32 + 2 * p + 1) * 33 + k4], As4[(tt * 32 + 2 * p + 2) * 33 + k4]));
        }
        __syncthreads();
        {   // L1: p=1..2
            int k4 = t & 31, q = t >> 5, tt = q & 3, p = 1 + (q >> 2);
            int br = (tt * 32 + p) * 33;
            As4[br + k4] = f4add(As4[br + k4],
                          f4add(As4[(tt * 32 + 2 * p + 1) * 33 + k4], As4[(tt * 32 + 2 * p + 2) * 33 + k4]));
        }
        __syncthreads();
        if (t < 128) {   // L0: p=0
            int tt = t >> 5, k4 = t & 31;
            int br = (tt * 32) * 33;
            As4[br + k4] = f4add(As4[br + k4], f4add(As4[(tt * 32 + 1) * 33 + k4], As4[(tt * 32 + 2) * 33 + k4]));
        }
        __syncthreads();

        // ---- fp32 -> bf16 hi/lo A tiles ----
        #pragma unroll
        for (int i = 0; i < 32; i++) {
            int idx = i * 256 + t;
            int row = idx >> 6, c2 = idx & 63;
            float2 v = *(const float2*)(stg + row * SP + c2 * 2);
            __nv_bfloat162 hh, ll;
            bsplit(v.x, hh.x, ll.x);
            bsplit(v.y, hh.y, ll.y);
            *(__nv_bfloat162*)(base + OFF_AH + row * TP + c2 * 4) = hh;
            *(__nv_bfloat162*)(base + OFF_AL + row * TP + c2 * 4) = ll;
        }
        __syncthreads();

        // ---- prefetch next tile's gather into (now free) stage ----
        int nxt = tile + 148;
        if (nxt < 2048) gather_pref(stg_u, emb, jpar ? tkA : tkB, t);
        if (nxt + 148 < 2048 && t < 128)
            (jpar ? tkB : tkA)[t] = toks_g[(nxt + 148) * 128 + t] + 1;

        // ---- GEMM ----
        float acc[16][4];
        #pragma unroll
        for (int n = 0; n < 16; n++)
            #pragma unroll
            for (int c = 0; c < 4; c++) acc[n][c] = 0.f;
        gemm_tile(alu + OFF_AH, alu + OFF_AL, alu + OFF_BH, alu + OFF_BL, w, lane, acc);

        // ---- shuffle epilogue: max over 32 nodes of acc + csz*bc, relu ----
        const int rr0 = (w & 1) * 16 + (lane >> 2);
        const float cz0 = c_cszf[rr0], cz1 = c_cszf[rr0 + 8];
        #pragma unroll
        for (int nt = 0; nt < 16; nt++) {
            int c0 = nt * 8 + 2 * (lane & 3);
            float b0 = bcs[c0], b1 = bcs[c0 + 1];
            float m0 = fmaxf(acc[nt][0] + cz0 * b0, acc[nt][2] + cz1 * b0);
            float m1 = fmaxf(acc[nt][1] + cz0 * b1, acc[nt][3] + cz1 * b1);
            #pragma unroll
            for (int o = 4; o <= 16; o <<= 1) {
                m0 = fmaxf(m0, __shfl_xor_sync(0xffffffffu, m0, o));
                m1 = fmaxf(m1, __shfl_xor_sync(0xffffffffu, m1, o));
            }
            if ((lane >> 2) == 0) { epi[w * 128 + c0] = m0; epi[w * 128 + c0 + 1] = m1; }
        }
        __syncthreads();
        #pragma unroll
        for (int rep = 0; rep < 2; rep++) {
            int task = rep * 256 + t;
            int st = task >> 7, col = task & 127;
            float m = fmaxf(fmaxf(epi[(2 * st) * 128 + col], epi[(2 * st + 1) * 128 + col]), 0.f);
            __nv_bfloat16 hi, lo;
            bsplit(m, hi, lo);
            int e = (tile * 4 + st) * 128 + col;
            g_Ahi[e] = hi; g_Alo[e] = lo;
        }
        __syncthreads();
    }
}

// ---------------------------------------------------------------------------
// K1b: persistent gi GEMM. 144 CTAs = (24 rb-groups x 6 gate-blocks).
//      B loaded once; A double-buffered via cp.async.
// ---------------------------------------------------------------------------
__device__ __forceinline__ void k1b_prefA(uint32_t dstAH, uint32_t dstAL, int rb, int t){
    const float4* sah = (const float4*)(g_Ahi + rb * 16384);
    const float4* sal = (const float4*)(g_Alo + rb * 16384);
    #pragma unroll
    for (int i = 0; i < 8; i++) {
        int idx = i * 256 + t, jj = idx >> 4, sg = idx & 15;
        cpa16(dstAH + jj * TP + sg * 16, sah + idx);
        cpa16(dstAL + jj * TP + sg * 16, sal + idx);
    }
    CP_COMMIT();
}

__global__ __launch_bounds__(256) void k1b_gi(int dummy)
{
    extern __shared__ char smraw[];
    const int t = threadIdx.x, w = t >> 5, lane = t & 31;
    const int by = blockIdx.x % 6, rb0 = blockIdx.x / 6;
    const uint32_t rawu = s2u(smraw);
    const uint32_t alu = (rawu + 1023u) & ~1023u;
    char* base = smraw + (alu - rawu);
    const uint32_t offAH0 = 69632u, offAL0 = 104448u;
    const uint32_t offAH1 = 139264u, offAL1 = 174080u;

    k1b_prefA(alu + offAH0, alu + offAL0, rb0, t);

    {   // B gate-block once
        const float4* sbh = (const float4*)(g_Bhi + (1 + by) * 16384);
        const float4* sbl = (const float4*)(g_Blo + (1 + by) * 16384);
        #pragma unroll
        for (int i = 0; i < 8; i++) {
            int idx = i * 256 + t, jj = idx >> 4, sg = idx & 15;
            *(float4*)(base + 0     + jj * TP + sg * 16) = sbh[idx];
            *(float4*)(base + 34816 + jj * TP + sg * 16) = sbl[idx];
        }
    }

    int pb = 0;
    for (int rb = rb0; rb < 64; rb += 24, pb ^= 1) {
        CP_WAIT0();
        __syncthreads();
        if (rb + 24 < 64)
            k1b_prefA(alu + (pb ? offAH0 : offAH1), alu + (pb ? offAL0 : offAL1), rb + 24, t);

        float acc[16][4];
        #pragma unroll
        for (int n = 0; n < 16; n++)
            #pragma unroll
            for (int c = 0; c < 4; c++) acc[n][c] = 0.f;
        gemm_tile(alu + (pb ? offAH1 : offAH0), alu + (pb ? offAL1 : offAL0),
                  alu + 0, alu + 34816, w, lane, acc);

        const int row = rb * 128 + 16 * w + (lane >> 2);
        float* o0 = g_gi + (size_t)row * 768 + by * 128;
        float* o1 = o0 + 8 * 768;
        const int cb = (lane & 3) * 2;
        #pragma unroll
        for (int nt = 0; nt < 16; nt++) {
            *(float2*)(o0 + nt * 8 + cb) = make_float2(acc[nt][0], acc[nt][1]);
            *(float2*)(o1 + nt * 8 + cb) = make_float2(acc[nt][2], acc[nt][3]);
        }
    }
}

// ---------------------------------------------------------------------------
__device__ __forceinline__ void ffma2(ull& d, ull a, ull b){
    asm("fma.rn.f32x2 %0, %1, %2, %0;" : "+l"(d) : "l"(a), "l"(b));
}
__device__ __forceinline__ float2 ull2f2(ull v){
    float2 f; asm("mov.b64 {%0, %1}, %2;" : "=f"(f.x), "=f"(f.y) : "l"(v)); return f;
}

// ---------------------------------------------------------------------------
// K2: GRU recurrence. 128 CTAs, one per (batch, dir). Lean registers:
//     biases in smem, gi prefetch via cp.async (no reg prefetch), fast
//     activations -> 64 weight regs fit without spill.
// ---------------------------------------------------------------------------
__global__ __launch_bounds__(768) void k2_gru(
    const float* __restrict__ Whh_f, const float* __restrict__ bih_f, const float* __restrict__ bhh_f,
    const float* __restrict__ Whh_b, const float* __restrict__ bih_b, const float* __restrict__ bhh_b)
{
    __shared__ float h_s[128];
    __shared__ float part[768];
    __shared__ __align__(16) float gi_buf[2][384];
    __shared__ float bih_s[384], bhh_s[384];

    const int t = threadIdx.x;
    const int b = blockIdx.x >> 1, dir = blockIdx.x & 1;
    const float* Whh = dir ? Whh_b : Whh_f;
    const float* bih = dir ? bih_b : bih_f;
    const float* bhh = dir ? bhh_b : bhh_f;

    const int j = (t < 384) ? t : t - 384;
    const int half = (t < 384) ? 0 : 1;

    ull w2[32];
    {
        const ulonglong2* wp = (const ulonglong2*)(Whh + j * 128 + half * 64);
        #pragma unroll
        for (int i = 0; i < 16; i++) { ulonglong2 v = wp[i]; w2[2*i] = v.x; w2[2*i+1] = v.y; }
    }
    if (t < 384) { bih_s[t] = bih[t]; bhh_s[t] = bhh[t]; }
    if (t < 128) h_s[t] = 0.f;

    const float* gsrc = g_gi + (size_t)(b * LL + (dir ? LL - 1 : 0)) * 768 + dir * 384;
    const int stp = dir ? -768 : 768;

    if (t < 96) cpa16(s2u(&gi_buf[0][0]) + t * 16, gsrc + t * 4);
    CP_COMMIT();
    __syncthreads();

    float hmax = -3e38f;
    for (int l = 0; l < LL; l++) {
        if (l + 1 < LL && t < 96)
            cpa16(s2u(&gi_buf[(l + 1) & 1][0]) + t * 16, gsrc + (l + 1) * stp + t * 4);
        CP_COMMIT();

        // matvec: 4 independent accumulators
        ull a0 = 0, a1 = 0, a2 = 0, a3 = 0;
        const ulonglong2* hp = (const ulonglong2*)(h_s + half * 64);
        #pragma unroll
        for (int i = 0; i < 16; i += 2) {
            ulonglong2 h0 = hp[i], h1 = hp[i + 1];
            ffma2(a0, w2[2*i],     h0.x);
            ffma2(a1, w2[2*i + 1], h0.y);
            ffma2(a2, w2[2*i + 2], h1.x);
            ffma2(a3, w2[2*i + 3], h1.y);
        }
        float2 f0 = ull2f2(a0), f1 = ull2f2(a1), f2 = ull2f2(a2), f3 = ull2f2(a3);
        part[t] = ((f0.x + f0.y) + (f1.x + f1.y)) + ((f2.x + f2.y) + (f3.x + f3.y));
        CP_WAIT1();
        __syncthreads();

        if (t < 128) {
            const float* gb = gi_buf[l & 1];
            float ghr = part[t]       + part[384 + t] + bhh_s[t];
            float ghz = part[128 + t] + part[512 + t] + bhh_s[128 + t];
            float ghn = part[256 + t] + part[640 + t] + bhh_s[256 + t];
            float gir = gb[t]       + bih_s[t];
            float giz = gb[128 + t] + bih_s[128 + t];
            float gin = gb[256 + t] + bih_s[256 + t];
            float r = __fdividef(1.f, 1.f + __expf(-(gir + ghr)));
            float z = __fdividef(1.f, 1.f + __expf(-(giz + ghz)));
            float y = gin + r * ghn;
            float n = 1.f - __fdividef(2.f, __expf(2.f * y) + 1.f);
            float hnew = (1.f - z) * n + z * h_s[t];
            h_s[t] = hnew;
            hmax = fmaxf(hmax, hnew);
        }
        __syncthreads();
    }
    if (t < 128) g_pooled[b * 256 + dir * 128 + t] = hmax;
}

// ---------------------------------------------------------------------------
// K3: lvec = pooled @ linW^T + linb ; rvec = doc attention.
// ---------------------------------------------------------------------------
__global__ __launch_bounds__(256) void k3_out(
    const float* __restrict__ emb, const float* __restrict__ Wb,
    const float* __restrict__ linW, const float* __restrict__ linb,
    const int* __restrict__ doc, float* __restrict__ out)
{
    __shared__ float demb[DLN * 128];
    __shared__ float h0[128];
    __shared__ float u[128];
    __shared__ float sc[DLN];
    __shared__ float ex[DLN];
    __shared__ float inv_s;
    __shared__ float pool[256];
    __shared__ int dti[DLN];

    const int t = threadIdx.x, b = blockIdx.x;
    const int wid = t >> 5, lane = t & 31;

    pool[t] = g_pooled[b * 256 + t];
    if (t < DLN) dti[t] = doc[b * DLN + t] + 1;
    __syncthreads();

    #pragma unroll
    for (int i = 0; i < 10; i++) {
        int idx = i * 256 + t;
        demb[idx] = emb[(size_t)dti[idx >> 7] * 128 + (idx & 127)];
    }
    __syncthreads();

    if (t < 128) {
        float s = 0.f;
        #pragma unroll
        for (int l = 0; l < DLN; l++) s += demb[l * 128 + t];
        h0[t] = s * (1.f / (float)DLN);
    }
    __syncthreads();

    for (int rr = 0; rr < 16; rr++) {
        int row = wid * 16 + rr;
        const float* wr = Wb + row * 128;
        float s = wr[lane] * h0[lane] + wr[lane + 32] * h0[lane + 32]
                + wr[lane + 64] * h0[lane + 64] + wr[lane + 96] * h0[lane + 96];
        #pragma unroll
        for (int o = 16; o > 0; o >>= 1) s += __shfl_xor_sync(0xffffffffu, s, o);
        if (lane == 0) u[row] = s;
    }
    __syncthreads();

    for (int l = wid; l < DLN; l += 8) {
        const float* dr = demb + l * 128;
        float s = dr[lane] * u[lane] + dr[lane + 32] * u[lane + 32]
                + dr[lane + 64] * u[lane + 64] + dr[lane + 96] * u[lane + 96];
        #pragma unroll
        for (int o = 16; o > 0; o >>= 1) s += __shfl_xor_sync(0xffffffffu, s, o);
        if (lane == 0) sc[l] = s;
    }
    __syncthreads();

    if (t == 0) {
        float mx = sc[0];
        #pragma unroll
        for (int l = 1; l < DLN; l++) mx = fmaxf(mx, sc[l]);
        float sum = 0.f;
        #pragma unroll
        for (int l = 0; l < DLN; l++) { float e = expf(sc[l] - mx); ex[l] = e; sum += e; }
        inv_s = 1.f / sum;
    }
    __syncthreads();

    if (t < 128) {
        float rv = 0.f;
        #pragma unroll
        for (int l = 0; l < DLN; l++) rv += ex[l] * demb[l * 128 + t];
        out[BB * 128 + b * 128 + t] = rv * inv_s;
    }

    for (int rr = 0; rr < 16; rr++) {
        int row = wid * 16 + rr;
        const float* wr = linW + row * 256;
        float s = 0.f;
        #pragma unroll
        for (int q = 0; q < 8; q++) s += wr[lane + 32 * q] * pool[lane + 32 * q];
        #pragma unroll
        for (int o = 16; o > 0; o >>= 1) s += __shfl_xor_sync(0xffffffffu, s, o);
        if (lane == 0) out[b * 128 + row] = s + linb[row];
    }
}

// ---------------------------------------------------------------------------
extern "C" void kernel_launch(void* const* d_in, const int* in_sizes, int n_in,
                              void* d_out, int out_size)
{
    const float* emb   = (const float*)d_in[0];
    const float* Wc    = (const float*)d_in[1];
    const float* bc    = (const float*)d_in[2];
    const float* Wb    = (const float*)d_in[3];
    const float* Wih_f = (const float*)d_in[4];
    const float* Whh_f = (const float*)d_in[5];
    const float* bih_f = (const float*)d_in[6];
    const float* bhh_f = (const float*)d_in[7];
    const float* Wih_b = (const float*)d_in[8];
    const float* Whh_b = (const float*)d_in[9];
    const float* bih_b = (const float*)d_in[10];
    const float* bhh_b = (const float*)d_in[11];
    const float* linW  = (const float*)d_in[12];
    const float* linb  = (const float*)d_in[13];
    const int* node_tokens = (const int*)d_in[14];
    const int* doc_tokens  = (const int*)d_in[15];
    float* out = (float*)d_out;

    cudaFuncSetAttribute(k1_stmt, cudaFuncAttributeMaxDynamicSharedMemorySize, K1_DYN);
    cudaFuncSetAttribute(k1b_gi,  cudaFuncAttributeMaxDynamicSharedMemorySize, K1B_DYN);

    k0_prep<<<7, 256>>>(Wc, Wih_f, Wih_b);
    k1_stmt<<<148, 256, K1_DYN>>>(emb, bc, node_tokens);
    k1b_gi<<<144, 256, K1B_DYN>>>(0);
    k2_gru<<<BB * 2, 768>>>(Whh_f, bih_f, bhh_f, Whh_b, bih_b, bhh_b);
    k3_out<<<BB, 256>>>(emb, Wb, linW, linb, doc_tokens, out);
}

// round 7
// speedup vs baseline: 2.0217x; 1.0528x over previous
#include <cuda_runtime.h>
#include <cuda_bf16.h>
#include <math.h>
#include <stdint.h>

#define TS 8192
#define BB 64
#define LL 128
#define DLN 20
#define TP 272      // bf16 tile pitch in BYTES (136 bf16)
#define SP 132      // fp32 stage pitch in floats

typedef unsigned long long ull;

// ---------------- scratch (device globals; no allocation allowed) ----------
__device__ float g_gi[TS * 768];                     // 25 MB
__device__ float g_pooled[BB * 256];
__device__ __align__(16) __nv_bfloat16 g_Bhi[7 * 16384];  // Wc + 6 Wih row-blocks, [j][k]
__device__ __align__(16) __nv_bfloat16 g_Blo[7 * 16384];
__device__ __align__(16) __nv_bfloat16 g_Ahi[TS * 128];   // stmt_h hi, [stmt][k]
__device__ __align__(16) __nv_bfloat16 g_Alo[TS * 128];

// subtree sizes of the 32-node binary heap
__constant__ float c_cszf[32] = {32,16,15,8,7,7,7,4,3,3,3,3,3,3,3,2,
                                 1,1,1,1,1,1,1,1,1,1,1,1,1,1,1,1};

// ---------------- helpers ---------------------------------------------------
__device__ __forceinline__ uint32_t s2u(const void* p){
    uint32_t a;
    asm("{ .reg .u64 t; cvta.to.shared.u64 t, %1; cvt.u32.u64 %0, t; }" : "=r"(a) : "l"(p));
    return a;
}
__device__ __forceinline__ void ldsm4(uint32_t addr, uint32_t r[4]){
    asm volatile("ldmatrix.sync.aligned.m8n8.x4.shared.b16 {%0,%1,%2,%3}, [%4];"
        : "=r"(r[0]), "=r"(r[1]), "=r"(r[2]), "=r"(r[3]) : "r"(addr));
}
__device__ __forceinline__ void mma_bf16(float d[4], const uint32_t a[4], uint32_t b0, uint32_t b1){
    asm volatile("mma.sync.aligned.m16n8k16.row.col.f32.bf16.bf16.f32 "
        "{%0,%1,%2,%3}, {%4,%5,%6,%7}, {%8,%9}, {%0,%1,%2,%3};"
        : "+f"(d[0]), "+f"(d[1]), "+f"(d[2]), "+f"(d[3])
        : "r"(a[0]), "r"(a[1]), "r"(a[2]), "r"(a[3]), "r"(b0), "r"(b1));
}
__device__ __forceinline__ float4 f4add(float4 a, float4 b){
    return make_float4(a.x + b.x, a.y + b.y, a.z + b.z, a.w + b.w);
}
__device__ __forceinline__ void bsplit(float x, __nv_bfloat16& h, __nv_bfloat16& l){
    h = __float2bfloat16_rn(x);
    l = __float2bfloat16_rn(x - __bfloat162float(h));
}
__device__ __forceinline__ void cpa16(uint32_t dst, const void* src){
    asm volatile("cp.async.cg.shared.global [%0], [%1], 16;"
        :: "r"(dst), "l"(__cvta_generic_to_global(src)) : "memory");
}
#define CP_COMMIT() asm volatile("cp.async.commit_group;" ::: "memory")
#define CP_WAIT0()  asm volatile("cp.async.wait_group 0;" ::: "memory")
#define CP_WAIT1()  asm volatile("cp.async.wait_group 1;" ::: "memory")

// smem layout (byte offsets from aligned base). One 128x136 bf16 tile = 34816 B.
#define OFF_AH 0
#define OFF_AL 34816
#define OFF_BH 69632
#define OFF_BL 104448
#define OFF_STG 139264                 // float[128][132] = 67584 B
#define K1_DYN  (1024 + 139264 + 67584)
#define K1B_DYN (1024 + 174080 + 34816)

// 128x64x128 split-bf16 GEMM slice: warp (wr, wc) does rows 16*wr..+15,
// cols 64*wc..+63 (8 n-tiles), 3 terms.
__device__ __forceinline__ void gemm_tile8(
    uint32_t sAH, uint32_t sAL, uint32_t sBH, uint32_t sBL,
    int wr, int wc, int lane, float acc[8][4])
{
    const uint32_t aOff = (uint32_t)(((lane & 15) + 16 * wr) * TP + ((lane >> 4) << 4));
    const uint32_t bOff = (uint32_t)((64 * wc + ((lane >> 4) << 3) + (lane & 7)) * TP
                                     + (((lane >> 3) & 1) << 4));
    #pragma unroll
    for (int ks = 0; ks < 8; ks++) {
        const uint32_t ko = ks * 32;          // 16 bf16 = 32 B
        uint32_t ah[4], al[4];
        ldsm4(sAH + aOff + ko, ah);
        ldsm4(sAL + aOff + ko, al);
        uint32_t bH = sBH + bOff + ko, bL = sBL + bOff + ko;
        #pragma unroll
        for (int p = 0; p < 4; p++) {
            uint32_t bh[4], bl[4];
            ldsm4(bH, bh);
            ldsm4(bL, bl);
            mma_bf16(acc[2 * p],     ah, bh[0], bh[1]);
            mma_bf16(acc[2 * p],     ah, bl[0], bl[1]);
            mma_bf16(acc[2 * p],     al, bh[0], bh[1]);
            mma_bf16(acc[2 * p + 1], ah, bh[2], bh[3]);
            mma_bf16(acc[2 * p + 1], ah, bl[2], bl[3]);
            mma_bf16(acc[2 * p + 1], al, bh[2], bh[3]);
            bH += 16 * TP; bL += 16 * TP;
        }
    }
}

// ---------------------------------------------------------------------------
// K0: bf16 hi/lo weight staging. tile 0 = Wc; tiles 1..6 = [Wih_f;Wih_b] blocks
// ---------------------------------------------------------------------------
__global__ __launch_bounds__(256) void k0_prep(
    const float* __restrict__ Wc, const float* __restrict__ Wih_f, const float* __restrict__ Wih_b)
{
    const int i = blockIdx.x;
    const float* src;
    if (i == 0) src = Wc;
    else { int cb = (i - 1) * 128; src = (cb < 384) ? (Wih_f + cb * 128) : (Wih_b + (cb - 384) * 128); }
    for (int p = threadIdx.x; p < 128 * 64; p += 256) {
        int j = p >> 6, kp = (p & 63) * 2;
        float x0 = src[j * 128 + kp], x1 = src[j * 128 + kp + 1];
        __nv_bfloat162 hh, ll;
        bsplit(x0, hh.x, ll.x);
        bsplit(x1, hh.y, ll.y);
        int e = i * 16384 + j * 128 + kp;
        *(__nv_bfloat162*)(g_Bhi + e) = hh;
        *(__nv_bfloat162*)(g_Blo + e) = ll;
    }
}

// issue cp.async gather of 128 embedding rows (512B each) into stage
__device__ __forceinline__ void gather_pref(
    uint32_t stg_u, const float* __restrict__ emb, const int* tk_s, int t)
{
    #pragma unroll
    for (int i = 0; i < 8; i++) {
        int idx = i * 512 + t;
        int row = idx >> 5, ch = idx & 31;
        cpa16(stg_u + (uint32_t)(row * (SP * 4) + ch * 16),
              emb + (size_t)tk_s[row] * 128 + ch * 4);
    }
    CP_COMMIT();
}

// ---------------------------------------------------------------------------
// K1: persistent (grid 148, 512 thr). Per tile (4 statements): prefetched
//     gather -> tree reduce -> bf16 split -> 3-term mma.sync GEMM vs Wc ->
//     shuffle epilogue (c(v)*bc bias, per-stmt max, relu) -> hi/lo staging.
// ---------------------------------------------------------------------------
__global__ __launch_bounds__(512) void k1_stmt(
    const float* __restrict__ emb, const float* __restrict__ bc,
    const int* __restrict__ toks_g)
{
    extern __shared__ char smraw[];
    __shared__ int tkA[128], tkB[128];
    __shared__ float bcs[128];
    __shared__ float epi[1024];

    const int t = threadIdx.x, w = t >> 5, lane = t & 31;
    const int wr = w & 7, wc = w >> 3;
    const uint32_t rawu = s2u(smraw);
    const uint32_t alu = (rawu + 1023u) & ~1023u;
    char* base = smraw + (alu - rawu);
    float* stg = (float*)(base + OFF_STG);
    float4* As4 = (float4*)stg;
    const uint32_t stg_u = alu + OFF_STG;

    if (t < 128) { bcs[t] = bc[t]; tkA[t] = toks_g[blockIdx.x * 128 + t] + 1; }
    __syncthreads();
    gather_pref(stg_u, emb, tkA, t);
    if ((int)blockIdx.x + 148 < 2048 && t < 128)
        tkB[t] = toks_g[(blockIdx.x + 148) * 128 + t] + 1;

    // Wc hi/lo tiles once
    {
        const float4* sh = (const float4*)g_Bhi;
        const float4* sl = (const float4*)g_Blo;
        #pragma unroll
        for (int i = 0; i < 4; i++) {
            int idx = i * 512 + t, jj = idx >> 4, sg = idx & 15;
            *(float4*)(base + OFF_BH + jj * TP + sg * 16) = sh[idx];
            *(float4*)(base + OFF_BL + jj * TP + sg * 16) = sl[idx];
        }
    }

    int jpar = 0;
    for (int tile = blockIdx.x; tile < 2048; tile += 148, jpar ^= 1) {
        CP_WAIT0();
        __syncthreads();

        // ---- tree reduce, strict heap levels (rows: stmt*32 + node) ----
        if (t < 128) {   // L4: p=15 (single child 31)
            int tt = t >> 5, k4 = t & 31;
            As4[(tt * 32 + 15) * 33 + k4] = f4add(As4[(tt * 32 + 15) * 33 + k4], As4[(tt * 32 + 31) * 33 + k4]);
        }
        __syncthreads();
        #pragma unroll
        for (int i = 0; i < 2; i++) {   // L3: p=7..14 (1024 tasks)
            int idx = i * 512 + t;
            int k4 = idx & 31, q = idx >> 5, tt = q & 3, p = 7 + (q >> 2);
            int br = (tt * 32 + p) * 33;
            As4[br + k4] = f4add(As4[br + k4],
                          f4add(As4[(tt * 32 + 2 * p + 1) * 33 + k4], As4[(tt * 32 + 2 * p + 2) * 33 + k4]));
        }
        __syncthreads();
        {   // L2: p=3..6 (512 tasks)
            int k4 = t & 31, q = t >> 5, tt = q & 3, p = 3 + (q >> 2);
            int br = (tt * 32 + p) * 33;
            As4[br + k4] = f4add(As4[br + k4],
                          f4add(As4[(tt * 32 + 2 * p + 1) * 33 + k4], As4[(tt * 32 + 2 * p + 2) * 33 + k4]));
        }
        __syncthreads();
        if (t < 256) {   // L1: p=1..2 (256 tasks)
            int k4 = t & 31, q = t >> 5, tt = q & 3, p = 1 + (q >> 2);
            int br = (tt * 32 + p) * 33;
            As4[br + k4] = f4add(As4[br + k4],
                          f4add(As4[(tt * 32 + 2 * p + 1) * 33 + k4], As4[(tt * 32 + 2 * p + 2) * 33 + k4]));
        }
        __syncthreads();
        if (t < 128) {   // L0: p=0
            int tt = t >> 5, k4 = t & 31;
            int br = (tt * 32) * 33;
            As4[br + k4] = f4add(As4[br + k4], f4add(As4[(tt * 32 + 1) * 33 + k4], As4[(tt * 32 + 2) * 33 + k4]));
        }
        __syncthreads();

        // ---- fp32 -> bf16 hi/lo A tiles ----
        #pragma unroll
        for (int i = 0; i < 16; i++) {
            int idx = i * 512 + t;
            int row = idx >> 6, c2 = idx & 63;
            float2 v = *(const float2*)(stg + row * SP + c2 * 2);
            __nv_bfloat162 hh, ll;
            bsplit(v.x, hh.x, ll.x);
            bsplit(v.y, hh.y, ll.y);
            *(__nv_bfloat162*)(base + OFF_AH + row * TP + c2 * 4) = hh;
            *(__nv_bfloat162*)(base + OFF_AL + row * TP + c2 * 4) = ll;
        }
        __syncthreads();

        // ---- prefetch next tile's gather into (now free) stage ----
        int nxt = tile + 148;
        if (nxt < 2048) gather_pref(stg_u, emb, jpar ? tkA : tkB, t);
        if (nxt + 148 < 2048 && t < 128)
            (jpar ? tkB : tkA)[t] = toks_g[(nxt + 148) * 128 + t] + 1;

        // ---- GEMM (16 warps: wr x wc) ----
        float acc[8][4];
        #pragma unroll
        for (int n = 0; n < 8; n++)
            #pragma unroll
            for (int c = 0; c < 4; c++) acc[n][c] = 0.f;
        gemm_tile8(alu + OFF_AH, alu + OFF_AL, alu + OFF_BH, alu + OFF_BL, wr, wc, lane, acc);

        // ---- shuffle epilogue: max over 32 nodes of acc + csz*bc, relu ----
        const int rr0 = (wr & 1) * 16 + (lane >> 2);
        const float cz0 = c_cszf[rr0], cz1 = c_cszf[rr0 + 8];
        #pragma unroll
        for (int nt = 0; nt < 8; nt++) {
            int c0 = 64 * wc + nt * 8 + 2 * (lane & 3);
            float b0 = bcs[c0], b1 = bcs[c0 + 1];
            float m0 = fmaxf(acc[nt][0] + cz0 * b0, acc[nt][2] + cz1 * b0);
            float m1 = fmaxf(acc[nt][1] + cz0 * b1, acc[nt][3] + cz1 * b1);
            #pragma unroll
            for (int o = 4; o <= 16; o <<= 1) {
                m0 = fmaxf(m0, __shfl_xor_sync(0xffffffffu, m0, o));
                m1 = fmaxf(m1, __shfl_xor_sync(0xffffffffu, m1, o));
            }
            if ((lane >> 2) == 0) { epi[wr * 128 + c0] = m0; epi[wr * 128 + c0 + 1] = m1; }
        }
        __syncthreads();
        {
            int st = t >> 7, col = t & 127;
            float m = fmaxf(fmaxf(epi[(2 * st) * 128 + col], epi[(2 * st + 1) * 128 + col]), 0.f);
            __nv_bfloat16 hi, lo;
            bsplit(m, hi, lo);
            int e = (tile * 4 + st) * 128 + col;
            g_Ahi[e] = hi; g_Alo[e] = lo;
        }
        __syncthreads();
    }
}

// ---------------------------------------------------------------------------
// K1b: persistent gi GEMM (512 thr). 144 CTAs = (24 rb-groups x 6 gate-blocks).
//      B loaded once; A double-buffered via cp.async. Adds bih bias.
// ---------------------------------------------------------------------------
__device__ __forceinline__ void k1b_prefA(uint32_t dstAH, uint32_t dstAL, int rb, int t){
    const float4* sah = (const float4*)(g_Ahi + rb * 16384);
    const float4* sal = (const float4*)(g_Alo + rb * 16384);
    #pragma unroll
    for (int i = 0; i < 4; i++) {
        int idx = i * 512 + t, jj = idx >> 4, sg = idx & 15;
        cpa16(dstAH + jj * TP + sg * 16, sah + idx);
        cpa16(dstAL + jj * TP + sg * 16, sal + idx);
    }
    CP_COMMIT();
}

__global__ __launch_bounds__(512) void k1b_gi(
    const float* __restrict__ bih_f, const float* __restrict__ bih_b)
{
    extern __shared__ char smraw[];
    __shared__ float bias_s[128];
    const int t = threadIdx.x, w = t >> 5, lane = t & 31;
    const int wr = w & 7, wc = w >> 3;
    const int by = blockIdx.x % 6, rb0 = blockIdx.x / 6;
    const uint32_t rawu = s2u(smraw);
    const uint32_t alu = (rawu + 1023u) & ~1023u;
    char* base = smraw + (alu - rawu);
    const uint32_t offAH0 = 69632u, offAL0 = 104448u;
    const uint32_t offAH1 = 139264u, offAL1 = 174080u;

    if (t < 128) bias_s[t] = (by < 3) ? bih_f[by * 128 + t] : bih_b[(by - 3) * 128 + t];

    k1b_prefA(alu + offAH0, alu + offAL0, rb0, t);

    {   // B gate-block once
        const float4* sbh = (const float4*)(g_Bhi + (1 + by) * 16384);
        const float4* sbl = (const float4*)(g_Blo + (1 + by) * 16384);
        #pragma unroll
        for (int i = 0; i < 4; i++) {
            int idx = i * 512 + t, jj = idx >> 4, sg = idx & 15;
            *(float4*)(base + 0     + jj * TP + sg * 16) = sbh[idx];
            *(float4*)(base + 34816 + jj * TP + sg * 16) = sbl[idx];
        }
    }

    int pb = 0;
    for (int rb = rb0; rb < 64; rb += 24, pb ^= 1) {
        CP_WAIT0();
        __syncthreads();
        if (rb + 24 < 64)
            k1b_prefA(alu + (pb ? offAH0 : offAH1), alu + (pb ? offAL0 : offAL1), rb + 24, t);

        float acc[8][4];
        #pragma unroll
        for (int n = 0; n < 8; n++)
            #pragma unroll
            for (int c = 0; c < 4; c++) acc[n][c] = 0.f;
        gemm_tile8(alu + (pb ? offAH1 : offAH0), alu + (pb ? offAL1 : offAL0),
                   alu + 0, alu + 34816, wr, wc, lane, acc);

        const int row = rb * 128 + 16 * wr + (lane >> 2);
        float* o0 = g_gi + (size_t)row * 768 + by * 128 + 64 * wc;
        float* o1 = o0 + 8 * 768;
        const int cb = (lane & 3) * 2;
        #pragma unroll
        for (int nt = 0; nt < 8; nt++) {
            float b0 = bias_s[64 * wc + nt * 8 + cb];
            float b1 = bias_s[64 * wc + nt * 8 + cb + 1];
            *(float2*)(o0 + nt * 8 + cb) = make_float2(acc[nt][0] + b0, acc[nt][1] + b1);
            *(float2*)(o1 + nt * 8 + cb) = make_float2(acc[nt][2] + b0, acc[nt][3] + b1);
        }
    }
}

// ---------------------------------------------------------------------------
__device__ __forceinline__ void ffma2(ull& d, ull a, ull b){
    asm("fma.rn.f32x2 %0, %1, %2, %0;" : "+l"(d) : "l"(a), "l"(b));
}
__device__ __forceinline__ float2 ull2f2(ull v){
    float2 f; asm("mov.b64 {%0, %1}, %2;" : "=f"(f.x), "=f"(f.y) : "l"(v)); return f;
}

// ---------------------------------------------------------------------------
// K2: GRU recurrence. 128 CTAs, one per (batch, dir). bih pre-folded into gi.
// ---------------------------------------------------------------------------
__global__ __launch_bounds__(768) void k2_gru(
    const float* __restrict__ Whh_f, const float* __restrict__ bhh_f,
    const float* __restrict__ Whh_b, const float* __restrict__ bhh_b)
{
    __shared__ float h_s[128];
    __shared__ float part[768];
    __shared__ __align__(16) float gi_buf[2][384];
    __shared__ float bhh_s[384];

    const int t = threadIdx.x;
    const int b = blockIdx.x >> 1, dir = blockIdx.x & 1;
    const float* Whh = dir ? Whh_b : Whh_f;
    const float* bhh = dir ? bhh_b : bhh_f;

    const int j = (t < 384) ? t : t - 384;
    const int half = (t < 384) ? 0 : 1;

    ull w2[32];
    {
        const ulonglong2* wp = (const ulonglong2*)(Whh + j * 128 + half * 64);
        #pragma unroll
        for (int i = 0; i < 16; i++) { ulonglong2 v = wp[i]; w2[2*i] = v.x; w2[2*i+1] = v.y; }
    }
    if (t < 384) bhh_s[t] = bhh[t];
    if (t < 128) h_s[t] = 0.f;

    const float* gsrc = g_gi + (size_t)(b * LL + (dir ? LL - 1 : 0)) * 768 + dir * 384;
    const int stp = dir ? -768 : 768;

    if (t < 96) cpa16(s2u(&gi_buf[0][0]) + t * 16, gsrc + t * 4);
    CP_COMMIT();
    __syncthreads();

    float hmax = -3e38f;
    for (int l = 0; l < LL; l++) {
        if (l + 1 < LL && t < 96)
            cpa16(s2u(&gi_buf[(l + 1) & 1][0]) + t * 16, gsrc + (l + 1) * stp + t * 4);
        CP_COMMIT();

        // matvec: 4 independent accumulators
        ull a0 = 0, a1 = 0, a2 = 0, a3 = 0;
        const ulonglong2* hp = (const ulonglong2*)(h_s + half * 64);
        #pragma unroll
        for (int i = 0; i < 16; i += 2) {
            ulonglong2 h0 = hp[i], h1 = hp[i + 1];
            ffma2(a0, w2[2*i],     h0.x);
            ffma2(a1, w2[2*i + 1], h0.y);
            ffma2(a2, w2[2*i + 2], h1.x);
            ffma2(a3, w2[2*i + 3], h1.y);
        }
        float2 f0 = ull2f2(a0), f1 = ull2f2(a1), f2 = ull2f2(a2), f3 = ull2f2(a3);
        part[t] = ((f0.x + f0.y) + (f1.x + f1.y)) + ((f2.x + f2.y) + (f3.x + f3.y));
        CP_WAIT1();
        __syncthreads();

        if (t < 128) {
            const float* gb = gi_buf[l & 1];
            float ghr = part[t]       + part[384 + t] + bhh_s[t];
            float ghz = part[128 + t] + part[512 + t] + bhh_s[128 + t];
            float ghn = part[256 + t] + part[640 + t] + bhh_s[256 + t];
            float r = __fdividef(1.f, 1.f + __expf(-(gb[t] + ghr)));
            float z = __fdividef(1.f, 1.f + __expf(-(gb[128 + t] + ghz)));
            float y = gb[256 + t] + r * ghn;
            float n = 1.f - __fdividef(2.f, __expf(2.f * y) + 1.f);
            float hnew = (1.f - z) * n + z * h_s[t];
            h_s[t] = hnew;
            hmax = fmaxf(hmax, hnew);
        }
        __syncthreads();
    }
    if (t < 128) g_pooled[b * 256 + dir * 128 + t] = hmax;
}

// ---------------------------------------------------------------------------
// K3: lvec = pooled @ linW^T + linb ; rvec = doc attention.
// ---------------------------------------------------------------------------
__global__ __launch_bounds__(256) void k3_out(
    const float* __restrict__ emb, const float* __restrict__ Wb,
    const float* __restrict__ linW, const float* __restrict__ linb,
    const int* __restrict__ doc, float* __restrict__ out)
{
    __shared__ float demb[DLN * 128];
    __shared__ float h0[128];
    __shared__ float u[128];
    __shared__ float sc[DLN];
    __shared__ float ex[DLN];
    __shared__ float inv_s;
    __shared__ float pool[256];
    __shared__ int dti[DLN];

    const int t = threadIdx.x, b = blockIdx.x;
    const int wid = t >> 5, lane = t & 31;

    pool[t] = g_pooled[b * 256 + t];
    if (t < DLN) dti[t] = doc[b * DLN + t] + 1;
    __syncthreads();

    #pragma unroll
    for (int i = 0; i < 10; i++) {
        int idx = i * 256 + t;
        demb[idx] = emb[(size_t)dti[idx >> 7] * 128 + (idx & 127)];
    }
    __syncthreads();

    if (t < 128) {
        float s = 0.f;
        #pragma unroll
        for (int l = 0; l < DLN; l++) s += demb[l * 128 + t];
        h0[t] = s * (1.f / (float)DLN);
    }
    __syncthreads();

    for (int rr = 0; rr < 16; rr++) {
        int row = wid * 16 + rr;
        const float* wr = Wb + row * 128;
        float s = wr[lane] * h0[lane] + wr[lane + 32] * h0[lane + 32]
                + wr[lane + 64] * h0[lane + 64] + wr[lane + 96] * h0[lane + 96];
        #pragma unroll
        for (int o = 16; o > 0; o >>= 1) s += __shfl_xor_sync(0xffffffffu, s, o);
        if (lane == 0) u[row] = s;
    }
    __syncthreads();

    for (int l = wid; l < DLN; l += 8) {
        const float* dr = demb + l * 128;
        float s = dr[lane] * u[lane] + dr[lane + 32] * u[lane + 32]
                + dr[lane + 64] * u[lane + 64] + dr[lane + 96] * u[lane + 96];
        #pragma unroll
        for (int o = 16; o > 0; o >>= 1) s += __shfl_xor_sync(0xffffffffu, s, o);
        if (lane == 0) sc[l] = s;
    }
    __syncthreads();

    if (t == 0) {
        float mx = sc[0];
        #pragma unroll
        for (int l = 1; l < DLN; l++) mx = fmaxf(mx, sc[l]);
        float sum = 0.f;
        #pragma unroll
        for (int l = 0; l < DLN; l++) { float e = expf(sc[l] - mx); ex[l] = e; sum += e; }
        inv_s = 1.f / sum;
    }
    __syncthreads();

    if (t < 128) {
        float rv = 0.f;
        #pragma unroll
        for (int l = 0; l < DLN; l++) rv += ex[l] * demb[l * 128 + t];
        out[BB * 128 + b * 128 + t] = rv * inv_s;
    }

    for (int rr = 0; rr < 16; rr++) {
        int row = wid * 16 + rr;
        const float* wr = linW + row * 256;
        float s = 0.f;
        #pragma unroll
        for (int q = 0; q < 8; q++) s += wr[lane + 32 * q] * pool[lane + 32 * q];
        #pragma unroll
        for (int o = 16; o > 0; o >>= 1) s += __shfl_xor_sync(0xffffffffu, s, o);
        if (lane == 0) out[b * 128 + row] = s + linb[row];
    }
}

// ---------------------------------------------------------------------------
extern "C" void kernel_launch(void* const* d_in, const int* in_sizes, int n_in,
                              void* d_out, int out_size)
{
    const float* emb   = (const float*)d_in[0];
    const float* Wc    = (const float*)d_in[1];
    const float* bc    = (const float*)d_in[2];
    const float* Wb    = (const float*)d_in[3];
    const float* Wih_f = (const float*)d_in[4];
    const float* Whh_f = (const float*)d_in[5];
    const float* bih_f = (const float*)d_in[6];
    const float* bhh_f = (const float*)d_in[7];
    const float* Wih_b = (const float*)d_in[8];
    const float* Whh_b = (const float*)d_in[9];
    const float* bih_b = (const float*)d_in[10];
    const float* bhh_b = (const float*)d_in[11];
    const float* linW  = (const float*)d_in[12];
    const float* linb  = (const float*)d_in[13];
    const int* node_tokens = (const int*)d_in[14];
    const int* doc_tokens  = (const int*)d_in[15];
    float* out = (float*)d_out;

    cudaFuncSetAttribute(k1_stmt, cudaFuncAttributeMaxDynamicSharedMemorySize, K1_DYN);
    cudaFuncSetAttribute(k1b_gi,  cudaFuncAttributeMaxDynamicSharedMemorySize, K1B_DYN);

    k0_prep<<<7, 256>>>(Wc, Wih_f, Wih_b);
    k1_stmt<<<148, 512, K1_DYN>>>(emb, bc, node_tokens);
    k1b_gi<<<144, 512, K1B_DYN>>>(bih_f, bih_b);
    k2_gru<<<BB * 2, 768>>>(Whh_f, bhh_f, Whh_b, bhh_b);
    k3_out<<<BB, 256>>>(emb, Wb, linW, linb, doc_tokens, out);
}

// round 9
// speedup vs baseline: 2.2357x; 1.1058x over previous
#include <cuda_runtime.h>
#include <cuda_fp16.h>
#include <math.h>
#include <stdint.h>

#define TS 8192
#define BB 64
#define LL 128
#define DLN 20
#define TP 272      // fp16 tile pitch in BYTES (136 halves)
#define SP 132      // fp32 stage pitch in floats

typedef unsigned long long ull;

// ---------------- scratch (device globals; no allocation allowed) ----------
__device__ float g_gi[TS * 768];                     // 25 MB
__device__ float g_pooled[BB * 256];
__device__ __align__(16) __half g_Bhi[7 * 16384];    // Wc + 6 Wih row-blocks, [j][k] fp16 hi
__device__ __align__(16) __half g_Blo[7 * 16384];    // fp16 lo
__device__ __align__(16) __half g_Af[TS * 128];      // stmt_h, single fp16

// subtree sizes of the 32-node binary heap
__constant__ float c_cszf[32] = {32,16,15,8,7,7,7,4,3,3,3,3,3,3,3,2,
                                 1,1,1,1,1,1,1,1,1,1,1,1,1,1,1,1};

// ---------------- helpers ---------------------------------------------------
__device__ __forceinline__ uint32_t s2u(const void* p){
    uint32_t a;
    asm("{ .reg .u64 t; cvta.to.shared.u64 t, %1; cvt.u32.u64 %0, t; }" : "=r"(a) : "l"(p));
    return a;
}
__device__ __forceinline__ void ldsm4(uint32_t addr, uint32_t r[4]){
    asm volatile("ldmatrix.sync.aligned.m8n8.x4.shared.b16 {%0,%1,%2,%3}, [%4];"
        : "=r"(r[0]), "=r"(r[1]), "=r"(r[2]), "=r"(r[3]) : "r"(addr));
}
__device__ __forceinline__ void mma_f16(float d[4], const uint32_t a[4], uint32_t b0, uint32_t b1){
    asm volatile("mma.sync.aligned.m16n8k16.row.col.f32.f16.f16.f32 "
        "{%0,%1,%2,%3}, {%4,%5,%6,%7}, {%8,%9}, {%0,%1,%2,%3};"
        : "+f"(d[0]), "+f"(d[1]), "+f"(d[2]), "+f"(d[3])
        : "r"(a[0]), "r"(a[1]), "r"(a[2]), "r"(a[3]), "r"(b0), "r"(b1));
}
__device__ __forceinline__ float4 f4add(float4 a, float4 b){
    return make_float4(a.x + b.x, a.y + b.y, a.z + b.z, a.w + b.w);
}
__device__ __forceinline__ void hsplit(float x, __half& h, __half& l){
    h = __float2half_rn(x);
    l = __float2half_rn(x - __half2float(h));
}
__device__ __forceinline__ void cpa16(uint32_t dst, const void* src){
    asm volatile("cp.async.cg.shared.global [%0], [%1], 16;"
        :: "r"(dst), "l"(__cvta_generic_to_global(src)) : "memory");
}
#define CP_COMMIT() asm volatile("cp.async.commit_group;" ::: "memory")
#define CP_WAIT0()  asm volatile("cp.async.wait_group 0;" ::: "memory")
#define CP_WAIT1()  asm volatile("cp.async.wait_group 1;" ::: "memory")

// smem layouts (byte offsets from aligned base). One 128x136 fp16 tile = 34816 B.
// K1:  A | Bh | Bl | stage
#define K1_OFF_A   0
#define K1_OFF_BH  34816
#define K1_OFF_BL  69632
#define K1_OFF_STG 104448                // float[128][132] = 67584 B
#define K1_DYN  (1024 + 104448 + 67584)
// K1b: Bh | Bl | A0 | A1
#define K1B_OFF_BH 0
#define K1B_OFF_BL 34816
#define K1B_OFF_A0 69632
#define K1B_OFF_A1 104448
#define K1B_DYN (1024 + 139264)

// 128x64x128 fp16 2-term GEMM slice: warp (wr, wc) does rows 16*wr..+15,
// cols 64*wc..+63 (8 n-tiles). C = A*Bh + A*Bl.
__device__ __forceinline__ void gemm_tile8_2t(
    uint32_t sA, uint32_t sBH, uint32_t sBL,
    int wr, int wc, int lane, float acc[8][4])
{
    const uint32_t aOff = (uint32_t)(((lane & 15) + 16 * wr) * TP + ((lane >> 4) << 4));
    const uint32_t bOff = (uint32_t)((64 * wc + ((lane >> 4) << 3) + (lane & 7)) * TP
                                     + (((lane >> 3) & 1) << 4));
    #pragma unroll
    for (int ks = 0; ks < 8; ks++) {
        const uint32_t ko = ks * 32;          // 16 halves = 32 B
        uint32_t a[4];
        ldsm4(sA + aOff + ko, a);
        uint32_t bH = sBH + bOff + ko, bL = sBL + bOff + ko;
        #pragma unroll
        for (int p = 0; p < 4; p++) {
            uint32_t bh[4], bl[4];
            ldsm4(bH, bh);
            ldsm4(bL, bl);
            mma_f16(acc[2 * p],     a, bh[0], bh[1]);
            mma_f16(acc[2 * p],     a, bl[0], bl[1]);
            mma_f16(acc[2 * p + 1], a, bh[2], bh[3]);
            mma_f16(acc[2 * p + 1], a, bl[2], bl[3]);
            bH += 16 * TP; bL += 16 * TP;
        }
    }
}

// ---------------------------------------------------------------------------
// K0: fp16 hi/lo weight staging. tile 0 = Wc; tiles 1..6 = [Wih_f;Wih_b] blocks
// ---------------------------------------------------------------------------
__global__ __launch_bounds__(256) void k0_prep(
    const float* __restrict__ Wc, const float* __restrict__ Wih_f, const float* __restrict__ Wih_b)
{
    const int i = blockIdx.x;
    const float* src;
    if (i == 0) src = Wc;
    else { int cb = (i - 1) * 128; src = (cb < 384) ? (Wih_f + cb * 128) : (Wih_b + (cb - 384) * 128); }
    for (int p = threadIdx.x; p < 128 * 64; p += 256) {
        int j = p >> 6, kp = (p & 63) * 2;
        float x0 = src[j * 128 + kp], x1 = src[j * 128 + kp + 1];
        __half2 hh, ll;
        hsplit(x0, hh.x, ll.x);
        hsplit(x1, hh.y, ll.y);
        int e = i * 16384 + j * 128 + kp;
        *(__half2*)(g_Bhi + e) = hh;
        *(__half2*)(g_Blo + e) = ll;
    }
}

// issue cp.async gather of 128 embedding rows (512B each) into stage
__device__ __forceinline__ void gather_pref(
    uint32_t stg_u, const float* __restrict__ emb, const int* tk_s, int t)
{
    #pragma unroll
    for (int i = 0; i < 8; i++) {
        int idx = i * 512 + t;
        int row = idx >> 5, ch = idx & 31;
        cpa16(stg_u + (uint32_t)(row * (SP * 4) + ch * 16),
              emb + (size_t)tk_s[row] * 128 + ch * 4);
    }
    CP_COMMIT();
}

// ---------------------------------------------------------------------------
// K1: persistent (grid 148, 512 thr). Per tile (4 statements): prefetched
//     gather -> tree reduce -> fp16 round -> 2-term mma.sync GEMM vs Wc ->
//     shuffle epilogue (c(v)*bc bias, per-stmt max, relu) -> fp16 staging.
// ---------------------------------------------------------------------------
__global__ __launch_bounds__(512) void k1_stmt(
    const float* __restrict__ emb, const float* __restrict__ bc,
    const int* __restrict__ toks_g)
{
    extern __shared__ char smraw[];
    __shared__ int tkA[128], tkB[128];
    __shared__ float bcs[128];
    __shared__ float epi[1024];

    const int t = threadIdx.x, w = t >> 5, lane = t & 31;
    const int wr = w & 7, wc = w >> 3;
    const uint32_t rawu = s2u(smraw);
    const uint32_t alu = (rawu + 1023u) & ~1023u;
    char* base = smraw + (alu - rawu);
    float* stg = (float*)(base + K1_OFF_STG);
    float4* As4 = (float4*)stg;
    const uint32_t stg_u = alu + K1_OFF_STG;

    if (t < 128) { bcs[t] = bc[t]; tkA[t] = toks_g[blockIdx.x * 128 + t] + 1; }
    __syncthreads();
    gather_pref(stg_u, emb, tkA, t);
    if ((int)blockIdx.x + 148 < 2048 && t < 128)
        tkB[t] = toks_g[(blockIdx.x + 148) * 128 + t] + 1;

    // Wc hi/lo tiles once
    {
        const float4* sh = (const float4*)g_Bhi;
        const float4* sl = (const float4*)g_Blo;
        #pragma unroll
        for (int i = 0; i < 4; i++) {
            int idx = i * 512 + t, jj = idx >> 4, sg = idx & 15;
            *(float4*)(base + K1_OFF_BH + jj * TP + sg * 16) = sh[idx];
            *(float4*)(base + K1_OFF_BL + jj * TP + sg * 16) = sl[idx];
        }
    }

    int jpar = 0;
    for (int tile = blockIdx.x; tile < 2048; tile += 148, jpar ^= 1) {
        CP_WAIT0();
        __syncthreads();

        // ---- tree reduce, strict heap levels (rows: stmt*32 + node) ----
        if (t < 128) {   // L4: p=15 (single child 31)
            int tt = t >> 5, k4 = t & 31;
            As4[(tt * 32 + 15) * 33 + k4] = f4add(As4[(tt * 32 + 15) * 33 + k4], As4[(tt * 32 + 31) * 33 + k4]);
        }
        __syncthreads();
        #pragma unroll
        for (int i = 0; i < 2; i++) {   // L3: p=7..14 (1024 tasks)
            int idx = i * 512 + t;
            int k4 = idx & 31, q = idx >> 5, tt = q & 3, p = 7 + (q >> 2);
            int br = (tt * 32 + p) * 33;
            As4[br + k4] = f4add(As4[br + k4],
                          f4add(As4[(tt * 32 + 2 * p + 1) * 33 + k4], As4[(tt * 32 + 2 * p + 2) * 33 + k4]));
        }
        __syncthreads();
        {   // L2: p=3..6 (512 tasks)
            int k4 = t & 31, q = t >> 5, tt = q & 3, p = 3 + (q >> 2);
            int br = (tt * 32 + p) * 33;
            As4[br + k4] = f4add(As4[br + k4],
                          f4add(As4[(tt * 32 + 2 * p + 1) * 33 + k4], As4[(tt * 32 + 2 * p + 2) * 33 + k4]));
        }
        __syncthreads();
        if (t < 256) {   // L1: p=1..2 (256 tasks)
            int k4 = t & 31, q = t >> 5, tt = q & 3, p = 1 + (q >> 2);
            int br = (tt * 32 + p) * 33;
            As4[br + k4] = f4add(As4[br + k4],
                          f4add(As4[(tt * 32 + 2 * p + 1) * 33 + k4], As4[(tt * 32 + 2 * p + 2) * 33 + k4]));
        }
        __syncthreads();
        if (t < 128) {   // L0: p=0
            int tt = t >> 5, k4 = t & 31;
            int br = (tt * 32) * 33;
            As4[br + k4] = f4add(As4[br + k4], f4add(As4[(tt * 32 + 1) * 33 + k4], As4[(tt * 32 + 2) * 33 + k4]));
        }
        __syncthreads();

        // ---- fp32 -> fp16 A tile (single rounding) ----
        #pragma unroll
        for (int i = 0; i < 16; i++) {
            int idx = i * 512 + t;
            int row = idx >> 6, c2 = idx & 63;
            float2 v = *(const float2*)(stg + row * SP + c2 * 2);
            __half2 hh;
            hh.x = __float2half_rn(v.x);
            hh.y = __float2half_rn(v.y);
            *(__half2*)(base + K1_OFF_A + row * TP + c2 * 4) = hh;
        }
        __syncthreads();

        // ---- prefetch next tile's gather into (now free) stage ----
        int nxt = tile + 148;
        if (nxt < 2048) gather_pref(stg_u, emb, jpar ? tkA : tkB, t);
        if (nxt + 148 < 2048 && t < 128)
            (jpar ? tkB : tkA)[t] = toks_g[(nxt + 148) * 128 + t] + 1;

        // ---- GEMM (16 warps: wr x wc), 2-term fp16 ----
        float acc[8][4];
        #pragma unroll
        for (int n = 0; n < 8; n++)
            #pragma unroll
            for (int c = 0; c < 4; c++) acc[n][c] = 0.f;
        gemm_tile8_2t(alu + K1_OFF_A, alu + K1_OFF_BH, alu + K1_OFF_BL, wr, wc, lane, acc);

        // ---- shuffle epilogue: max over 32 nodes of acc + csz*bc, relu ----
        const int rr0 = (wr & 1) * 16 + (lane >> 2);
        const float cz0 = c_cszf[rr0], cz1 = c_cszf[rr0 + 8];
        #pragma unroll
        for (int nt = 0; nt < 8; nt++) {
            int c0 = 64 * wc + nt * 8 + 2 * (lane & 3);
            float b0 = bcs[c0], b1 = bcs[c0 + 1];
            float m0 = fmaxf(acc[nt][0] + cz0 * b0, acc[nt][2] + cz1 * b0);
            float m1 = fmaxf(acc[nt][1] + cz0 * b1, acc[nt][3] + cz1 * b1);
            #pragma unroll
            for (int o = 4; o <= 16; o <<= 1) {
                m0 = fmaxf(m0, __shfl_xor_sync(0xffffffffu, m0, o));
                m1 = fmaxf(m1, __shfl_xor_sync(0xffffffffu, m1, o));
            }
            if ((lane >> 2) == 0) { epi[wr * 128 + c0] = m0; epi[wr * 128 + c0 + 1] = m1; }
        }
        __syncthreads();
        {
            int st = t >> 7, col = t & 127;
            float m = fmaxf(fmaxf(epi[(2 * st) * 128 + col], epi[(2 * st + 1) * 128 + col]), 0.f);
            g_Af[(tile * 4 + st) * 128 + col] = __float2half_rn(m);
        }
        __syncthreads();
    }
}

// ---------------------------------------------------------------------------
// K1b: persistent gi GEMM (512 thr). 144 CTAs = (24 rb-groups x 6 gate-blocks).
//      B hi/lo loaded once; single-fp16 A double-buffered via cp.async.
//      Adds bih bias (pre-folded out of k2).
// ---------------------------------------------------------------------------
__device__ __forceinline__ void k1b_prefA(uint32_t dstA, int rb, int t){
    const float4* sa = (const float4*)(g_Af + rb * 16384);
    #pragma unroll
    for (int i = 0; i < 4; i++) {
        int idx = i * 512 + t, jj = idx >> 4, sg = idx & 15;
        cpa16(dstA + jj * TP + sg * 16, sa + idx);
    }
    CP_COMMIT();
}

__global__ __launch_bounds__(512) void k1b_gi(
    const float* __restrict__ bih_f, const float* __restrict__ bih_b)
{
    extern __shared__ char smraw[];
    __shared__ float bias_s[128];
    const int t = threadIdx.x, w = t >> 5, lane = t & 31;
    const int wr = w & 7, wc = w >> 3;
    const int by = blockIdx.x % 6, rb0 = blockIdx.x / 6;
    const uint32_t rawu = s2u(smraw);
    const uint32_t alu = (rawu + 1023u) & ~1023u;
    char* base = smraw + (alu - rawu);

    if (t < 128) bias_s[t] = (by < 3) ? bih_f[by * 128 + t] : bih_b[(by - 3) * 128 + t];

    k1b_prefA(alu + K1B_OFF_A0, rb0, t);

    {   // B gate-block once
        const float4* sbh = (const float4*)(g_Bhi + (1 + by) * 16384);
        const float4* sbl = (const float4*)(g_Blo + (1 + by) * 16384);
        #pragma unroll
        for (int i = 0; i < 4; i++) {
            int idx = i * 512 + t, jj = idx >> 4, sg = idx & 15;
            *(float4*)(base + K1B_OFF_BH + jj * TP + sg * 16) = sbh[idx];
            *(float4*)(base + K1B_OFF_BL + jj * TP + sg * 16) = sbl[idx];
        }
    }

    int pb = 0;
    for (int rb = rb0; rb < 64; rb += 24, pb ^= 1) {
        CP_WAIT0();
        __syncthreads();
        if (rb + 24 < 64)
            k1b_prefA(alu + (pb ? K1B_OFF_A0 : K1B_OFF_A1), rb + 24, t);

        float acc[8][4];
        #pragma unroll
        for (int n = 0; n < 8; n++)
            #pragma unroll
            for (int c = 0; c < 4; c++) acc[n][c] = 0.f;
        gemm_tile8_2t(alu + (pb ? K1B_OFF_A1 : K1B_OFF_A0),
                      alu + K1B_OFF_BH, alu + K1B_OFF_BL, wr, wc, lane, acc);

        const int row = rb * 128 + 16 * wr + (lane >> 2);
        float* o0 = g_gi + (size_t)row * 768 + by * 128 + 64 * wc;
        float* o1 = o0 + 8 * 768;
        const int cb = (lane & 3) * 2;
        #pragma unroll
        for (int nt = 0; nt < 8; nt++) {
            float b0 = bias_s[64 * wc + nt * 8 + cb];
            float b1 = bias_s[64 * wc + nt * 8 + cb + 1];
            *(float2*)(o0 + nt * 8 + cb) = make_float2(acc[nt][0] + b0, acc[nt][1] + b1);
            *(float2*)(o1 + nt * 8 + cb) = make_float2(acc[nt][2] + b0, acc[nt][3] + b1);
        }
    }
}

// ---------------------------------------------------------------------------
__device__ __forceinline__ void ffma2(ull& d, ull a, ull b){
    asm("fma.rn.f32x2 %0, %1, %2, %0;" : "+l"(d) : "l"(a), "l"(b));
}
__device__ __forceinline__ float2 ull2f2(ull v){
    float2 f; asm("mov.b64 {%0, %1}, %2;" : "=f"(f.x), "=f"(f.y) : "l"(v)); return f;
}

// ---------------------------------------------------------------------------
// K2: GRU recurrence. 128 CTAs, one per (batch, dir). bih pre-folded into gi.
// ---------------------------------------------------------------------------
__global__ __launch_bounds__(768) void k2_gru(
    const float* __restrict__ Whh_f, const float* __restrict__ bhh_f,
    const float* __restrict__ Whh_b, const float* __restrict__ bhh_b)
{
    __shared__ float h_s[128];
    __shared__ float part[768];
    __shared__ __align__(16) float gi_buf[2][384];
    __shared__ float bhh_s[384];

    const int t = threadIdx.x;
    const int b = blockIdx.x >> 1, dir = blockIdx.x & 1;
    const float* Whh = dir ? Whh_b : Whh_f;
    const float* bhh = dir ? bhh_b : bhh_f;

    const int j = (t < 384) ? t : t - 384;
    const int half = (t < 384) ? 0 : 1;

    ull w2[32];
    {
        const ulonglong2* wp = (const ulonglong2*)(Whh + j * 128 + half * 64);
        #pragma unroll
        for (int i = 0; i < 16; i++) { ulonglong2 v = wp[i]; w2[2*i] = v.x; w2[2*i+1] = v.y; }
    }
    if (t < 384) bhh_s[t] = bhh[t];
    if (t < 128) h_s[t] = 0.f;

    const float* gsrc = g_gi + (size_t)(b * LL + (dir ? LL - 1 : 0)) * 768 + dir * 384;
    const int stp = dir ? -768 : 768;

    if (t < 96) cpa16(s2u(&gi_buf[0][0]) + t * 16, gsrc + t * 4);
    CP_COMMIT();
    __syncthreads();

    float hmax = -3e38f;
    for (int l = 0; l < LL; l++) {
        if (l + 1 < LL && t < 96)
            cpa16(s2u(&gi_buf[(l + 1) & 1][0]) + t * 16, gsrc + (l + 1) * stp + t * 4);
        CP_COMMIT();

        // matvec: 4 independent accumulators
        ull a0 = 0, a1 = 0, a2 = 0, a3 = 0;
        const ulonglong2* hp = (const ulonglong2*)(h_s + half * 64);
        #pragma unroll
        for (int i = 0; i < 16; i += 2) {
            ulonglong2 h0 = hp[i], h1 = hp[i + 1];
            ffma2(a0, w2[2*i],     h0.x);
            ffma2(a1, w2[2*i + 1], h0.y);
            ffma2(a2, w2[2*i + 2], h1.x);
            ffma2(a3, w2[2*i + 3], h1.y);
        }
        float2 f0 = ull2f2(a0), f1 = ull2f2(a1), f2 = ull2f2(a2), f3 = ull2f2(a3);
        part[t] = ((f0.x + f0.y) + (f1.x + f1.y)) + ((f2.x + f2.y) + (f3.x + f3.y));
        CP_WAIT1();
        __syncthreads();

        if (t < 128) {
            const float* gb = gi_buf[l & 1];
            float ghr = part[t]       + part[384 + t] + bhh_s[t];
            float ghz = part[128 + t] + part[512 + t] + bhh_s[128 + t];
            float ghn = part[256 + t] + part[640 + t] + bhh_s[256 + t];
            float r = __fdividef(1.f, 1.f + __expf(-(gb[t] + ghr)));
            float z = __fdividef(1.f, 1.f + __expf(-(gb[128 + t] + ghz)));
            float y = gb[256 + t] + r * ghn;
            float n = 1.f - __fdividef(2.f, __expf(2.f * y) + 1.f);
            float hnew = (1.f - z) * n + z * h_s[t];
            h_s[t] = hnew;
            hmax = fmaxf(hmax, hnew);
        }
        __syncthreads();
    }
    if (t < 128) g_pooled[b * 256 + dir * 128 + t] = hmax;
}

// ---------------------------------------------------------------------------
// K3: lvec = pooled @ linW^T + linb ; rvec = doc attention.
// ---------------------------------------------------------------------------
__global__ __launch_bounds__(256) void k3_out(
    const float* __restrict__ emb, const float* __restrict__ Wb,
    const float* __restrict__ linW, const float* __restrict__ linb,
    const int* __restrict__ doc, float* __restrict__ out)
{
    __shared__ float demb[DLN * 128];
    __shared__ float h0[128];
    __shared__ float u[128];
    __shared__ float sc[DLN];
    __shared__ float ex[DLN];
    __shared__ float inv_s;
    __shared__ float pool[256];
    __shared__ int dti[DLN];

    const int t = threadIdx.x, b = blockIdx.x;
    const int wid = t >> 5, lane = t & 31;

    pool[t] = g_pooled[b * 256 + t];
    if (t < DLN) dti[t] = doc[b * DLN + t] + 1;
    __syncthreads();

    #pragma unroll
    for (int i = 0; i < 10; i++) {
        int idx = i * 256 + t;
        demb[idx] = emb[(size_t)dti[idx >> 7] * 128 + (idx & 127)];
    }
    __syncthreads();

    if (t < 128) {
        float s = 0.f;
        #pragma unroll
        for (int l = 0; l < DLN; l++) s += demb[l * 128 + t];
        h0[t] = s * (1.f / (float)DLN);
    }
    __syncthreads();

    for (int rr = 0; rr < 16; rr++) {
        int row = wid * 16 + rr;
        const float* wr = Wb + row * 128;
        float s = wr[lane] * h0[lane] + wr[lane + 32] * h0[lane + 32]
                + wr[lane + 64] * h0[lane + 64] + wr[lane + 96] * h0[lane + 96];
        #pragma unroll
        for (int o = 16; o > 0; o >>= 1) s += __shfl_xor_sync(0xffffffffu, s, o);
        if (lane == 0) u[row] = s;
    }
    __syncthreads();

    for (int l = wid; l < DLN; l += 8) {
        const float* dr = demb + l * 128;
        float s = dr[lane] * u[lane] + dr[lane + 32] * u[lane + 32]
                + dr[lane + 64] * u[lane + 64] + dr[lane + 96] * u[lane + 96];
        #pragma unroll
        for (int o = 16; o > 0; o >>= 1) s += __shfl_xor_sync(0xffffffffu, s, o);
        if (lane == 0) sc[l] = s;
    }
    __syncthreads();

    if (t == 0) {
        float mx = sc[0];
        #pragma unroll
        for (int l = 1; l < DLN; l++) mx = fmaxf(mx, sc[l]);
        float sum = 0.f;
        #pragma unroll
        for (int l = 0; l < DLN; l++) { float e = expf(sc[l] - mx); ex[l] = e; sum += e; }
        inv_s = 1.f / sum;
    }
    __syncthreads();

    if (t < 128) {
        float rv = 0.f;
        #pragma unroll
        for (int l = 0; l < DLN; l++) rv += ex[l] * demb[l * 128 + t];
        out[BB * 128 + b * 128 + t] = rv * inv_s;
    }

    for (int rr = 0; rr < 16; rr++) {
        int row = wid * 16 + rr;
        const float* wr = linW + row * 256;
        float s = 0.f;
        #pragma unroll
        for (int q = 0; q < 8; q++) s += wr[lane + 32 * q] * pool[lane + 32 * q];
        #pragma unroll
        for (int o = 16; o > 0; o >>= 1) s += __shfl_xor_sync(0xffffffffu, s, o);
        if (lane == 0) out[b * 128 + row] = s + linb[row];
    }
}

// ---------------------------------------------------------------------------
extern "C" void kernel_launch(void* const* d_in, const int* in_sizes, int n_in,
                              void* d_out, int out_size)
{
    const float* emb   = (const float*)d_in[0];
    const float* Wc    = (const float*)d_in[1];
    const float* bc    = (const float*)d_in[2];
    const float* Wb    = (const float*)d_in[3];
    const float* Wih_f = (const float*)d_in[4];
    const float* Whh_f = (const float*)d_in[5];
    const float* bih_f = (const float*)d_in[6];
    const float* bhh_f = (const float*)d_in[7];
    const float* Wih_b = (const float*)d_in[8];
    const float* Whh_b = (const float*)d_in[9];
    const float* bih_b = (const float*)d_in[10];
    const float* bhh_b = (const float*)d_in[11];
    const float* linW  = (const float*)d_in[12];
    const float* linb  = (const float*)d_in[13];
    const int* node_tokens = (const int*)d_in[14];
    const int* doc_tokens  = (const int*)d_in[15];
    float* out = (float*)d_out;

    cudaFuncSetAttribute(k1_stmt, cudaFuncAttributeMaxDynamicSharedMemorySize, K1_DYN);
    cudaFuncSetAttribute(k1b_gi,  cudaFuncAttributeMaxDynamicSharedMemorySize, K1B_DYN);

    k0_prep<<<7, 256>>>(Wc, Wih_f, Wih_b);
    k1_stmt<<<148, 512, K1_DYN>>>(emb, bc, node_tokens);
    k1b_gi<<<144, 512, K1B_DYN>>>(bih_f, bih_b);
    k2_gru<<<BB * 2, 768>>>(Whh_f, bhh_f, Whh_b, bhh_b);
    k3_out<<<BB, 256>>>(emb, Wb, linW, linb, doc_tokens, out);
}

// round 10
// speedup vs baseline: 2.4949x; 1.1160x over previous
#include <cuda_runtime.h>
#include <cuda_fp16.h>
#include <math.h>
#include <stdint.h>

#define TS 8192
#define BB 64
#define LL 128
#define DLN 20
#define TP 272      // fp16 tile pitch in BYTES (136 halves)
#define SP 132      // fp32 stage pitch in floats

typedef unsigned long long ull;

// ---------------- scratch (device globals; no allocation allowed) ----------
__device__ float g_gi[TS * 768];                     // 25 MB
__device__ float g_pooled[BB * 256];
__device__ __align__(16) __half g_Bhi[7 * 16384];    // Wc + 6 Wih row-blocks, [j][k] fp16 hi
__device__ __align__(16) __half g_Blo[7 * 16384];    // fp16 lo
__device__ __align__(16) __half g_Af[TS * 128];      // stmt_h, single fp16

// subtree sizes of the 32-node binary heap
__constant__ float c_cszf[32] = {32,16,15,8,7,7,7,4,3,3,3,3,3,3,3,2,
                                 1,1,1,1,1,1,1,1,1,1,1,1,1,1,1,1};

// ---------------- helpers ---------------------------------------------------
__device__ __forceinline__ uint32_t s2u(const void* p){
    uint32_t a;
    asm("{ .reg .u64 t; cvta.to.shared.u64 t, %1; cvt.u32.u64 %0, t; }" : "=r"(a) : "l"(p));
    return a;
}
__device__ __forceinline__ void ldsm4(uint32_t addr, uint32_t r[4]){
    asm volatile("ldmatrix.sync.aligned.m8n8.x4.shared.b16 {%0,%1,%2,%3}, [%4];"
        : "=r"(r[0]), "=r"(r[1]), "=r"(r[2]), "=r"(r[3]) : "r"(addr));
}
__device__ __forceinline__ void mma_f16(float d[4], const uint32_t a[4], uint32_t b0, uint32_t b1){
    asm volatile("mma.sync.aligned.m16n8k16.row.col.f32.f16.f16.f32 "
        "{%0,%1,%2,%3}, {%4,%5,%6,%7}, {%8,%9}, {%0,%1,%2,%3};"
        : "+f"(d[0]), "+f"(d[1]), "+f"(d[2]), "+f"(d[3])
        : "r"(a[0]), "r"(a[1]), "r"(a[2]), "r"(a[3]), "r"(b0), "r"(b1));
}
__device__ __forceinline__ float4 f4add(float4 a, float4 b){
    return make_float4(a.x + b.x, a.y + b.y, a.z + b.z, a.w + b.w);
}
__device__ __forceinline__ void hsplit(float x, __half& h, __half& l){
    h = __float2half_rn(x);
    l = __float2half_rn(x - __half2float(h));
}
__device__ __forceinline__ void cpa16(uint32_t dst, const void* src){
    asm volatile("cp.async.cg.shared.global [%0], [%1], 16;"
        :: "r"(dst), "l"(__cvta_generic_to_global(src)) : "memory");
}
#define CP_COMMIT() asm volatile("cp.async.commit_group;" ::: "memory")
#define CP_WAIT0()  asm volatile("cp.async.wait_group 0;" ::: "memory")
#define CP_WAIT1()  asm volatile("cp.async.wait_group 1;" ::: "memory")

// smem layouts (byte offsets from aligned base). One 128x136 fp16 tile = 34816 B.
// K1:  A | Bh | Bl | stage
#define K1_OFF_A   0
#define K1_OFF_BH  34816
#define K1_OFF_BL  69632
#define K1_OFF_STG 104448                // float[128][132] = 67584 B
#define K1_DYN  (1024 + 104448 + 67584)
// K1b: Bh | Bl | A0 | A1
#define K1B_OFF_BH 0
#define K1B_OFF_BL 34816
#define K1B_OFF_A0 69632
#define K1B_OFF_A1 104448
#define K1B_DYN (1024 + 139264)

// 128x64x128 fp16 2-term GEMM slice: warp (wr, wc) does rows 16*wr..+15,
// cols 64*wc..+63 (8 n-tiles). C = A*Bh + A*Bl.
__device__ __forceinline__ void gemm_tile8_2t(
    uint32_t sA, uint32_t sBH, uint32_t sBL,
    int wr, int wc, int lane, float acc[8][4])
{
    const uint32_t aOff = (uint32_t)(((lane & 15) + 16 * wr) * TP + ((lane >> 4) << 4));
    const uint32_t bOff = (uint32_t)((64 * wc + ((lane >> 4) << 3) + (lane & 7)) * TP
                                     + (((lane >> 3) & 1) << 4));
    #pragma unroll
    for (int ks = 0; ks < 8; ks++) {
        const uint32_t ko = ks * 32;          // 16 halves = 32 B
        uint32_t a[4];
        ldsm4(sA + aOff + ko, a);
        uint32_t bH = sBH + bOff + ko, bL = sBL + bOff + ko;
        #pragma unroll
        for (int p = 0; p < 4; p++) {
            uint32_t bh[4], bl[4];
            ldsm4(bH, bh);
            ldsm4(bL, bl);
            mma_f16(acc[2 * p],     a, bh[0], bh[1]);
            mma_f16(acc[2 * p],     a, bl[0], bl[1]);
            mma_f16(acc[2 * p + 1], a, bh[2], bh[3]);
            mma_f16(acc[2 * p + 1], a, bl[2], bl[3]);
            bH += 16 * TP; bL += 16 * TP;
        }
    }
}

// ---------------------------------------------------------------------------
// K0: fp16 hi/lo weight staging. tile 0 = Wc; tiles 1..6 = [Wih_f;Wih_b] blocks
// ---------------------------------------------------------------------------
__global__ __launch_bounds__(256) void k0_prep(
    const float* __restrict__ Wc, const float* __restrict__ Wih_f, const float* __restrict__ Wih_b)
{
    const int i = blockIdx.x;
    const float* src;
    if (i == 0) src = Wc;
    else { int cb = (i - 1) * 128; src = (cb < 384) ? (Wih_f + cb * 128) : (Wih_b + (cb - 384) * 128); }
    for (int p = threadIdx.x; p < 128 * 64; p += 256) {
        int j = p >> 6, kp = (p & 63) * 2;
        float x0 = src[j * 128 + kp], x1 = src[j * 128 + kp + 1];
        __half2 hh, ll;
        hsplit(x0, hh.x, ll.x);
        hsplit(x1, hh.y, ll.y);
        int e = i * 16384 + j * 128 + kp;
        *(__half2*)(g_Bhi + e) = hh;
        *(__half2*)(g_Blo + e) = ll;
    }
}

// issue cp.async gather of 128 embedding rows (512B each) into stage
__device__ __forceinline__ void gather_pref(
    uint32_t stg_u, const float* __restrict__ emb, const int* tk_s, int t)
{
    #pragma unroll
    for (int i = 0; i < 8; i++) {
        int idx = i * 512 + t;
        int row = idx >> 5, ch = idx & 31;
        cpa16(stg_u + (uint32_t)(row * (SP * 4) + ch * 16),
              emb + (size_t)tk_s[row] * 128 + ch * 4);
    }
    CP_COMMIT();
}

// ---------------------------------------------------------------------------
// K1: persistent (grid 148, 512 thr). Per tile (4 statements): prefetched
//     gather -> tree reduce -> fp16 round -> 2-term mma.sync GEMM vs Wc ->
//     shuffle epilogue (c(v)*bc bias, per-stmt max, relu) -> fp16 staging.
// ---------------------------------------------------------------------------
__global__ __launch_bounds__(512) void k1_stmt(
    const float* __restrict__ emb, const float* __restrict__ bc,
    const int* __restrict__ toks_g)
{
    extern __shared__ char smraw[];
    __shared__ int tkA[128], tkB[128];
    __shared__ float bcs[128];
    __shared__ float epi[1024];

    const int t = threadIdx.x, w = t >> 5, lane = t & 31;
    const int wr = w & 7, wc = w >> 3;
    const uint32_t rawu = s2u(smraw);
    const uint32_t alu = (rawu + 1023u) & ~1023u;
    char* base = smraw + (alu - rawu);
    float* stg = (float*)(base + K1_OFF_STG);
    float4* As4 = (float4*)stg;
    const uint32_t stg_u = alu + K1_OFF_STG;

    if (t < 128) { bcs[t] = bc[t]; tkA[t] = toks_g[blockIdx.x * 128 + t] + 1; }
    __syncthreads();
    gather_pref(stg_u, emb, tkA, t);
    if ((int)blockIdx.x + 148 < 2048 && t < 128)
        tkB[t] = toks_g[(blockIdx.x + 148) * 128 + t] + 1;

    // Wc hi/lo tiles once
    {
        const float4* sh = (const float4*)g_Bhi;
        const float4* sl = (const float4*)g_Blo;
        #pragma unroll
        for (int i = 0; i < 4; i++) {
            int idx = i * 512 + t, jj = idx >> 4, sg = idx & 15;
            *(float4*)(base + K1_OFF_BH + jj * TP + sg * 16) = sh[idx];
            *(float4*)(base + K1_OFF_BL + jj * TP + sg * 16) = sl[idx];
        }
    }

    int jpar = 0;
    for (int tile = blockIdx.x; tile < 2048; tile += 148, jpar ^= 1) {
        CP_WAIT0();
        __syncthreads();

        // ---- tree reduce, strict heap levels (rows: stmt*32 + node) ----
        if (t < 128) {   // L4: p=15 (single child 31)
            int tt = t >> 5, k4 = t & 31;
            As4[(tt * 32 + 15) * 33 + k4] = f4add(As4[(tt * 32 + 15) * 33 + k4], As4[(tt * 32 + 31) * 33 + k4]);
        }
        __syncthreads();
        #pragma unroll
        for (int i = 0; i < 2; i++) {   // L3: p=7..14 (1024 tasks)
            int idx = i * 512 + t;
            int k4 = idx & 31, q = idx >> 5, tt = q & 3, p = 7 + (q >> 2);
            int br = (tt * 32 + p) * 33;
            As4[br + k4] = f4add(As4[br + k4],
                          f4add(As4[(tt * 32 + 2 * p + 1) * 33 + k4], As4[(tt * 32 + 2 * p + 2) * 33 + k4]));
        }
        __syncthreads();
        {   // L2: p=3..6 (512 tasks)
            int k4 = t & 31, q = t >> 5, tt = q & 3, p = 3 + (q >> 2);
            int br = (tt * 32 + p) * 33;
            As4[br + k4] = f4add(As4[br + k4],
                          f4add(As4[(tt * 32 + 2 * p + 1) * 33 + k4], As4[(tt * 32 + 2 * p + 2) * 33 + k4]));
        }
        __syncthreads();
        if (t < 256) {   // L1: p=1..2 (256 tasks)
            int k4 = t & 31, q = t >> 5, tt = q & 3, p = 1 + (q >> 2);
            int br = (tt * 32 + p) * 33;
            As4[br + k4] = f4add(As4[br + k4],
                          f4add(As4[(tt * 32 + 2 * p + 1) * 33 + k4], As4[(tt * 32 + 2 * p + 2) * 33 + k4]));
        }
        __syncthreads();
        if (t < 128) {   // L0: p=0
            int tt = t >> 5, k4 = t & 31;
            int br = (tt * 32) * 33;
            As4[br + k4] = f4add(As4[br + k4], f4add(As4[(tt * 32 + 1) * 33 + k4], As4[(tt * 32 + 2) * 33 + k4]));
        }
        __syncthreads();

        // ---- fp32 -> fp16 A tile (single rounding) ----
        #pragma unroll
        for (int i = 0; i < 16; i++) {
            int idx = i * 512 + t;
            int row = idx >> 6, c2 = idx & 63;
            float2 v = *(const float2*)(stg + row * SP + c2 * 2);
            __half2 hh;
            hh.x = __float2half_rn(v.x);
            hh.y = __float2half_rn(v.y);
            *(__half2*)(base + K1_OFF_A + row * TP + c2 * 4) = hh;
        }
        __syncthreads();

        // ---- prefetch next tile's gather into (now free) stage ----
        int nxt = tile + 148;
        if (nxt < 2048) gather_pref(stg_u, emb, jpar ? tkA : tkB, t);
        if (nxt + 148 < 2048 && t < 128)
            (jpar ? tkB : tkA)[t] = toks_g[(nxt + 148) * 128 + t] + 1;

        // ---- GEMM (16 warps: wr x wc), 2-term fp16 ----
        float acc[8][4];
        #pragma unroll
        for (int n = 0; n < 8; n++)
            #pragma unroll
            for (int c = 0; c < 4; c++) acc[n][c] = 0.f;
        gemm_tile8_2t(alu + K1_OFF_A, alu + K1_OFF_BH, alu + K1_OFF_BL, wr, wc, lane, acc);

        // ---- shuffle epilogue: max over 32 nodes of acc + csz*bc, relu ----
        const int rr0 = (wr & 1) * 16 + (lane >> 2);
        const float cz0 = c_cszf[rr0], cz1 = c_cszf[rr0 + 8];
        #pragma unroll
        for (int nt = 0; nt < 8; nt++) {
            int c0 = 64 * wc + nt * 8 + 2 * (lane & 3);
            float b0 = bcs[c0], b1 = bcs[c0 + 1];
            float m0 = fmaxf(acc[nt][0] + cz0 * b0, acc[nt][2] + cz1 * b0);
            float m1 = fmaxf(acc[nt][1] + cz0 * b1, acc[nt][3] + cz1 * b1);
            #pragma unroll
            for (int o = 4; o <= 16; o <<= 1) {
                m0 = fmaxf(m0, __shfl_xor_sync(0xffffffffu, m0, o));
                m1 = fmaxf(m1, __shfl_xor_sync(0xffffffffu, m1, o));
            }
            if ((lane >> 2) == 0) { epi[wr * 128 + c0] = m0; epi[wr * 128 + c0 + 1] = m1; }
        }
        __syncthreads();
        {
            int st = t >> 7, col = t & 127;
            float m = fmaxf(fmaxf(epi[(2 * st) * 128 + col], epi[(2 * st + 1) * 128 + col]), 0.f);
            g_Af[(tile * 4 + st) * 128 + col] = __float2half_rn(m);
        }
        __syncthreads();
    }
}

// ---------------------------------------------------------------------------
// K1b: persistent gi GEMM (512 thr). 144 CTAs = (24 rb-groups x 6 gate-blocks).
//      B hi/lo loaded once; single-fp16 A double-buffered via cp.async.
//      Adds bih bias (pre-folded out of k2).
// ---------------------------------------------------------------------------
__device__ __forceinline__ void k1b_prefA(uint32_t dstA, int rb, int t){
    const float4* sa = (const float4*)(g_Af + rb * 16384);
    #pragma unroll
    for (int i = 0; i < 4; i++) {
        int idx = i * 512 + t, jj = idx >> 4, sg = idx & 15;
        cpa16(dstA + jj * TP + sg * 16, sa + idx);
    }
    CP_COMMIT();
}

__global__ __launch_bounds__(512) void k1b_gi(
    const float* __restrict__ bih_f, const float* __restrict__ bih_b)
{
    extern __shared__ char smraw[];
    __shared__ float bias_s[128];
    const int t = threadIdx.x, w = t >> 5, lane = t & 31;
    const int wr = w & 7, wc = w >> 3;
    const int by = blockIdx.x % 6, rb0 = blockIdx.x / 6;
    const uint32_t rawu = s2u(smraw);
    const uint32_t alu = (rawu + 1023u) & ~1023u;
    char* base = smraw + (alu - rawu);

    if (t < 128) bias_s[t] = (by < 3) ? bih_f[by * 128 + t] : bih_b[(by - 3) * 128 + t];

    k1b_prefA(alu + K1B_OFF_A0, rb0, t);

    {   // B gate-block once
        const float4* sbh = (const float4*)(g_Bhi + (1 + by) * 16384);
        const float4* sbl = (const float4*)(g_Blo + (1 + by) * 16384);
        #pragma unroll
        for (int i = 0; i < 4; i++) {
            int idx = i * 512 + t, jj = idx >> 4, sg = idx & 15;
            *(float4*)(base + K1B_OFF_BH + jj * TP + sg * 16) = sbh[idx];
            *(float4*)(base + K1B_OFF_BL + jj * TP + sg * 16) = sbl[idx];
        }
    }

    int pb = 0;
    for (int rb = rb0; rb < 64; rb += 24, pb ^= 1) {
        CP_WAIT0();
        __syncthreads();
        if (rb + 24 < 64)
            k1b_prefA(alu + (pb ? K1B_OFF_A0 : K1B_OFF_A1), rb + 24, t);

        float acc[8][4];
        #pragma unroll
        for (int n = 0; n < 8; n++)
            #pragma unroll
            for (int c = 0; c < 4; c++) acc[n][c] = 0.f;
        gemm_tile8_2t(alu + (pb ? K1B_OFF_A1 : K1B_OFF_A0),
                      alu + K1B_OFF_BH, alu + K1B_OFF_BL, wr, wc, lane, acc);

        const int row = rb * 128 + 16 * wr + (lane >> 2);
        float* o0 = g_gi + (size_t)row * 768 + by * 128 + 64 * wc;
        float* o1 = o0 + 8 * 768;
        const int cb = (lane & 3) * 2;
        #pragma unroll
        for (int nt = 0; nt < 8; nt++) {
            float b0 = bias_s[64 * wc + nt * 8 + cb];
            float b1 = bias_s[64 * wc + nt * 8 + cb + 1];
            *(float2*)(o0 + nt * 8 + cb) = make_float2(acc[nt][0] + b0, acc[nt][1] + b1);
            *(float2*)(o1 + nt * 8 + cb) = make_float2(acc[nt][2] + b0, acc[nt][3] + b1);
        }
    }
}

// ---------------------------------------------------------------------------
__device__ __forceinline__ void ffma2(ull& d, ull a, ull b){
    asm("fma.rn.f32x2 %0, %1, %2, %0;" : "+l"(d) : "l"(a), "l"(b));
}
__device__ __forceinline__ float2 ull2f2(ull v){
    float2 f; asm("mov.b64 {%0, %1}, %2;" : "=f"(f.x), "=f"(f.y) : "l"(v)); return f;
}

// ---------------------------------------------------------------------------
// K2: GRU recurrence. 128 CTAs, one per (batch, dir). 384 threads: thread
//     (g, tt) owns rows 2tt, 2tt+1 for h-half g -> h LDS amortized over 2
//     rows (halves smem-issue), 128 weight regs/thread (fits, no spill).
// ---------------------------------------------------------------------------
__global__ __launch_bounds__(384) void k2_gru(
    const float* __restrict__ Whh_f, const float* __restrict__ bhh_f,
    const float* __restrict__ Whh_b, const float* __restrict__ bhh_b)
{
    __shared__ float h_s[128];
    __shared__ float part[768];              // [half][row]
    __shared__ __align__(16) float gi_buf[2][384];
    __shared__ float bhh_s[384];

    const int t = threadIdx.x;
    const int b = blockIdx.x >> 1, dir = blockIdx.x & 1;
    const float* Whh = dir ? Whh_b : Whh_f;
    const float* bhh = dir ? bhh_b : bhh_f;

    const int g  = (t < 192) ? 0 : 1;
    const int tt = (t < 192) ? t : t - 192;
    const int j0 = 2 * tt;                   // rows j0, j0+1

    ull w0[32], w1[32];                      // 2 rows x 64 cols fp32
    {
        const ulonglong2* p0 = (const ulonglong2*)(Whh + (size_t)j0 * 128 + g * 64);
        const ulonglong2* p1 = (const ulonglong2*)(Whh + (size_t)(j0 + 1) * 128 + g * 64);
        #pragma unroll
        for (int i = 0; i < 16; i++) {
            ulonglong2 v0 = p0[i]; w0[2*i] = v0.x; w0[2*i+1] = v0.y;
            ulonglong2 v1 = p1[i]; w1[2*i] = v1.x; w1[2*i+1] = v1.y;
        }
    }
    bhh_s[t] = bhh[t];
    if (t < 128) h_s[t] = 0.f;

    const float* gsrc = g_gi + (size_t)(b * LL + (dir ? LL - 1 : 0)) * 768 + dir * 384;
    const int stp = dir ? -768 : 768;

    if (t < 96) cpa16(s2u(&gi_buf[0][0]) + t * 16, gsrc + t * 4);
    CP_COMMIT();
    __syncthreads();

    float hmax = -3e38f;
    for (int l = 0; l < LL; l++) {
        if (l + 1 < LL && t < 96)
            cpa16(s2u(&gi_buf[(l + 1) & 1][0]) + t * 16, gsrc + (l + 1) * stp + t * 4);
        CP_COMMIT();

        // matvec: 2 rows share each h load; 4 independent chains
        ull a00 = 0, a01 = 0, a10 = 0, a11 = 0;
        const ulonglong2* hp = (const ulonglong2*)(h_s + g * 64);
        #pragma unroll
        for (int i = 0; i < 16; i++) {
            ulonglong2 hv = hp[i];
            ffma2(a00, w0[2*i],     hv.x);
            ffma2(a01, w0[2*i + 1], hv.y);
            ffma2(a10, w1[2*i],     hv.x);
            ffma2(a11, w1[2*i + 1], hv.y);
        }
        float2 f00 = ull2f2(a00), f01 = ull2f2(a01);
        float2 f10 = ull2f2(a10), f11 = ull2f2(a11);
        *(float2*)(part + g * 384 + j0) = make_float2(
            (f00.x + f00.y) + (f01.x + f01.y),
            (f10.x + f10.y) + (f11.x + f11.y));
        CP_WAIT1();
        __syncthreads();

        if (t < 128) {
            const float* gb = gi_buf[l & 1];
            float ghr = part[t]       + part[384 + t] + bhh_s[t];
            float ghz = part[128 + t] + part[512 + t] + bhh_s[128 + t];
            float ghn = part[256 + t] + part[640 + t] + bhh_s[256 + t];
            float r = __fdividef(1.f, 1.f + __expf(-(gb[t] + ghr)));
            float z = __fdividef(1.f, 1.f + __expf(-(gb[128 + t] + ghz)));
            float y = gb[256 + t] + r * ghn;
            float n = 1.f - __fdividef(2.f, __expf(2.f * y) + 1.f);
            float hnew = (1.f - z) * n + z * h_s[t];
            h_s[t] = hnew;
            hmax = fmaxf(hmax, hnew);
        }
        __syncthreads();
    }
    if (t < 128) g_pooled[b * 256 + dir * 128 + t] = hmax;
}

// ---------------------------------------------------------------------------
// K3: lvec = pooled @ linW^T + linb ; rvec = doc attention.
// ---------------------------------------------------------------------------
__global__ __launch_bounds__(256) void k3_out(
    const float* __restrict__ emb, const float* __restrict__ Wb,
    const float* __restrict__ linW, const float* __restrict__ linb,
    const int* __restrict__ doc, float* __restrict__ out)
{
    __shared__ float demb[DLN * 128];
    __shared__ float h0[128];
    __shared__ float u[128];
    __shared__ float sc[DLN];
    __shared__ float ex[DLN];
    __shared__ float inv_s;
    __shared__ float pool[256];
    __shared__ int dti[DLN];

    const int t = threadIdx.x, b = blockIdx.x;
    const int wid = t >> 5, lane = t & 31;

    pool[t] = g_pooled[b * 256 + t];
    if (t < DLN) dti[t] = doc[b * DLN + t] + 1;
    __syncthreads();

    #pragma unroll
    for (int i = 0; i < 10; i++) {
        int idx = i * 256 + t;
        demb[idx] = emb[(size_t)dti[idx >> 7] * 128 + (idx & 127)];
    }
    __syncthreads();

    if (t < 128) {
        float s = 0.f;
        #pragma unroll
        for (int l = 0; l < DLN; l++) s += demb[l * 128 + t];
        h0[t] = s * (1.f / (float)DLN);
    }
    __syncthreads();

    for (int rr = 0; rr < 16; rr++) {
        int row = wid * 16 + rr;
        const float* wr = Wb + row * 128;
        float s = wr[lane] * h0[lane] + wr[lane + 32] * h0[lane + 32]
                + wr[lane + 64] * h0[lane + 64] + wr[lane + 96] * h0[lane + 96];
        #pragma unroll
        for (int o = 16; o > 0; o >>= 1) s += __shfl_xor_sync(0xffffffffu, s, o);
        if (lane == 0) u[row] = s;
    }
    __syncthreads();

    for (int l = wid; l < DLN; l += 8) {
        const float* dr = demb + l * 128;
        float s = dr[lane] * u[lane] + dr[lane + 32] * u[lane + 32]
                + dr[lane + 64] * u[lane + 64] + dr[lane + 96] * u[lane + 96];
        #pragma unroll
        for (int o = 16; o > 0; o >>= 1) s += __shfl_xor_sync(0xffffffffu, s, o);
        if (lane == 0) sc[l] = s;
    }
    __syncthreads();

    if (t == 0) {
        float mx = sc[0];
        #pragma unroll
        for (int l = 1; l < DLN; l++) mx = fmaxf(mx, sc[l]);
        float sum = 0.f;
        #pragma unroll
        for (int l = 0; l < DLN; l++) { float e = expf(sc[l] - mx); ex[l] = e; sum += e; }
        inv_s = 1.f / sum;
    }
    __syncthreads();

    if (t < 128) {
        float rv = 0.f;
        #pragma unroll
        for (int l = 0; l < DLN; l++) rv += ex[l] * demb[l * 128 + t];
        out[BB * 128 + b * 128 + t] = rv * inv_s;
    }

    for (int rr = 0; rr < 16; rr++) {
        int row = wid * 16 + rr;
        const float* wr = linW + row * 256;
        float s = 0.f;
        #pragma unroll
        for (int q = 0; q < 8; q++) s += wr[lane + 32 * q] * pool[lane + 32 * q];
        #pragma unroll
        for (int o = 16; o > 0; o >>= 1) s += __shfl_xor_sync(0xffffffffu, s, o);
        if (lane == 0) out[b * 128 + row] = s + linb[row];
    }
}

// ---------------------------------------------------------------------------
extern "C" void kernel_launch(void* const* d_in, const int* in_sizes, int n_in,
                              void* d_out, int out_size)
{
    const float* emb   = (const float*)d_in[0];
    const float* Wc    = (const float*)d_in[1];
    const float* bc    = (const float*)d_in[2];
    const float* Wb    = (const float*)d_in[3];
    const float* Wih_f = (const float*)d_in[4];
    const float* Whh_f = (const float*)d_in[5];
    const float* bih_f = (const float*)d_in[6];
    const float* bhh_f = (const float*)d_in[7];
    const float* Wih_b = (const float*)d_in[8];
    const float* Whh_b = (const float*)d_in[9];
    const float* bih_b = (const float*)d_in[10];
    const float* bhh_b = (const float*)d_in[11];
    const float* linW  = (const float*)d_in[12];
    const float* linb  = (const float*)d_in[13];
    const int* node_tokens = (const int*)d_in[14];
    const int* doc_tokens  = (const int*)d_in[15];
    float* out = (float*)d_out;

    cudaFuncSetAttribute(k1_stmt, cudaFuncAttributeMaxDynamicSharedMemorySize, K1_DYN);
    cudaFuncSetAttribute(k1b_gi,  cudaFuncAttributeMaxDynamicSharedMemorySize, K1B_DYN);

    k0_prep<<<7, 256>>>(Wc, Wih_f, Wih_b);
    k1_stmt<<<148, 512, K1_DYN>>>(emb, bc, node_tokens);
    k1b_gi<<<144, 512, K1B_DYN>>>(bih_f, bih_b);
    k2_gru<<<BB * 2, 384>>>(Whh_f, bhh_f, Whh_b, bhh_b);
    k3_out<<<BB, 256>>>(emb, Wb, linW, linb, doc_tokens, out);
}

// round 11
// speedup vs baseline: 2.8524x; 1.1433x over previous
#include <cuda_runtime.h>
#include <cuda_fp16.h>
#include <math.h>
#include <stdint.h>

#define TS 8192
#define BB 64
#define LL 128
#define DLN 20
#define TP 272      // fp16 tile pitch in BYTES (136 halves)
#define SP 132      // fp32 stage pitch in floats

typedef unsigned long long ull;

// ---------------- scratch (device globals; no allocation allowed) ----------
__device__ float g_gi[TS * 768];                     // 25 MB
__device__ float g_pooled[BB * 256];
__device__ __align__(16) __half g_Bh[7 * 16384];     // Wc + 6 Wih row-blocks, [j][k] fp16
__device__ __align__(16) __half g_Af[TS * 128];      // stmt_h, fp16

// subtree sizes of the 32-node binary heap
__constant__ float c_cszf[32] = {32,16,15,8,7,7,7,4,3,3,3,3,3,3,3,2,
                                 1,1,1,1,1,1,1,1,1,1,1,1,1,1,1,1};

// ---------------- helpers ---------------------------------------------------
__device__ __forceinline__ uint32_t s2u(const void* p){
    uint32_t a;
    asm("{ .reg .u64 t; cvta.to.shared.u64 t, %1; cvt.u32.u64 %0, t; }" : "=r"(a) : "l"(p));
    return a;
}
__device__ __forceinline__ void ldsm4(uint32_t addr, uint32_t r[4]){
    asm volatile("ldmatrix.sync.aligned.m8n8.x4.shared.b16 {%0,%1,%2,%3}, [%4];"
        : "=r"(r[0]), "=r"(r[1]), "=r"(r[2]), "=r"(r[3]) : "r"(addr));
}
__device__ __forceinline__ void mma_f16(float d[4], const uint32_t a[4], uint32_t b0, uint32_t b1){
    asm volatile("mma.sync.aligned.m16n8k16.row.col.f32.f16.f16.f32 "
        "{%0,%1,%2,%3}, {%4,%5,%6,%7}, {%8,%9}, {%0,%1,%2,%3};"
        : "+f"(d[0]), "+f"(d[1]), "+f"(d[2]), "+f"(d[3])
        : "r"(a[0]), "r"(a[1]), "r"(a[2]), "r"(a[3]), "r"(b0), "r"(b1));
}
__device__ __forceinline__ float4 f4add(float4 a, float4 b){
    return make_float4(a.x + b.x, a.y + b.y, a.z + b.z, a.w + b.w);
}
__device__ __forceinline__ void cpa16(uint32_t dst, const void* src){
    asm volatile("cp.async.cg.shared.global [%0], [%1], 16;"
        :: "r"(dst), "l"(__cvta_generic_to_global(src)) : "memory");
}
#define CP_COMMIT() asm volatile("cp.async.commit_group;" ::: "memory")
#define CP_WAIT0()  asm volatile("cp.async.wait_group 0;" ::: "memory")
#define CP_WAIT1()  asm volatile("cp.async.wait_group 1;" ::: "memory")

// smem layouts (byte offsets from aligned base). One 128x136 fp16 tile = 34816 B.
// K1:  A | B | stage
#define K1_OFF_A   0
#define K1_OFF_B   34816
#define K1_OFF_STG 69632                 // float[128][132] = 67584 B
#define K1_DYN  (1024 + 69632 + 67584)
// K1b: B | A0 | A1
#define K1B_OFF_B  0
#define K1B_OFF_A0 34816
#define K1B_OFF_A1 69632
#define K1B_DYN (1024 + 104448)

// 128x64x128 fp16 1-term GEMM slice: warp (wr, wc) does rows 16*wr..+15,
// cols 64*wc..+63 (8 n-tiles).
__device__ __forceinline__ void gemm_tile8_1t(
    uint32_t sA, uint32_t sB,
    int wr, int wc, int lane, float acc[8][4])
{
    const uint32_t aOff = (uint32_t)(((lane & 15) + 16 * wr) * TP + ((lane >> 4) << 4));
    const uint32_t bOff = (uint32_t)((64 * wc + ((lane >> 4) << 3) + (lane & 7)) * TP
                                     + (((lane >> 3) & 1) << 4));
    #pragma unroll
    for (int ks = 0; ks < 8; ks++) {
        const uint32_t ko = ks * 32;          // 16 halves = 32 B
        uint32_t a[4];
        ldsm4(sA + aOff + ko, a);
        uint32_t bP = sB + bOff + ko;
        #pragma unroll
        for (int p = 0; p < 4; p++) {
            uint32_t bh[4];
            ldsm4(bP, bh);
            mma_f16(acc[2 * p],     a, bh[0], bh[1]);
            mma_f16(acc[2 * p + 1], a, bh[2], bh[3]);
            bP += 16 * TP;
        }
    }
}

// ---------------------------------------------------------------------------
// K0: fp16 weight staging. tile 0 = Wc; tiles 1..6 = [Wih_f;Wih_b] blocks
// ---------------------------------------------------------------------------
__global__ __launch_bounds__(256) void k0_prep(
    const float* __restrict__ Wc, const float* __restrict__ Wih_f, const float* __restrict__ Wih_b)
{
    const int i = blockIdx.x;
    const float* src;
    if (i == 0) src = Wc;
    else { int cb = (i - 1) * 128; src = (cb < 384) ? (Wih_f + cb * 128) : (Wih_b + (cb - 384) * 128); }
    for (int p = threadIdx.x; p < 128 * 64; p += 256) {
        int j = p >> 6, kp = (p & 63) * 2;
        __half2 hh;
        hh.x = __float2half_rn(src[j * 128 + kp]);
        hh.y = __float2half_rn(src[j * 128 + kp + 1]);
        *(__half2*)(g_Bh + i * 16384 + j * 128 + kp) = hh;
    }
}

// issue cp.async gather of 128 embedding rows (512B each) into stage
__device__ __forceinline__ void gather_pref(
    uint32_t stg_u, const float* __restrict__ emb, const int* tk_s, int t)
{
    #pragma unroll
    for (int i = 0; i < 8; i++) {
        int idx = i * 512 + t;
        int row = idx >> 5, ch = idx & 31;
        cpa16(stg_u + (uint32_t)(row * (SP * 4) + ch * 16),
              emb + (size_t)tk_s[row] * 128 + ch * 4);
    }
    CP_COMMIT();
}

// ---------------------------------------------------------------------------
// K1: persistent (grid 148, 512 thr). Per tile (4 statements): prefetched
//     gather -> tree reduce -> fp16 round -> 1-term mma.sync GEMM vs Wc ->
//     shuffle epilogue (c(v)*bc bias, per-stmt max, relu) -> fp16 staging.
// ---------------------------------------------------------------------------
__global__ __launch_bounds__(512) void k1_stmt(
    const float* __restrict__ emb, const float* __restrict__ bc,
    const int* __restrict__ toks_g)
{
    extern __shared__ char smraw[];
    __shared__ int tkA[128], tkB[128];
    __shared__ float bcs[128];
    __shared__ float epi[1024];

    const int t = threadIdx.x, w = t >> 5, lane = t & 31;
    const int wr = w & 7, wc = w >> 3;
    const uint32_t rawu = s2u(smraw);
    const uint32_t alu = (rawu + 1023u) & ~1023u;
    char* base = smraw + (alu - rawu);
    float* stg = (float*)(base + K1_OFF_STG);
    float4* As4 = (float4*)stg;
    const uint32_t stg_u = alu + K1_OFF_STG;

    if (t < 128) { bcs[t] = bc[t]; tkA[t] = toks_g[blockIdx.x * 128 + t] + 1; }
    __syncthreads();
    gather_pref(stg_u, emb, tkA, t);
    if ((int)blockIdx.x + 148 < 2048 && t < 128)
        tkB[t] = toks_g[(blockIdx.x + 148) * 128 + t] + 1;

    // Wc fp16 tile once
    {
        const float4* sh = (const float4*)g_Bh;
        #pragma unroll
        for (int i = 0; i < 4; i++) {
            int idx = i * 512 + t, jj = idx >> 4, sg = idx & 15;
            *(float4*)(base + K1_OFF_B + jj * TP + sg * 16) = sh[idx];
        }
    }

    int jpar = 0;
    for (int tile = blockIdx.x; tile < 2048; tile += 148, jpar ^= 1) {
        CP_WAIT0();
        __syncthreads();

        // ---- tree reduce, strict heap levels (rows: stmt*32 + node) ----
        if (t < 128) {   // L4: p=15 (single child 31)
            int tt = t >> 5, k4 = t & 31;
            As4[(tt * 32 + 15) * 33 + k4] = f4add(As4[(tt * 32 + 15) * 33 + k4], As4[(tt * 32 + 31) * 33 + k4]);
        }
        __syncthreads();
        #pragma unroll
        for (int i = 0; i < 2; i++) {   // L3: p=7..14 (1024 tasks)
            int idx = i * 512 + t;
            int k4 = idx & 31, q = idx >> 5, tt = q & 3, p = 7 + (q >> 2);
            int br = (tt * 32 + p) * 33;
            As4[br + k4] = f4add(As4[br + k4],
                          f4add(As4[(tt * 32 + 2 * p + 1) * 33 + k4], As4[(tt * 32 + 2 * p + 2) * 33 + k4]));
        }
        __syncthreads();
        {   // L2: p=3..6 (512 tasks)
            int k4 = t & 31, q = t >> 5, tt = q & 3, p = 3 + (q >> 2);
            int br = (tt * 32 + p) * 33;
            As4[br + k4] = f4add(As4[br + k4],
                          f4add(As4[(tt * 32 + 2 * p + 1) * 33 + k4], As4[(tt * 32 + 2 * p + 2) * 33 + k4]));
        }
        __syncthreads();
        if (t < 256) {   // L1: p=1..2 (256 tasks)
            int k4 = t & 31, q = t >> 5, tt = q & 3, p = 1 + (q >> 2);
            int br = (tt * 32 + p) * 33;
            As4[br + k4] = f4add(As4[br + k4],
                          f4add(As4[(tt * 32 + 2 * p + 1) * 33 + k4], As4[(tt * 32 + 2 * p + 2) * 33 + k4]));
        }
        __syncthreads();
        if (t < 128) {   // L0: p=0
            int tt = t >> 5, k4 = t & 31;
            int br = (tt * 32) * 33;
            As4[br + k4] = f4add(As4[br + k4], f4add(As4[(tt * 32 + 1) * 33 + k4], As4[(tt * 32 + 2) * 33 + k4]));
        }
        __syncthreads();

        // ---- fp32 -> fp16 A tile (single rounding) ----
        #pragma unroll
        for (int i = 0; i < 16; i++) {
            int idx = i * 512 + t;
            int row = idx >> 6, c2 = idx & 63;
            float2 v = *(const float2*)(stg + row * SP + c2 * 2);
            __half2 hh;
            hh.x = __float2half_rn(v.x);
            hh.y = __float2half_rn(v.y);
            *(__half2*)(base + K1_OFF_A + row * TP + c2 * 4) = hh;
        }
        __syncthreads();

        // ---- prefetch next tile's gather into (now free) stage ----
        int nxt = tile + 148;
        if (nxt < 2048) gather_pref(stg_u, emb, jpar ? tkA : tkB, t);
        if (nxt + 148 < 2048 && t < 128)
            (jpar ? tkB : tkA)[t] = toks_g[(nxt + 148) * 128 + t] + 1;

        // ---- GEMM (16 warps: wr x wc), 1-term fp16 ----
        float acc[8][4];
        #pragma unroll
        for (int n = 0; n < 8; n++)
            #pragma unroll
            for (int c = 0; c < 4; c++) acc[n][c] = 0.f;
        gemm_tile8_1t(alu + K1_OFF_A, alu + K1_OFF_B, wr, wc, lane, acc);

        // ---- shuffle epilogue: max over 32 nodes of acc + csz*bc, relu ----
        const int rr0 = (wr & 1) * 16 + (lane >> 2);
        const float cz0 = c_cszf[rr0], cz1 = c_cszf[rr0 + 8];
        #pragma unroll
        for (int nt = 0; nt < 8; nt++) {
            int c0 = 64 * wc + nt * 8 + 2 * (lane & 3);
            float b0 = bcs[c0], b1 = bcs[c0 + 1];
            float m0 = fmaxf(acc[nt][0] + cz0 * b0, acc[nt][2] + cz1 * b0);
            float m1 = fmaxf(acc[nt][1] + cz0 * b1, acc[nt][3] + cz1 * b1);
            #pragma unroll
            for (int o = 4; o <= 16; o <<= 1) {
                m0 = fmaxf(m0, __shfl_xor_sync(0xffffffffu, m0, o));
                m1 = fmaxf(m1, __shfl_xor_sync(0xffffffffu, m1, o));
            }
            if ((lane >> 2) == 0) { epi[wr * 128 + c0] = m0; epi[wr * 128 + c0 + 1] = m1; }
        }
        __syncthreads();
        {
            int st = t >> 7, col = t & 127;
            float m = fmaxf(fmaxf(epi[(2 * st) * 128 + col], epi[(2 * st + 1) * 128 + col]), 0.f);
            g_Af[(tile * 4 + st) * 128 + col] = __float2half_rn(m);
        }
        __syncthreads();
    }
}

// ---------------------------------------------------------------------------
// K1b: persistent gi GEMM (512 thr). 144 CTAs = (24 rb-groups x 6 gate-blocks).
//      B loaded once; fp16 A double-buffered via cp.async. Adds bih bias.
// ---------------------------------------------------------------------------
__device__ __forceinline__ void k1b_prefA(uint32_t dstA, int rb, int t){
    const float4* sa = (const float4*)(g_Af + rb * 16384);
    #pragma unroll
    for (int i = 0; i < 4; i++) {
        int idx = i * 512 + t, jj = idx >> 4, sg = idx & 15;
        cpa16(dstA + jj * TP + sg * 16, sa + idx);
    }
    CP_COMMIT();
}

__global__ __launch_bounds__(512) void k1b_gi(
    const float* __restrict__ bih_f, const float* __restrict__ bih_b)
{
    extern __shared__ char smraw[];
    __shared__ float bias_s[128];
    const int t = threadIdx.x, w = t >> 5, lane = t & 31;
    const int wr = w & 7, wc = w >> 3;
    const int by = blockIdx.x % 6, rb0 = blockIdx.x / 6;
    const uint32_t rawu = s2u(smraw);
    const uint32_t alu = (rawu + 1023u) & ~1023u;
    char* base = smraw + (alu - rawu);

    if (t < 128) bias_s[t] = (by < 3) ? bih_f[by * 128 + t] : bih_b[(by - 3) * 128 + t];

    k1b_prefA(alu + K1B_OFF_A0, rb0, t);

    {   // B gate-block once
        const float4* sbh = (const float4*)(g_Bh + (1 + by) * 16384);
        #pragma unroll
        for (int i = 0; i < 4; i++) {
            int idx = i * 512 + t, jj = idx >> 4, sg = idx & 15;
            *(float4*)(base + K1B_OFF_B + jj * TP + sg * 16) = sbh[idx];
        }
    }

    int pb = 0;
    for (int rb = rb0; rb < 64; rb += 24, pb ^= 1) {
        CP_WAIT0();
        __syncthreads();
        if (rb + 24 < 64)
            k1b_prefA(alu + (pb ? K1B_OFF_A0 : K1B_OFF_A1), rb + 24, t);

        float acc[8][4];
        #pragma unroll
        for (int n = 0; n < 8; n++)
            #pragma unroll
            for (int c = 0; c < 4; c++) acc[n][c] = 0.f;
        gemm_tile8_1t(alu + (pb ? K1B_OFF_A1 : K1B_OFF_A0),
                      alu + K1B_OFF_B, wr, wc, lane, acc);

        const int row = rb * 128 + 16 * wr + (lane >> 2);
        float* o0 = g_gi + (size_t)row * 768 + by * 128 + 64 * wc;
        float* o1 = o0 + 8 * 768;
        const int cb = (lane & 3) * 2;
        #pragma unroll
        for (int nt = 0; nt < 8; nt++) {
            float b0 = bias_s[64 * wc + nt * 8 + cb];
            float b1 = bias_s[64 * wc + nt * 8 + cb + 1];
            *(float2*)(o0 + nt * 8 + cb) = make_float2(acc[nt][0] + b0, acc[nt][1] + b1);
            *(float2*)(o1 + nt * 8 + cb) = make_float2(acc[nt][2] + b0, acc[nt][3] + b1);
        }
    }
}

// ---------------------------------------------------------------------------
__device__ __forceinline__ void ffma2(ull& d, ull a, ull b){
    asm("fma.rn.f32x2 %0, %1, %2, %0;" : "+l"(d) : "l"(a), "l"(b));
}
__device__ __forceinline__ float2 ull2f2(ull v){
    float2 f; asm("mov.b64 {%0, %1}, %2;" : "=f"(f.x), "=f"(f.y) : "l"(v)); return f;
}

// ---------------------------------------------------------------------------
// K2: GRU recurrence. 128 CTAs, one per (batch, dir). 384 threads: thread
//     (g, tt) owns rows 2tt, 2tt+1 for h-half g -> h LDS amortized over 2
//     rows, 128 weight regs/thread (fits, no spill).
// ---------------------------------------------------------------------------
__global__ __launch_bounds__(384) void k2_gru(
    const float* __restrict__ Whh_f, const float* __restrict__ bhh_f,
    const float* __restrict__ Whh_b, const float* __restrict__ bhh_b)
{
    __shared__ float h_s[128];
    __shared__ float part[768];              // [half][row]
    __shared__ __align__(16) float gi_buf[2][384];
    __shared__ float bhh_s[384];

    const int t = threadIdx.x;
    const int b = blockIdx.x >> 1, dir = blockIdx.x & 1;
    const float* Whh = dir ? Whh_b : Whh_f;
    const float* bhh = dir ? bhh_b : bhh_f;

    const int g  = (t < 192) ? 0 : 1;
    const int tt = (t < 192) ? t : t - 192;
    const int j0 = 2 * tt;                   // rows j0, j0+1

    ull w0[32], w1[32];                      // 2 rows x 64 cols fp32
    {
        const ulonglong2* p0 = (const ulonglong2*)(Whh + (size_t)j0 * 128 + g * 64);
        const ulonglong2* p1 = (const ulonglong2*)(Whh + (size_t)(j0 + 1) * 128 + g * 64);
        #pragma unroll
        for (int i = 0; i < 16; i++) {
            ulonglong2 v0 = p0[i]; w0[2*i] = v0.x; w0[2*i+1] = v0.y;
            ulonglong2 v1 = p1[i]; w1[2*i] = v1.x; w1[2*i+1] = v1.y;
        }
    }
    bhh_s[t] = bhh[t];
    if (t < 128) h_s[t] = 0.f;

    const float* gsrc = g_gi + (size_t)(b * LL + (dir ? LL - 1 : 0)) * 768 + dir * 384;
    const int stp = dir ? -768 : 768;

    if (t < 96) cpa16(s2u(&gi_buf[0][0]) + t * 16, gsrc + t * 4);
    CP_COMMIT();
    __syncthreads();

    float hmax = -3e38f;
    for (int l = 0; l < LL; l++) {
        if (l + 1 < LL && t < 96)
            cpa16(s2u(&gi_buf[(l + 1) & 1][0]) + t * 16, gsrc + (l + 1) * stp + t * 4);
        CP_COMMIT();

        // matvec: 2 rows share each h load; 4 independent chains
        ull a00 = 0, a01 = 0, a10 = 0, a11 = 0;
        const ulonglong2* hp = (const ulonglong2*)(h_s + g * 64);
        #pragma unroll
        for (int i = 0; i < 16; i++) {
            ulonglong2 hv = hp[i];
            ffma2(a00, w0[2*i],     hv.x);
            ffma2(a01, w0[2*i + 1], hv.y);
            ffma2(a10, w1[2*i],     hv.x);
            ffma2(a11, w1[2*i + 1], hv.y);
        }
        float2 f00 = ull2f2(a00), f01 = ull2f2(a01);
        float2 f10 = ull2f2(a10), f11 = ull2f2(a11);
        *(float2*)(part + g * 384 + j0) = make_float2(
            (f00.x + f00.y) + (f01.x + f01.y),
            (f10.x + f10.y) + (f11.x + f11.y));
        CP_WAIT1();
        __syncthreads();

        if (t < 128) {
            const float* gb = gi_buf[l & 1];
            float ghr = part[t]       + part[384 + t] + bhh_s[t];
            float ghz = part[128 + t] + part[512 + t] + bhh_s[128 + t];
            float ghn = part[256 + t] + part[640 + t] + bhh_s[256 + t];
            float r = __fdividef(1.f, 1.f + __expf(-(gb[t] + ghr)));
            float z = __fdividef(1.f, 1.f + __expf(-(gb[128 + t] + ghz)));
            float y = gb[256 + t] + r * ghn;
            float n = 1.f - __fdividef(2.f, __expf(2.f * y) + 1.f);
            float hnew = (1.f - z) * n + z * h_s[t];
            h_s[t] = hnew;
            hmax = fmaxf(hmax, hnew);
        }
        __syncthreads();
    }
    if (t < 128) g_pooled[b * 256 + dir * 128 + t] = hmax;
}

// ---------------------------------------------------------------------------
// K3: lvec = pooled @ linW^T + linb ; rvec = doc attention.
// ---------------------------------------------------------------------------
__global__ __launch_bounds__(256) void k3_out(
    const float* __restrict__ emb, const float* __restrict__ Wb,
    const float* __restrict__ linW, const float* __restrict__ linb,
    const int* __restrict__ doc, float* __restrict__ out)
{
    __shared__ float demb[DLN * 128];
    __shared__ float h0[128];
    __shared__ float u[128];
    __shared__ float sc[DLN];
    __shared__ float ex[DLN];
    __shared__ float inv_s;
    __shared__ float pool[256];
    __shared__ int dti[DLN];

    const int t = threadIdx.x, b = blockIdx.x;
    const int wid = t >> 5, lane = t & 31;

    pool[t] = g_pooled[b * 256 + t];
    if (t < DLN) dti[t] = doc[b * DLN + t] + 1;
    __syncthreads();

    #pragma unroll
    for (int i = 0; i < 10; i++) {
        int idx = i * 256 + t;
        demb[idx] = emb[(size_t)dti[idx >> 7] * 128 + (idx & 127)];
    }
    __syncthreads();

    if (t < 128) {
        float s = 0.f;
        #pragma unroll
        for (int l = 0; l < DLN; l++) s += demb[l * 128 + t];
        h0[t] = s * (1.f / (float)DLN);
    }
    __syncthreads();

    for (int rr = 0; rr < 16; rr++) {
        int row = wid * 16 + rr;
        const float* wr = Wb + row * 128;
        float s = wr[lane] * h0[lane] + wr[lane + 32] * h0[lane + 32]
                + wr[lane + 64] * h0[lane + 64] + wr[lane + 96] * h0[lane + 96];
        #pragma unroll
        for (int o = 16; o > 0; o >>= 1) s += __shfl_xor_sync(0xffffffffu, s, o);
        if (lane == 0) u[row] = s;
    }
    __syncthreads();

    for (int l = wid; l < DLN; l += 8) {
        const float* dr = demb + l * 128;
        float s = dr[lane] * u[lane] + dr[lane + 32] * u[lane + 32]
                + dr[lane + 64] * u[lane + 64] + dr[lane + 96] * u[lane + 96];
        #pragma unroll
        for (int o = 16; o > 0; o >>= 1) s += __shfl_xor_sync(0xffffffffu, s, o);
        if (lane == 0) sc[l] = s;
    }
    __syncthreads();

    if (t == 0) {
        float mx = sc[0];
        #pragma unroll
        for (int l = 1; l < DLN; l++) mx = fmaxf(mx, sc[l]);
        float sum = 0.f;
        #pragma unroll
        for (int l = 0; l < DLN; l++) { float e = expf(sc[l] - mx); ex[l] = e; sum += e; }
        inv_s = 1.f / sum;
    }
    __syncthreads();

    if (t < 128) {
        float rv = 0.f;
        #pragma unroll
        for (int l = 0; l < DLN; l++) rv += ex[l] * demb[l * 128 + t];
        out[BB * 128 + b * 128 + t] = rv * inv_s;
    }

    for (int rr = 0; rr < 16; rr++) {
        int row = wid * 16 + rr;
        const float* wr = linW + row * 256;
        float s = 0.f;
        #pragma unroll
        for (int q = 0; q < 8; q++) s += wr[lane + 32 * q] * pool[lane + 32 * q];
        #pragma unroll
        for (int o = 16; o > 0; o >>= 1) s += __shfl_xor_sync(0xffffffffu, s, o);
        if (lane == 0) out[b * 128 + row] = s + linb[row];
    }
}

// ---------------------------------------------------------------------------
extern "C" void kernel_launch(void* const* d_in, const int* in_sizes, int n_in,
                              void* d_out, int out_size)
{
    const float* emb   = (const float*)d_in[0];
    const float* Wc    = (const float*)d_in[1];
    const float* bc    = (const float*)d_in[2];
    const float* Wb    = (const float*)d_in[3];
    const float* Wih_f = (const float*)d_in[4];
    const float* Whh_f = (const float*)d_in[5];
    const float* bih_f = (const float*)d_in[6];
    const float* bhh_f = (const float*)d_in[7];
    const float* Wih_b = (const float*)d_in[8];
    const float* Whh_b = (const float*)d_in[9];
    const float* bih_b = (const float*)d_in[10];
    const float* bhh_b = (const float*)d_in[11];
    const float* linW  = (const float*)d_in[12];
    const float* linb  = (const float*)d_in[13];
    const int* node_tokens = (const int*)d_in[14];
    const int* doc_tokens  = (const int*)d_in[15];
    float* out = (float*)d_out;

    cudaFuncSetAttribute(k1_stmt, cudaFuncAttributeMaxDynamicSharedMemorySize, K1_DYN);
    cudaFuncSetAttribute(k1b_gi,  cudaFuncAttributeMaxDynamicSharedMemorySize, K1B_DYN);

    k0_prep<<<7, 256>>>(Wc, Wih_f, Wih_b);
    k1_stmt<<<148, 512, K1_DYN>>>(emb, bc, node_tokens);
    k1b_gi<<<144, 512, K1B_DYN>>>(bih_f, bih_b);
    k2_gru<<<BB * 2, 384>>>(Whh_f, bhh_f, Whh_b, bhh_b);
    k3_out<<<BB, 256>>>(emb, Wb, linW, linb, doc_tokens, out);
}

// round 12
// speedup vs baseline: 2.8540x; 1.0006x over previous
#include <cuda_runtime.h>
#include <cuda_fp16.h>
#include <math.h>
#include <stdint.h>

#define TS 8192
#define BB 64
#define LL 128
#define DLN 20
#define TP 272      // fp16 tile pitch in BYTES (136 halves)
#define SP 132      // fp32 stage pitch in floats

typedef unsigned long long ull;

// ---------------- scratch (device globals; no allocation allowed) ----------
__device__ float g_gi[TS * 768];                     // 25 MB
__device__ float g_pooled[BB * 256];
__device__ __align__(16) __half g_Bh[7 * 16384];     // Wc + 6 Wih row-blocks, [j][k] fp16
__device__ __align__(16) __half g_Af[TS * 128];      // stmt_h, fp16

// subtree sizes of the 32-node binary heap
__constant__ float c_cszf[32] = {32,16,15,8,7,7,7,4,3,3,3,3,3,3,3,2,
                                 1,1,1,1,1,1,1,1,1,1,1,1,1,1,1,1};

// ---------------- helpers ---------------------------------------------------
__device__ __forceinline__ uint32_t s2u(const void* p){
    uint32_t a;
    asm("{ .reg .u64 t; cvta.to.shared.u64 t, %1; cvt.u32.u64 %0, t; }" : "=r"(a) : "l"(p));
    return a;
}
__device__ __forceinline__ void ldsm4(uint32_t addr, uint32_t r[4]){
    asm volatile("ldmatrix.sync.aligned.m8n8.x4.shared.b16 {%0,%1,%2,%3}, [%4];"
        : "=r"(r[0]), "=r"(r[1]), "=r"(r[2]), "=r"(r[3]) : "r"(addr));
}
__device__ __forceinline__ void mma_f16(float d[4], const uint32_t a[4], uint32_t b0, uint32_t b1){
    asm volatile("mma.sync.aligned.m16n8k16.row.col.f32.f16.f16.f32 "
        "{%0,%1,%2,%3}, {%4,%5,%6,%7}, {%8,%9}, {%0,%1,%2,%3};"
        : "+f"(d[0]), "+f"(d[1]), "+f"(d[2]), "+f"(d[3])
        : "r"(a[0]), "r"(a[1]), "r"(a[2]), "r"(a[3]), "r"(b0), "r"(b1));
}
__device__ __forceinline__ float4 f4add(float4 a, float4 b){
    return make_float4(a.x + b.x, a.y + b.y, a.z + b.z, a.w + b.w);
}
__device__ __forceinline__ void cpa16(uint32_t dst, const void* src){
    asm volatile("cp.async.cg.shared.global [%0], [%1], 16;"
        :: "r"(dst), "l"(__cvta_generic_to_global(src)) : "memory");
}
#define CP_COMMIT() asm volatile("cp.async.commit_group;" ::: "memory")
#define CP_WAIT0()  asm volatile("cp.async.wait_group 0;" ::: "memory")
#define CP_WAIT1()  asm volatile("cp.async.wait_group 1;" ::: "memory")

// smem layouts (byte offsets from aligned base). One 128x136 fp16 tile = 34816 B.
// K1:  A | B | stage
#define K1_OFF_A   0
#define K1_OFF_B   34816
#define K1_OFF_STG 69632                 // float[128][132] = 67584 B
#define K1_DYN  (1024 + 69632 + 67584)
// K1b: B | A0 | A1
#define K1B_OFF_B  0
#define K1B_OFF_A0 34816
#define K1B_OFF_A1 69632
#define K1B_DYN (1024 + 104448)

// 128x64x128 fp16 1-term GEMM slice: warp (wr, wc) does rows 16*wr..+15,
// cols 64*wc..+63 (8 n-tiles).
__device__ __forceinline__ void gemm_tile8_1t(
    uint32_t sA, uint32_t sB,
    int wr, int wc, int lane, float acc[8][4])
{
    const uint32_t aOff = (uint32_t)(((lane & 15) + 16 * wr) * TP + ((lane >> 4) << 4));
    const uint32_t bOff = (uint32_t)((64 * wc + ((lane >> 4) << 3) + (lane & 7)) * TP
                                     + (((lane >> 3) & 1) << 4));
    #pragma unroll
    for (int ks = 0; ks < 8; ks++) {
        const uint32_t ko = ks * 32;          // 16 halves = 32 B
        uint32_t a[4];
        ldsm4(sA + aOff + ko, a);
        uint32_t bP = sB + bOff + ko;
        #pragma unroll
        for (int p = 0; p < 4; p++) {
            uint32_t bh[4];
            ldsm4(bP, bh);
            mma_f16(acc[2 * p],     a, bh[0], bh[1]);
            mma_f16(acc[2 * p + 1], a, bh[2], bh[3]);
            bP += 16 * TP;
        }
    }
}

// ---------------------------------------------------------------------------
// K0: fp16 weight staging. tile 0 = Wc; tiles 1..6 = [Wih_f;Wih_b] blocks
// ---------------------------------------------------------------------------
__global__ __launch_bounds__(256) void k0_prep(
    const float* __restrict__ Wc, const float* __restrict__ Wih_f, const float* __restrict__ Wih_b)
{
    const int i = blockIdx.x;
    const float* src;
    if (i == 0) src = Wc;
    else { int cb = (i - 1) * 128; src = (cb < 384) ? (Wih_f + cb * 128) : (Wih_b + (cb - 384) * 128); }
    for (int p = threadIdx.x; p < 128 * 64; p += 256) {
        int j = p >> 6, kp = (p & 63) * 2;
        __half2 hh;
        hh.x = __float2half_rn(src[j * 128 + kp]);
        hh.y = __float2half_rn(src[j * 128 + kp + 1]);
        *(__half2*)(g_Bh + i * 16384 + j * 128 + kp) = hh;
    }
}

// issue cp.async gather of 128 embedding rows (512B each) into stage
__device__ __forceinline__ void gather_pref(
    uint32_t stg_u, const float* __restrict__ emb, const int* tk_s, int t)
{
    #pragma unroll
    for (int i = 0; i < 8; i++) {
        int idx = i * 512 + t;
        int row = idx >> 5, ch = idx & 31;
        cpa16(stg_u + (uint32_t)(row * (SP * 4) + ch * 16),
              emb + (size_t)tk_s[row] * 128 + ch * 4);
    }
    CP_COMMIT();
}

// ---------------------------------------------------------------------------
// K1: persistent (grid 148, 512 thr). Per tile (4 statements): prefetched
//     gather -> tree reduce -> fp16 round -> 1-term mma.sync GEMM vs Wc ->
//     shuffle epilogue (c(v)*bc bias, per-stmt max, relu) -> fp16 staging.
// ---------------------------------------------------------------------------
__global__ __launch_bounds__(512) void k1_stmt(
    const float* __restrict__ emb, const float* __restrict__ bc,
    const int* __restrict__ toks_g)
{
    extern __shared__ char smraw[];
    __shared__ int tkA[128], tkB[128];
    __shared__ float bcs[128];
    __shared__ float epi[1024];

    const int t = threadIdx.x, w = t >> 5, lane = t & 31;
    const int wr = w & 7, wc = w >> 3;
    const uint32_t rawu = s2u(smraw);
    const uint32_t alu = (rawu + 1023u) & ~1023u;
    char* base = smraw + (alu - rawu);
    float* stg = (float*)(base + K1_OFF_STG);
    float4* As4 = (float4*)stg;
    const uint32_t stg_u = alu + K1_OFF_STG;

    if (t < 128) { bcs[t] = bc[t]; tkA[t] = toks_g[blockIdx.x * 128 + t] + 1; }
    __syncthreads();
    gather_pref(stg_u, emb, tkA, t);
    if ((int)blockIdx.x + 148 < 2048 && t < 128)
        tkB[t] = toks_g[(blockIdx.x + 148) * 128 + t] + 1;

    // Wc fp16 tile once
    {
        const float4* sh = (const float4*)g_Bh;
        #pragma unroll
        for (int i = 0; i < 4; i++) {
            int idx = i * 512 + t, jj = idx >> 4, sg = idx & 15;
            *(float4*)(base + K1_OFF_B + jj * TP + sg * 16) = sh[idx];
        }
    }

    int jpar = 0;
    for (int tile = blockIdx.x; tile < 2048; tile += 148, jpar ^= 1) {
        CP_WAIT0();
        __syncthreads();

        // ---- tree reduce, strict heap levels (rows: stmt*32 + node) ----
        if (t < 128) {   // L4: p=15 (single child 31)
            int tt = t >> 5, k4 = t & 31;
            As4[(tt * 32 + 15) * 33 + k4] = f4add(As4[(tt * 32 + 15) * 33 + k4], As4[(tt * 32 + 31) * 33 + k4]);
        }
        __syncthreads();
        #pragma unroll
        for (int i = 0; i < 2; i++) {   // L3: p=7..14 (1024 tasks)
            int idx = i * 512 + t;
            int k4 = idx & 31, q = idx >> 5, tt = q & 3, p = 7 + (q >> 2);
            int br = (tt * 32 + p) * 33;
            As4[br + k4] = f4add(As4[br + k4],
                          f4add(As4[(tt * 32 + 2 * p + 1) * 33 + k4], As4[(tt * 32 + 2 * p + 2) * 33 + k4]));
        }
        __syncthreads();
        {   // L2: p=3..6 (512 tasks)
            int k4 = t & 31, q = t >> 5, tt = q & 3, p = 3 + (q >> 2);
            int br = (tt * 32 + p) * 33;
            As4[br + k4] = f4add(As4[br + k4],
                          f4add(As4[(tt * 32 + 2 * p + 1) * 33 + k4], As4[(tt * 32 + 2 * p + 2) * 33 + k4]));
        }
        __syncthreads();
        if (t < 256) {   // L1: p=1..2 (256 tasks)
            int k4 = t & 31, q = t >> 5, tt = q & 3, p = 1 + (q >> 2);
            int br = (tt * 32 + p) * 33;
            As4[br + k4] = f4add(As4[br + k4],
                          f4add(As4[(tt * 32 + 2 * p + 1) * 33 + k4], As4[(tt * 32 + 2 * p + 2) * 33 + k4]));
        }
        __syncthreads();
        if (t < 128) {   // L0: p=0
            int tt = t >> 5, k4 = t & 31;
            int br = (tt * 32) * 33;
            As4[br + k4] = f4add(As4[br + k4], f4add(As4[(tt * 32 + 1) * 33 + k4], As4[(tt * 32 + 2) * 33 + k4]));
        }
        __syncthreads();

        // ---- fp32 -> fp16 A tile (single rounding) ----
        #pragma unroll
        for (int i = 0; i < 16; i++) {
            int idx = i * 512 + t;
            int row = idx >> 6, c2 = idx & 63;
            float2 v = *(const float2*)(stg + row * SP + c2 * 2);
            __half2 hh;
            hh.x = __float2half_rn(v.x);
            hh.y = __float2half_rn(v.y);
            *(__half2*)(base + K1_OFF_A + row * TP + c2 * 4) = hh;
        }
        __syncthreads();

        // ---- prefetch next tile's gather into (now free) stage ----
        int nxt = tile + 148;
        if (nxt < 2048) gather_pref(stg_u, emb, jpar ? tkA : tkB, t);
        if (nxt + 148 < 2048 && t < 128)
            (jpar ? tkB : tkA)[t] = toks_g[(nxt + 148) * 128 + t] + 1;

        // ---- GEMM (16 warps: wr x wc), 1-term fp16 ----
        float acc[8][4];
        #pragma unroll
        for (int n = 0; n < 8; n++)
            #pragma unroll
            for (int c = 0; c < 4; c++) acc[n][c] = 0.f;
        gemm_tile8_1t(alu + K1_OFF_A, alu + K1_OFF_B, wr, wc, lane, acc);

        // ---- shuffle epilogue: max over 32 nodes of acc + csz*bc, relu ----
        const int rr0 = (wr & 1) * 16 + (lane >> 2);
        const float cz0 = c_cszf[rr0], cz1 = c_cszf[rr0 + 8];
        #pragma unroll
        for (int nt = 0; nt < 8; nt++) {
            int c0 = 64 * wc + nt * 8 + 2 * (lane & 3);
            float b0 = bcs[c0], b1 = bcs[c0 + 1];
            float m0 = fmaxf(acc[nt][0] + cz0 * b0, acc[nt][2] + cz1 * b0);
            float m1 = fmaxf(acc[nt][1] + cz0 * b1, acc[nt][3] + cz1 * b1);
            #pragma unroll
            for (int o = 4; o <= 16; o <<= 1) {
                m0 = fmaxf(m0, __shfl_xor_sync(0xffffffffu, m0, o));
                m1 = fmaxf(m1, __shfl_xor_sync(0xffffffffu, m1, o));
            }
            if ((lane >> 2) == 0) { epi[wr * 128 + c0] = m0; epi[wr * 128 + c0 + 1] = m1; }
        }
        __syncthreads();
        {
            int st = t >> 7, col = t & 127;
            float m = fmaxf(fmaxf(epi[(2 * st) * 128 + col], epi[(2 * st + 1) * 128 + col]), 0.f);
            g_Af[(tile * 4 + st) * 128 + col] = __float2half_rn(m);
        }
        __syncthreads();
    }
}

// ---------------------------------------------------------------------------
// K1b: persistent gi GEMM (512 thr). 144 CTAs = (24 rb-groups x 6 gate-blocks).
//      B loaded once; fp16 A double-buffered via cp.async. Adds bih bias.
// ---------------------------------------------------------------------------
__device__ __forceinline__ void k1b_prefA(uint32_t dstA, int rb, int t){
    const float4* sa = (const float4*)(g_Af + rb * 16384);
    #pragma unroll
    for (int i = 0; i < 4; i++) {
        int idx = i * 512 + t, jj = idx >> 4, sg = idx & 15;
        cpa16(dstA + jj * TP + sg * 16, sa + idx);
    }
    CP_COMMIT();
}

__global__ __launch_bounds__(512) void k1b_gi(
    const float* __restrict__ bih_f, const float* __restrict__ bih_b)
{
    extern __shared__ char smraw[];
    __shared__ float bias_s[128];
    const int t = threadIdx.x, w = t >> 5, lane = t & 31;
    const int wr = w & 7, wc = w >> 3;
    const int by = blockIdx.x % 6, rb0 = blockIdx.x / 6;
    const uint32_t rawu = s2u(smraw);
    const uint32_t alu = (rawu + 1023u) & ~1023u;
    char* base = smraw + (alu - rawu);

    if (t < 128) bias_s[t] = (by < 3) ? bih_f[by * 128 + t] : bih_b[(by - 3) * 128 + t];

    k1b_prefA(alu + K1B_OFF_A0, rb0, t);

    {   // B gate-block once
        const float4* sbh = (const float4*)(g_Bh + (1 + by) * 16384);
        #pragma unroll
        for (int i = 0; i < 4; i++) {
            int idx = i * 512 + t, jj = idx >> 4, sg = idx & 15;
            *(float4*)(base + K1B_OFF_B + jj * TP + sg * 16) = sbh[idx];
        }
    }

    int pb = 0;
    for (int rb = rb0; rb < 64; rb += 24, pb ^= 1) {
        CP_WAIT0();
        __syncthreads();
        if (rb + 24 < 64)
            k1b_prefA(alu + (pb ? K1B_OFF_A0 : K1B_OFF_A1), rb + 24, t);

        float acc[8][4];
        #pragma unroll
        for (int n = 0; n < 8; n++)
            #pragma unroll
            for (int c = 0; c < 4; c++) acc[n][c] = 0.f;
        gemm_tile8_1t(alu + (pb ? K1B_OFF_A1 : K1B_OFF_A0),
                      alu + K1B_OFF_B, wr, wc, lane, acc);

        const int row = rb * 128 + 16 * wr + (lane >> 2);
        float* o0 = g_gi + (size_t)row * 768 + by * 128 + 64 * wc;
        float* o1 = o0 + 8 * 768;
        const int cb = (lane & 3) * 2;
        #pragma unroll
        for (int nt = 0; nt < 8; nt++) {
            float b0 = bias_s[64 * wc + nt * 8 + cb];
            float b1 = bias_s[64 * wc + nt * 8 + cb + 1];
            *(float2*)(o0 + nt * 8 + cb) = make_float2(acc[nt][0] + b0, acc[nt][1] + b1);
            *(float2*)(o1 + nt * 8 + cb) = make_float2(acc[nt][2] + b0, acc[nt][3] + b1);
        }
    }
}

// ---------------------------------------------------------------------------
__device__ __forceinline__ void ffma2(ull& d, ull a, ull b){
    asm("fma.rn.f32x2 %0, %1, %2, %0;" : "+l"(d) : "l"(a), "l"(b));
}
__device__ __forceinline__ float2 ull2f2(ull v){
    float2 f; asm("mov.b64 {%0, %1}, %2;" : "=f"(f.x), "=f"(f.y) : "l"(v)); return f;
}

// ---------------------------------------------------------------------------
// K2: GRU recurrence. 128 CTAs, one per (batch, dir). 384 threads: thread
//     (g, tt) owns rows 2tt, 2tt+1 for h-half g -> h LDS amortized over 2
//     rows, 128 weight regs/thread (fits, no spill).
// ---------------------------------------------------------------------------
__global__ __launch_bounds__(384) void k2_gru(
    const float* __restrict__ Whh_f, const float* __restrict__ bhh_f,
    const float* __restrict__ Whh_b, const float* __restrict__ bhh_b)
{
    __shared__ float h_s[128];
    __shared__ float part[768];              // [half][row]
    __shared__ __align__(16) float gi_buf[2][384];
    __shared__ float bhh_s[384];

    const int t = threadIdx.x;
    const int b = blockIdx.x >> 1, dir = blockIdx.x & 1;
    const float* Whh = dir ? Whh_b : Whh_f;
    const float* bhh = dir ? bhh_b : bhh_f;

    const int g  = (t < 192) ? 0 : 1;
    const int tt = (t < 192) ? t : t - 192;
    const int j0 = 2 * tt;                   // rows j0, j0+1

    ull w0[32], w1[32];                      // 2 rows x 64 cols fp32
    {
        const ulonglong2* p0 = (const ulonglong2*)(Whh + (size_t)j0 * 128 + g * 64);
        const ulonglong2* p1 = (const ulonglong2*)(Whh + (size_t)(j0 + 1) * 128 + g * 64);
        #pragma unroll
        for (int i = 0; i < 16; i++) {
            ulonglong2 v0 = p0[i]; w0[2*i] = v0.x; w0[2*i+1] = v0.y;
            ulonglong2 v1 = p1[i]; w1[2*i] = v1.x; w1[2*i+1] = v1.y;
        }
    }
    bhh_s[t] = bhh[t];
    if (t < 128) h_s[t] = 0.f;

    const float* gsrc = g_gi + (size_t)(b * LL + (dir ? LL - 1 : 0)) * 768 + dir * 384;
    const int stp = dir ? -768 : 768;

    if (t < 96) cpa16(s2u(&gi_buf[0][0]) + t * 16, gsrc + t * 4);
    CP_COMMIT();
    __syncthreads();

    float hmax = -3e38f;
    for (int l = 0; l < LL; l++) {
        if (l + 1 < LL && t < 96)
            cpa16(s2u(&gi_buf[(l + 1) & 1][0]) + t * 16, gsrc + (l + 1) * stp + t * 4);
        CP_COMMIT();

        // matvec: 2 rows share each h load; 4 independent chains
        ull a00 = 0, a01 = 0, a10 = 0, a11 = 0;
        const ulonglong2* hp = (const ulonglong2*)(h_s + g * 64);
        #pragma unroll
        for (int i = 0; i < 16; i++) {
            ulonglong2 hv = hp[i];
            ffma2(a00, w0[2*i],     hv.x);
            ffma2(a01, w0[2*i + 1], hv.y);
            ffma2(a10, w1[2*i],     hv.x);
            ffma2(a11, w1[2*i + 1], hv.y);
        }
        float2 f00 = ull2f2(a00), f01 = ull2f2(a01);
        float2 f10 = ull2f2(a10), f11 = ull2f2(a11);
        *(float2*)(part + g * 384 + j0) = make_float2(
            (f00.x + f00.y) + (f01.x + f01.y),
            (f10.x + f10.y) + (f11.x + f11.y));
        CP_WAIT1();
        __syncthreads();

        if (t < 128) {
            const float* gb = gi_buf[l & 1];
            float ghr = part[t]       + part[384 + t] + bhh_s[t];
            float ghz = part[128 + t] + part[512 + t] + bhh_s[128 + t];
            float ghn = part[256 + t] + part[640 + t] + bhh_s[256 + t];
            float r = __fdividef(1.f, 1.f + __expf(-(gb[t] + ghr)));
            float z = __fdividef(1.f, 1.f + __expf(-(gb[128 + t] + ghz)));
            float y = gb[256 + t] + r * ghn;
            float n = 1.f - __fdividef(2.f, __expf(2.f * y) + 1.f);
            float hnew = (1.f - z) * n + z * h_s[t];
            h_s[t] = hnew;
            hmax = fmaxf(hmax, hnew);
        }
        __syncthreads();
    }
    if (t < 128) g_pooled[b * 256 + dir * 128 + t] = hmax;
}

// ---------------------------------------------------------------------------
// K3: lvec = pooled @ linW^T + linb ; rvec = doc attention.
// ---------------------------------------------------------------------------
__global__ __launch_bounds__(256) void k3_out(
    const float* __restrict__ emb, const float* __restrict__ Wb,
    const float* __restrict__ linW, const float* __restrict__ linb,
    const int* __restrict__ doc, float* __restrict__ out)
{
    __shared__ float demb[DLN * 128];
    __shared__ float h0[128];
    __shared__ float u[128];
    __shared__ float sc[DLN];
    __shared__ float ex[DLN];
    __shared__ float inv_s;
    __shared__ float pool[256];
    __shared__ int dti[DLN];

    const int t = threadIdx.x, b = blockIdx.x;
    const int wid = t >> 5, lane = t & 31;

    pool[t] = g_pooled[b * 256 + t];
    if (t < DLN) dti[t] = doc[b * DLN + t] + 1;
    __syncthreads();

    #pragma unroll
    for (int i = 0; i < 10; i++) {
        int idx = i * 256 + t;
        demb[idx] = emb[(size_t)dti[idx >> 7] * 128 + (idx & 127)];
    }
    __syncthreads();

    if (t < 128) {
        float s = 0.f;
        #pragma unroll
        for (int l = 0; l < DLN; l++) s += demb[l * 128 + t];
        h0[t] = s * (1.f / (float)DLN);
    }
    __syncthreads();

    for (int rr = 0; rr < 16; rr++) {
        int row = wid * 16 + rr;
        const float* wr = Wb + row * 128;
        float s = wr[lane] * h0[lane] + wr[lane + 32] * h0[lane + 32]
                + wr[lane + 64] * h0[lane + 64] + wr[lane + 96] * h0[lane + 96];
        #pragma unroll
        for (int o = 16; o > 0; o >>= 1) s += __shfl_xor_sync(0xffffffffu, s, o);
        if (lane == 0) u[row] = s;
    }
    __syncthreads();

    for (int l = wid; l < DLN; l += 8) {
        const float* dr = demb + l * 128;
        float s = dr[lane] * u[lane] + dr[lane + 32] * u[lane + 32]
                + dr[lane + 64] * u[lane + 64] + dr[lane + 96] * u[lane + 96];
        #pragma unroll
        for (int o = 16; o > 0; o >>= 1) s += __shfl_xor_sync(0xffffffffu, s, o);
        if (lane == 0) sc[l] = s;
    }
    __syncthreads();

    if (t == 0) {
        float mx = sc[0];
        #pragma unroll
        for (int l = 1; l < DLN; l++) mx = fmaxf(mx, sc[l]);
        float sum = 0.f;
        #pragma unroll
        for (int l = 0; l < DLN; l++) { float e = expf(sc[l] - mx); ex[l] = e; sum += e; }
        inv_s = 1.f / sum;
    }
    __syncthreads();

    if (t < 128) {
        float rv = 0.f;
        #pragma unroll
        for (int l = 0; l < DLN; l++) rv += ex[l] * demb[l * 128 + t];
        out[BB * 128 + b * 128 + t] = rv * inv_s;
    }

    for (int rr = 0; rr < 16; rr++) {
        int row = wid * 16 + rr;
        const float* wr = linW + row * 256;
        float s = 0.f;
        #pragma unroll
        for (int q = 0; q < 8; q++) s += wr[lane + 32 * q] * pool[lane + 32 * q];
        #pragma unroll
        for (int o = 16; o > 0; o >>= 1) s += __shfl_xor_sync(0xffffffffu, s, o);
        if (lane == 0) out[b * 128 + row] = s + linb[row];
    }
}

// ---------------------------------------------------------------------------
extern "C" void kernel_launch(void* const* d_in, const int* in_sizes, int n_in,
                              void* d_out, int out_size)
{
    const float* emb   = (const float*)d_in[0];
    const float* Wc    = (const float*)d_in[1];
    const float* bc    = (const float*)d_in[2];
    const float* Wb    = (const float*)d_in[3];
    const float* Wih_f = (const float*)d_in[4];
    const float* Whh_f = (const float*)d_in[5];
    const float* bih_f = (const float*)d_in[6];
    const float* bhh_f = (const float*)d_in[7];
    const float* Wih_b = (const float*)d_in[8];
    const float* Whh_b = (const float*)d_in[9];
    const float* bih_b = (const float*)d_in[10];
    const float* bhh_b = (const float*)d_in[11];
    const float* linW  = (const float*)d_in[12];
    const float* linb  = (const float*)d_in[13];
    const int* node_tokens = (const int*)d_in[14];
    const int* doc_tokens  = (const int*)d_in[15];
    float* out = (float*)d_out;

    cudaFuncSetAttribute(k1_stmt, cudaFuncAttributeMaxDynamicSharedMemorySize, K1_DYN);
    cudaFuncSetAttribute(k1b_gi,  cudaFuncAttributeMaxDynamicSharedMemorySize, K1B_DYN);

    k0_prep<<<7, 256>>>(Wc, Wih_f, Wih_b);
    k1_stmt<<<148, 512, K1_DYN>>>(emb, bc, node_tokens);
    k1b_gi<<<144, 512, K1B_DYN>>>(bih_f, bih_b);
    k2_gru<<<BB * 2, 384>>>(Whh_f, bhh_f, Whh_b, bhh_b);
    k3_out<<<BB, 256>>>(emb, Wb, linW, linb, doc_tokens, out);
}

// round 13
// speedup vs baseline: 2.9621x; 1.0379x over previous
#include <cuda_runtime.h>
#include <cuda_fp16.h>
#include <math.h>
#include <stdint.h>

#define TS 8192
#define BB 64
#define LL 128
#define DLN 20
#define TP 272      // fp16 tile pitch in BYTES (136 halves)
#define SP 132      // fp32 stage pitch in floats

typedef unsigned long long ull;

// ---------------- scratch (device globals; no allocation allowed) ----------
__device__ float g_gi[TS * 768];                     // 25 MB
__device__ float g_pooled[BB * 256];
__device__ __align__(16) __half g_Af[TS * 128];      // stmt_h, fp16

// subtree sizes of the 32-node binary heap
__constant__ float c_cszf[32] = {32,16,15,8,7,7,7,4,3,3,3,3,3,3,3,2,
                                 1,1,1,1,1,1,1,1,1,1,1,1,1,1,1,1};

// ---------------- helpers ---------------------------------------------------
__device__ __forceinline__ uint32_t s2u(const void* p){
    uint32_t a;
    asm("{ .reg .u64 t; cvta.to.shared.u64 t, %1; cvt.u32.u64 %0, t; }" : "=r"(a) : "l"(p));
    return a;
}
__device__ __forceinline__ void ldsm4(uint32_t addr, uint32_t r[4]){
    asm volatile("ldmatrix.sync.aligned.m8n8.x4.shared.b16 {%0,%1,%2,%3}, [%4];"
        : "=r"(r[0]), "=r"(r[1]), "=r"(r[2]), "=r"(r[3]) : "r"(addr));
}
__device__ __forceinline__ void mma_f16(float d[4], const uint32_t a[4], uint32_t b0, uint32_t b1){
    asm volatile("mma.sync.aligned.m16n8k16.row.col.f32.f16.f16.f32 "
        "{%0,%1,%2,%3}, {%4,%5,%6,%7}, {%8,%9}, {%0,%1,%2,%3};"
        : "+f"(d[0]), "+f"(d[1]), "+f"(d[2]), "+f"(d[3])
        : "r"(a[0]), "r"(a[1]), "r"(a[2]), "r"(a[3]), "r"(b0), "r"(b1));
}
__device__ __forceinline__ float4 f4add(float4 a, float4 b){
    return make_float4(a.x + b.x, a.y + b.y, a.z + b.z, a.w + b.w);
}
__device__ __forceinline__ void cpa16(uint32_t dst, const void* src){
    asm volatile("cp.async.cg.shared.global [%0], [%1], 16;"
        :: "r"(dst), "l"(__cvta_generic_to_global(src)) : "memory");
}
#define CP_COMMIT() asm volatile("cp.async.commit_group;" ::: "memory")
#define CP_WAIT0()  asm volatile("cp.async.wait_group 0;" ::: "memory")

// smem layouts (byte offsets from aligned base). One 128x136 fp16 tile = 34816 B.
// K1:  A | B | stage
#define K1_OFF_A   0
#define K1_OFF_B   34816
#define K1_OFF_STG 69632                 // float[128][132] = 67584 B
#define K1_DYN  (1024 + 69632 + 67584)
// K1b: B | A0 | A1
#define K1B_OFF_B  0
#define K1B_OFF_A0 34816
#define K1B_OFF_A1 69632
#define K1B_DYN (1024 + 104448)

// 128x64x128 fp16 1-term GEMM slice: warp (wr, wc) does rows 16*wr..+15,
// cols 64*wc..+63 (8 n-tiles).
__device__ __forceinline__ void gemm_tile8_1t(
    uint32_t sA, uint32_t sB,
    int wr, int wc, int lane, float acc[8][4])
{
    const uint32_t aOff = (uint32_t)(((lane & 15) + 16 * wr) * TP + ((lane >> 4) << 4));
    const uint32_t bOff = (uint32_t)((64 * wc + ((lane >> 4) << 3) + (lane & 7)) * TP
                                     + (((lane >> 3) & 1) << 4));
    #pragma unroll
    for (int ks = 0; ks < 8; ks++) {
        const uint32_t ko = ks * 32;          // 16 halves = 32 B
        uint32_t a[4];
        ldsm4(sA + aOff + ko, a);
        uint32_t bP = sB + bOff + ko;
        #pragma unroll
        for (int p = 0; p < 4; p++) {
            uint32_t bh[4];
            ldsm4(bP, bh);
            mma_f16(acc[2 * p],     a, bh[0], bh[1]);
            mma_f16(acc[2 * p + 1], a, bh[2], bh[3]);
            bP += 16 * TP;
        }
    }
}

// convert a 128x128 fp32 weight block (row-major, gmem) into fp16 smem tile
__device__ __forceinline__ void conv_w_tile(char* dst, const float* __restrict__ src, int t){
    #pragma unroll
    for (int i = 0; i < 8; i++) {
        int idx = i * 512 + t;
        int j = idx >> 5, c4 = idx & 31;
        float4 v = *(const float4*)(src + j * 128 + c4 * 4);
        __half2 h0, h1;
        h0.x = __float2half_rn(v.x); h0.y = __float2half_rn(v.y);
        h1.x = __float2half_rn(v.z); h1.y = __float2half_rn(v.w);
        *(__half2*)(dst + j * TP + c4 * 8)     = h0;
        *(__half2*)(dst + j * TP + c4 * 8 + 4) = h1;
    }
}

// issue cp.async gather of 128 embedding rows (512B each) into stage
__device__ __forceinline__ void gather_pref(
    uint32_t stg_u, const float* __restrict__ emb, const int* tk_s, int t)
{
    #pragma unroll
    for (int i = 0; i < 8; i++) {
        int idx = i * 512 + t;
        int row = idx >> 5, ch = idx & 31;
        cpa16(stg_u + (uint32_t)(row * (SP * 4) + ch * 16),
              emb + (size_t)tk_s[row] * 128 + ch * 4);
    }
    CP_COMMIT();
}

// ---------------------------------------------------------------------------
// K1: persistent (grid 148, 512 thr). Per tile (4 statements): prefetched
//     gather -> tree reduce -> fp16 round -> 1-term mma.sync GEMM vs Wc ->
//     shuffle epilogue (c(v)*bc bias, per-stmt max, relu) -> fp16 staging.
// ---------------------------------------------------------------------------
__global__ __launch_bounds__(512) void k1_stmt(
    const float* __restrict__ emb, const float* __restrict__ Wc,
    const float* __restrict__ bc, const int* __restrict__ toks_g)
{
    extern __shared__ char smraw[];
    __shared__ int tkA[128], tkB[128];
    __shared__ float bcs[128];
    __shared__ float epi[1024];

    const int t = threadIdx.x, w = t >> 5, lane = t & 31;
    const int wr = w & 7, wc = w >> 3;
    const uint32_t rawu = s2u(smraw);
    const uint32_t alu = (rawu + 1023u) & ~1023u;
    char* base = smraw + (alu - rawu);
    float* stg = (float*)(base + K1_OFF_STG);
    float4* As4 = (float4*)stg;
    const uint32_t stg_u = alu + K1_OFF_STG;

    if (t < 128) { bcs[t] = bc[t]; tkA[t] = toks_g[blockIdx.x * 128 + t] + 1; }
    __syncthreads();
    gather_pref(stg_u, emb, tkA, t);
    if ((int)blockIdx.x + 148 < 2048 && t < 128)
        tkB[t] = toks_g[(blockIdx.x + 148) * 128 + t] + 1;

    // Wc fp16 tile once (converted in-CTA from gmem)
    conv_w_tile(base + K1_OFF_B, Wc, t);

    int jpar = 0;
    for (int tile = blockIdx.x; tile < 2048; tile += 148, jpar ^= 1) {
        CP_WAIT0();
        __syncthreads();

        // ---- tree reduce, strict heap levels (rows: stmt*32 + node) ----
        if (t < 128) {   // L4: p=15 (single child 31)
            int tt = t >> 5, k4 = t & 31;
            As4[(tt * 32 + 15) * 33 + k4] = f4add(As4[(tt * 32 + 15) * 33 + k4], As4[(tt * 32 + 31) * 33 + k4]);
        }
        __syncthreads();
        #pragma unroll
        for (int i = 0; i < 2; i++) {   // L3: p=7..14 (1024 tasks)
            int idx = i * 512 + t;
            int k4 = idx & 31, q = idx >> 5, tt = q & 3, p = 7 + (q >> 2);
            int br = (tt * 32 + p) * 33;
            As4[br + k4] = f4add(As4[br + k4],
                          f4add(As4[(tt * 32 + 2 * p + 1) * 33 + k4], As4[(tt * 32 + 2 * p + 2) * 33 + k4]));
        }
        __syncthreads();
        {   // L2: p=3..6 (512 tasks)
            int k4 = t & 31, q = t >> 5, tt = q & 3, p = 3 + (q >> 2);
            int br = (tt * 32 + p) * 33;
            As4[br + k4] = f4add(As4[br + k4],
                          f4add(As4[(tt * 32 + 2 * p + 1) * 33 + k4], As4[(tt * 32 + 2 * p + 2) * 33 + k4]));
        }
        __syncthreads();
        if (t < 256) {   // L1: p=1..2 (256 tasks)
            int k4 = t & 31, q = t >> 5, tt = q & 3, p = 1 + (q >> 2);
            int br = (tt * 32 + p) * 33;
            As4[br + k4] = f4add(As4[br + k4],
                          f4add(As4[(tt * 32 + 2 * p + 1) * 33 + k4], As4[(tt * 32 + 2 * p + 2) * 33 + k4]));
        }
        __syncthreads();
        if (t < 128) {   // L0: p=0
            int tt = t >> 5, k4 = t & 31;
            int br = (tt * 32) * 33;
            As4[br + k4] = f4add(As4[br + k4], f4add(As4[(tt * 32 + 1) * 33 + k4], As4[(tt * 32 + 2) * 33 + k4]));
        }
        __syncthreads();

        // ---- fp32 -> fp16 A tile (single rounding) ----
        #pragma unroll
        for (int i = 0; i < 16; i++) {
            int idx = i * 512 + t;
            int row = idx >> 6, c2 = idx & 63;
            float2 v = *(const float2*)(stg + row * SP + c2 * 2);
            __half2 hh;
            hh.x = __float2half_rn(v.x);
            hh.y = __float2half_rn(v.y);
            *(__half2*)(base + K1_OFF_A + row * TP + c2 * 4) = hh;
        }
        __syncthreads();

        // ---- prefetch next tile's gather into (now free) stage ----
        int nxt = tile + 148;
        if (nxt < 2048) gather_pref(stg_u, emb, jpar ? tkA : tkB, t);
        if (nxt + 148 < 2048 && t < 128)
            (jpar ? tkB : tkA)[t] = toks_g[(nxt + 148) * 128 + t] + 1;

        // ---- GEMM (16 warps: wr x wc), 1-term fp16 ----
        float acc[8][4];
        #pragma unroll
        for (int n = 0; n < 8; n++)
            #pragma unroll
            for (int c = 0; c < 4; c++) acc[n][c] = 0.f;
        gemm_tile8_1t(alu + K1_OFF_A, alu + K1_OFF_B, wr, wc, lane, acc);

        // ---- shuffle epilogue: max over 32 nodes of acc + csz*bc, relu ----
        const int rr0 = (wr & 1) * 16 + (lane >> 2);
        const float cz0 = c_cszf[rr0], cz1 = c_cszf[rr0 + 8];
        #pragma unroll
        for (int nt = 0; nt < 8; nt++) {
            int c0 = 64 * wc + nt * 8 + 2 * (lane & 3);
            float b0 = bcs[c0], b1 = bcs[c0 + 1];
            float m0 = fmaxf(acc[nt][0] + cz0 * b0, acc[nt][2] + cz1 * b0);
            float m1 = fmaxf(acc[nt][1] + cz0 * b1, acc[nt][3] + cz1 * b1);
            #pragma unroll
            for (int o = 4; o <= 16; o <<= 1) {
                m0 = fmaxf(m0, __shfl_xor_sync(0xffffffffu, m0, o));
                m1 = fmaxf(m1, __shfl_xor_sync(0xffffffffu, m1, o));
            }
            if ((lane >> 2) == 0) { epi[wr * 128 + c0] = m0; epi[wr * 128 + c0 + 1] = m1; }
        }
        __syncthreads();
        {
            int st = t >> 7, col = t & 127;
            float m = fmaxf(fmaxf(epi[(2 * st) * 128 + col], epi[(2 * st + 1) * 128 + col]), 0.f);
            g_Af[(tile * 4 + st) * 128 + col] = __float2half_rn(m);
        }
        __syncthreads();
    }
}

// ---------------------------------------------------------------------------
// K1b: persistent gi GEMM (512 thr). 144 CTAs = (24 rb-groups x 6 gate-blocks).
//      B converted once from gmem; fp16 A double-buffered via cp.async.
//      Adds bih bias (pre-folded out of k2).
// ---------------------------------------------------------------------------
__device__ __forceinline__ void k1b_prefA(uint32_t dstA, int rb, int t){
    const float4* sa = (const float4*)(g_Af + rb * 16384);
    #pragma unroll
    for (int i = 0; i < 4; i++) {
        int idx = i * 512 + t, jj = idx >> 4, sg = idx & 15;
        cpa16(dstA + jj * TP + sg * 16, sa + idx);
    }
    CP_COMMIT();
}

__global__ __launch_bounds__(512) void k1b_gi(
    const float* __restrict__ Wih_f, const float* __restrict__ Wih_b,
    const float* __restrict__ bih_f, const float* __restrict__ bih_b)
{
    extern __shared__ char smraw[];
    __shared__ float bias_s[128];
    const int t = threadIdx.x, w = t >> 5, lane = t & 31;
    const int wr = w & 7, wc = w >> 3;
    const int by = blockIdx.x % 6, rb0 = blockIdx.x / 6;
    const uint32_t rawu = s2u(smraw);
    const uint32_t alu = (rawu + 1023u) & ~1023u;
    char* base = smraw + (alu - rawu);

    if (t < 128) bias_s[t] = (by < 3) ? bih_f[by * 128 + t] : bih_b[(by - 3) * 128 + t];

    k1b_prefA(alu + K1B_OFF_A0, rb0, t);

    // B gate-block once (converted in-CTA from gmem)
    {
        const float* Wsel = (by < 3) ? (Wih_f + (size_t)by * 128 * 128)
                                     : (Wih_b + (size_t)(by - 3) * 128 * 128);
        conv_w_tile(base + K1B_OFF_B, Wsel, t);
    }

    int pb = 0;
    for (int rb = rb0; rb < 64; rb += 24, pb ^= 1) {
        CP_WAIT0();
        __syncthreads();
        if (rb + 24 < 64)
            k1b_prefA(alu + (pb ? K1B_OFF_A0 : K1B_OFF_A1), rb + 24, t);

        float acc[8][4];
        #pragma unroll
        for (int n = 0; n < 8; n++)
            #pragma unroll
            for (int c = 0; c < 4; c++) acc[n][c] = 0.f;
        gemm_tile8_1t(alu + (pb ? K1B_OFF_A1 : K1B_OFF_A0),
                      alu + K1B_OFF_B, wr, wc, lane, acc);

        const int row = rb * 128 + 16 * wr + (lane >> 2);
        float* o0 = g_gi + (size_t)row * 768 + by * 128 + 64 * wc;
        float* o1 = o0 + 8 * 768;
        const int cb = (lane & 3) * 2;
        #pragma unroll
        for (int nt = 0; nt < 8; nt++) {
            float b0 = bias_s[64 * wc + nt * 8 + cb];
            float b1 = bias_s[64 * wc + nt * 8 + cb + 1];
            *(float2*)(o0 + nt * 8 + cb) = make_float2(acc[nt][0] + b0, acc[nt][1] + b1);
            *(float2*)(o1 + nt * 8 + cb) = make_float2(acc[nt][2] + b0, acc[nt][3] + b1);
        }
    }
}

// ---------------------------------------------------------------------------
__device__ __forceinline__ void ffma2(ull& d, ull a, ull b){
    asm("fma.rn.f32x2 %0, %1, %2, %0;" : "+l"(d) : "l"(a), "l"(b));
}
__device__ __forceinline__ float2 ull2f2(ull v){
    float2 f; asm("mov.b64 {%0, %1}, %2;" : "=f"(f.x), "=f"(f.y) : "l"(v)); return f;
}

// ---------------------------------------------------------------------------
// K2: GRU recurrence. 128 CTAs, one per (batch, dir). 384 threads: thread
//     (g, tt) owns rows 2tt, 2tt+1 for h-half g. gi read directly via LDG
//     by the gate threads at loop top (no cp.async machinery, fewer regs).
// ---------------------------------------------------------------------------
__global__ __launch_bounds__(384) void k2_gru(
    const float* __restrict__ Whh_f, const float* __restrict__ bhh_f,
    const float* __restrict__ Whh_b, const float* __restrict__ bhh_b)
{
    __shared__ float h_s[128];
    __shared__ float part[768];              // [half][row]
    __shared__ float bhh_s[384];

    const int t = threadIdx.x;
    const int b = blockIdx.x >> 1, dir = blockIdx.x & 1;
    const float* Whh = dir ? Whh_b : Whh_f;
    const float* bhh = dir ? bhh_b : bhh_f;

    const int g  = (t < 192) ? 0 : 1;
    const int tt = (t < 192) ? t : t - 192;
    const int j0 = 2 * tt;                   // rows j0, j0+1

    ull w0[32], w1[32];                      // 2 rows x 64 cols fp32
    {
        const ulonglong2* p0 = (const ulonglong2*)(Whh + (size_t)j0 * 128 + g * 64);
        const ulonglong2* p1 = (const ulonglong2*)(Whh + (size_t)(j0 + 1) * 128 + g * 64);
        #pragma unroll
        for (int i = 0; i < 16; i++) {
            ulonglong2 v0 = p0[i]; w0[2*i] = v0.x; w0[2*i+1] = v0.y;
            ulonglong2 v1 = p1[i]; w1[2*i] = v1.x; w1[2*i+1] = v1.y;
        }
    }
    bhh_s[t] = bhh[t];
    if (t < 128) h_s[t] = 0.f;

    // gi source: row l (forward) or 127-l (backward), this dir's 384-gate slice
    const float* gbase = g_gi + (size_t)(b * LL + (dir ? LL - 1 : 0)) * 768 + dir * 384;
    const int stp = dir ? -768 : 768;
    __syncthreads();

    float hmax = -3e38f;
    for (int l = 0; l < LL; l++) {
        // gate threads fetch this step's gi early (covered by the matvec)
        float gr, gz, gn;
        if (t < 128) {
            const float* gp = gbase + (ptrdiff_t)l * stp;
            gr = __ldg(gp + t);
            gz = __ldg(gp + 128 + t);
            gn = __ldg(gp + 256 + t);
        }

        // matvec: 2 rows share each h load; 4 independent chains
        ull a00 = 0, a01 = 0, a10 = 0, a11 = 0;
        const ulonglong2* hp = (const ulonglong2*)(h_s + g * 64);
        #pragma unroll
        for (int i = 0; i < 16; i++) {
            ulonglong2 hv = hp[i];
            ffma2(a00, w0[2*i],     hv.x);
            ffma2(a01, w0[2*i + 1], hv.y);
            ffma2(a10, w1[2*i],     hv.x);
            ffma2(a11, w1[2*i + 1], hv.y);
        }
        float2 f00 = ull2f2(a00), f01 = ull2f2(a01);
        float2 f10 = ull2f2(a10), f11 = ull2f2(a11);
        *(float2*)(part + g * 384 + j0) = make_float2(
            (f00.x + f00.y) + (f01.x + f01.y),
            (f10.x + f10.y) + (f11.x + f11.y));
        __syncthreads();

        if (t < 128) {
            float ghr = part[t]       + part[384 + t] + bhh_s[t];
            float ghz = part[128 + t] + part[512 + t] + bhh_s[128 + t];
            float ghn = part[256 + t] + part[640 + t] + bhh_s[256 + t];
            float r = __fdividef(1.f, 1.f + __expf(-(gr + ghr)));
            float z = __fdividef(1.f, 1.f + __expf(-(gz + ghz)));
            float y = gn + r * ghn;
            float n = 1.f - __fdividef(2.f, __expf(2.f * y) + 1.f);
            float hnew = (1.f - z) * n + z * h_s[t];
            h_s[t] = hnew;
            hmax = fmaxf(hmax, hnew);
        }
        __syncthreads();
    }
    if (t < 128) g_pooled[b * 256 + dir * 128 + t] = hmax;
}

// ---------------------------------------------------------------------------
// K3: lvec = pooled @ linW^T + linb ; rvec = doc attention.
// ---------------------------------------------------------------------------
__global__ __launch_bounds__(256) void k3_out(
    const float* __restrict__ emb, const float* __restrict__ Wb,
    const float* __restrict__ linW, const float* __restrict__ linb,
    const int* __restrict__ doc, float* __restrict__ out)
{
    __shared__ float demb[DLN * 128];
    __shared__ float h0[128];
    __shared__ float u[128];
    __shared__ float sc[DLN];
    __shared__ float ex[DLN];
    __shared__ float inv_s;
    __shared__ float pool[256];
    __shared__ int dti[DLN];

    const int t = threadIdx.x, b = blockIdx.x;
    const int wid = t >> 5, lane = t & 31;

    pool[t] = g_pooled[b * 256 + t];
    if (t < DLN) dti[t] = doc[b * DLN + t] + 1;
    __syncthreads();

    #pragma unroll
    for (int i = 0; i < 10; i++) {
        int idx = i * 256 + t;
        demb[idx] = emb[(size_t)dti[idx >> 7] * 128 + (idx & 127)];
    }
    __syncthreads();

    if (t < 128) {
        float s = 0.f;
        #pragma unroll
        for (int l = 0; l < DLN; l++) s += demb[l * 128 + t];
        h0[t] = s * (1.f / (float)DLN);
    }
    __syncthreads();

    for (int rr = 0; rr < 16; rr++) {
        int row = wid * 16 + rr;
        const float* wr = Wb + row * 128;
        float s = wr[lane] * h0[lane] + wr[lane + 32] * h0[lane + 32]
                + wr[lane + 64] * h0[lane + 64] + wr[lane + 96] * h0[lane + 96];
        #pragma unroll
        for (int o = 16; o > 0; o >>= 1) s += __shfl_xor_sync(0xffffffffu, s, o);
        if (lane == 0) u[row] = s;
    }
    __syncthreads();

    for (int l = wid; l < DLN; l += 8) {
        const float* dr = demb + l * 128;
        float s = dr[lane] * u[lane] + dr[lane + 32] * u[lane + 32]
                + dr[lane + 64] * u[lane + 64] + dr[lane + 96] * u[lane + 96];
        #pragma unroll
        for (int o = 16; o > 0; o >>= 1) s += __shfl_xor_sync(0xffffffffu, s, o);
        if (lane == 0) sc[l] = s;
    }
    __syncthreads();

    if (t == 0) {
        float mx = sc[0];
        #pragma unroll
        for (int l = 1; l < DLN; l++) mx = fmaxf(mx, sc[l]);
        float sum = 0.f;
        #pragma unroll
        for (int l = 0; l < DLN; l++) { float e = expf(sc[l] - mx); ex[l] = e; sum += e; }
        inv_s = 1.f / sum;
    }
    __syncthreads();

    if (t < 128) {
        float rv = 0.f;
        #pragma unroll
        for (int l = 0; l < DLN; l++) rv += ex[l] * demb[l * 128 + t];
        out[BB * 128 + b * 128 + t] = rv * inv_s;
    }

    for (int rr = 0; rr < 16; rr++) {
        int row = wid * 16 + rr;
        const float* wr = linW + row * 256;
        float s = 0.f;
        #pragma unroll
        for (int q = 0; q < 8; q++) s += wr[lane + 32 * q] * pool[lane + 32 * q];
        #pragma unroll
        for (int o = 16; o > 0; o >>= 1) s += __shfl_xor_sync(0xffffffffu, s, o);
        if (lane == 0) out[b * 128 + row] = s + linb[row];
    }
}

// ---------------------------------------------------------------------------
extern "C" void kernel_launch(void* const* d_in, const int* in_sizes, int n_in,
                              void* d_out, int out_size)
{
    const float* emb   = (const float*)d_in[0];
    const float* Wc    = (const float*)d_in[1];
    const float* bc    = (const float*)d_in[2];
    const float* Wb    = (const float*)d_in[3];
    const float* Wih_f = (const float*)d_in[4];
    const float* Whh_f = (const float*)d_in[5];
    const float* bih_f = (const float*)d_in[6];
    const float* bhh_f = (const float*)d_in[7];
    const float* Wih_b = (const float*)d_in[8];
    const float* Whh_b = (const float*)d_in[9];
    const float* bih_b = (const float*)d_in[10];
    const float* bhh_b = (const float*)d_in[11];
    const float* linW  = (const float*)d_in[12];
    const float* linb  = (const float*)d_in[13];
    const int* node_tokens = (const int*)d_in[14];
    const int* doc_tokens  = (const int*)d_in[15];
    float* out = (float*)d_out;

    cudaFuncSetAttribute(k1_stmt, cudaFuncAttributeMaxDynamicSharedMemorySize, K1_DYN);
    cudaFuncSetAttribute(k1b_gi,  cudaFuncAttributeMaxDynamicSharedMemorySize, K1B_DYN);

    k1_stmt<<<148, 512, K1_DYN>>>(emb, Wc, bc, node_tokens);
    k1b_gi<<<144, 512, K1B_DYN>>>(Wih_f, Wih_b, bih_f, bih_b);
    k2_gru<<<BB * 2, 384>>>(Whh_f, bhh_f, Whh_b, bhh_b);
    k3_out<<<BB, 256>>>(emb, Wb, linW, linb, doc_tokens, out);
}

// round 14
// speedup vs baseline: 3.0787x; 1.0394x over previous
#include <cuda_runtime.h>
#include <cuda_fp16.h>
#include <math.h>
#include <stdint.h>

#define TS 8192
#define BB 64
#define LL 128
#define DLN 20
#define TP 272      // fp16 tile pitch in BYTES (136 halves)
#define SP 132      // fp32 stage pitch in floats

typedef unsigned long long ull;

// ---------------- scratch (device globals; no allocation allowed) ----------
__device__ float g_gi[TS * 768];                     // 25 MB
__device__ float g_pooled[BB * 256];
__device__ __align__(16) __half g_Af[TS * 128];      // stmt_h, fp16

// subtree sizes of the 32-node binary heap
__constant__ float c_cszf[32] = {32,16,15,8,7,7,7,4,3,3,3,3,3,3,3,2,
                                 1,1,1,1,1,1,1,1,1,1,1,1,1,1,1,1};

// ---------------- helpers ---------------------------------------------------
__device__ __forceinline__ uint32_t s2u(const void* p){
    uint32_t a;
    asm("{ .reg .u64 t; cvta.to.shared.u64 t, %1; cvt.u32.u64 %0, t; }" : "=r"(a) : "l"(p));
    return a;
}
__device__ __forceinline__ void ldsm4(uint32_t addr, uint32_t r[4]){
    asm volatile("ldmatrix.sync.aligned.m8n8.x4.shared.b16 {%0,%1,%2,%3}, [%4];"
        : "=r"(r[0]), "=r"(r[1]), "=r"(r[2]), "=r"(r[3]) : "r"(addr));
}
__device__ __forceinline__ void mma_f16(float d[4], const uint32_t a[4], uint32_t b0, uint32_t b1){
    asm volatile("mma.sync.aligned.m16n8k16.row.col.f32.f16.f16.f32 "
        "{%0,%1,%2,%3}, {%4,%5,%6,%7}, {%8,%9}, {%0,%1,%2,%3};"
        : "+f"(d[0]), "+f"(d[1]), "+f"(d[2]), "+f"(d[3])
        : "r"(a[0]), "r"(a[1]), "r"(a[2]), "r"(a[3]), "r"(b0), "r"(b1));
}
__device__ __forceinline__ float4 f4add(float4 a, float4 b){
    return make_float4(a.x + b.x, a.y + b.y, a.z + b.z, a.w + b.w);
}
__device__ __forceinline__ void cpa16(uint32_t dst, const void* src){
    asm volatile("cp.async.cg.shared.global [%0], [%1], 16;"
        :: "r"(dst), "l"(__cvta_generic_to_global(src)) : "memory");
}
#define CP_COMMIT() asm volatile("cp.async.commit_group;" ::: "memory")
#define CP_WAIT0()  asm volatile("cp.async.wait_group 0;" ::: "memory")

// smem layouts (byte offsets from aligned base). One 128x136 fp16 tile = 34816 B.
// K1:  A | B | stage
#define K1_OFF_A   0
#define K1_OFF_B   34816
#define K1_OFF_STG 69632                 // float[128][132] = 67584 B
#define K1_DYN  (1024 + 69632 + 67584)
// K1b: B | A0 | A1
#define K1B_OFF_B  0
#define K1B_OFF_A0 34816
#define K1B_OFF_A1 69632
#define K1B_DYN (1024 + 104448)
// K3: Wb staged in dynamic smem
#define K3_DYN (128 * 128 * 4)

// 128x64x128 fp16 1-term GEMM slice: warp (wr, wc) does rows 16*wr..+15,
// cols 64*wc..+63 (8 n-tiles).
__device__ __forceinline__ void gemm_tile8_1t(
    uint32_t sA, uint32_t sB,
    int wr, int wc, int lane, float acc[8][4])
{
    const uint32_t aOff = (uint32_t)(((lane & 15) + 16 * wr) * TP + ((lane >> 4) << 4));
    const uint32_t bOff = (uint32_t)((64 * wc + ((lane >> 4) << 3) + (lane & 7)) * TP
                                     + (((lane >> 3) & 1) << 4));
    #pragma unroll
    for (int ks = 0; ks < 8; ks++) {
        const uint32_t ko = ks * 32;          // 16 halves = 32 B
        uint32_t a[4];
        ldsm4(sA + aOff + ko, a);
        uint32_t bP = sB + bOff + ko;
        #pragma unroll
        for (int p = 0; p < 4; p++) {
            uint32_t bh[4];
            ldsm4(bP, bh);
            mma_f16(acc[2 * p],     a, bh[0], bh[1]);
            mma_f16(acc[2 * p + 1], a, bh[2], bh[3]);
            bP += 16 * TP;
        }
    }
}

// convert a 128x128 fp32 weight block (row-major, gmem) into fp16 smem tile
__device__ __forceinline__ void conv_w_tile(char* dst, const float* __restrict__ src, int t){
    #pragma unroll
    for (int i = 0; i < 8; i++) {
        int idx = i * 512 + t;
        int j = idx >> 5, c4 = idx & 31;
        float4 v = *(const float4*)(src + j * 128 + c4 * 4);
        __half2 h0, h1;
        h0.x = __float2half_rn(v.x); h0.y = __float2half_rn(v.y);
        h1.x = __float2half_rn(v.z); h1.y = __float2half_rn(v.w);
        *(__half2*)(dst + j * TP + c4 * 8)     = h0;
        *(__half2*)(dst + j * TP + c4 * 8 + 4) = h1;
    }
}

// issue cp.async gather of 128 embedding rows (512B each) into stage
__device__ __forceinline__ void gather_pref(
    uint32_t stg_u, const float* __restrict__ emb, const int* tk_s, int t)
{
    #pragma unroll
    for (int i = 0; i < 8; i++) {
        int idx = i * 512 + t;
        int row = idx >> 5, ch = idx & 31;
        cpa16(stg_u + (uint32_t)(row * (SP * 4) + ch * 16),
              emb + (size_t)tk_s[row] * 128 + ch * 4);
    }
    CP_COMMIT();
}

// ---------------------------------------------------------------------------
// K1: persistent (grid 148, 512 thr). Per tile (4 statements): prefetched
//     gather -> tree reduce (2 barriers) -> fp16 round -> 1-term mma.sync
//     GEMM vs Wc -> shuffle epilogue -> fp16 staging.
// ---------------------------------------------------------------------------
__global__ __launch_bounds__(512) void k1_stmt(
    const float* __restrict__ emb, const float* __restrict__ Wc,
    const float* __restrict__ bc, const int* __restrict__ toks_g)
{
    extern __shared__ char smraw[];
    __shared__ int tkA[128], tkB[128];
    __shared__ float bcs[128];
    __shared__ float epi[1024];

    const int t = threadIdx.x, w = t >> 5, lane = t & 31;
    const int wr = w & 7, wc = w >> 3;
    const uint32_t rawu = s2u(smraw);
    const uint32_t alu = (rawu + 1023u) & ~1023u;
    char* base = smraw + (alu - rawu);
    float* stg = (float*)(base + K1_OFF_STG);
    float4* As4 = (float4*)stg;
    const uint32_t stg_u = alu + K1_OFF_STG;

    if (t < 128) { bcs[t] = bc[t]; tkA[t] = toks_g[blockIdx.x * 128 + t] + 1; }
    __syncthreads();
    gather_pref(stg_u, emb, tkA, t);
    if ((int)blockIdx.x + 148 < 2048 && t < 128)
        tkB[t] = toks_g[(blockIdx.x + 148) * 128 + t] + 1;

    // Wc fp16 tile once (converted in-CTA from gmem)
    conv_w_tile(base + K1_OFF_B, Wc, t);

    int jpar = 0;
    for (int tile = blockIdx.x; tile < 2048; tile += 148, jpar ^= 1) {
        CP_WAIT0();
        __syncthreads();

        // ---- tree reduce. Pass A: L4 fused into p=7 task + L3 (p=7..14) ----
        #pragma unroll
        for (int i = 0; i < 2; i++) {
            int idx = i * 512 + t;
            int k4 = idx & 31, q = idx >> 5, tt = q & 3, p = 7 + (q >> 2);
            int rb = tt * 32;
            if (p == 7) {
                float4 a15 = f4add(As4[(rb + 15) * 33 + k4], As4[(rb + 31) * 33 + k4]);
                As4[(rb + 15) * 33 + k4] = a15;
                As4[(rb + 7) * 33 + k4] = f4add(As4[(rb + 7) * 33 + k4],
                                          f4add(a15, As4[(rb + 16) * 33 + k4]));
            } else {
                As4[(rb + p) * 33 + k4] = f4add(As4[(rb + p) * 33 + k4],
                    f4add(As4[(rb + 2 * p + 1) * 33 + k4], As4[(rb + 2 * p + 2) * 33 + k4]));
            }
        }
        __syncthreads();
        // ---- Pass B: L2+L1+L0 fused per (stmt, k4) column, register chain ----
        if (t < 128) {
            int tt = t >> 5, k4 = t & 31;
            int rb = tt * 32;
            #define AV(p) As4[(rb + (p)) * 33 + k4]
            float4 a3 = f4add(AV(3), f4add(AV(7),  AV(8)));  AV(3) = a3;
            float4 a4 = f4add(AV(4), f4add(AV(9),  AV(10))); AV(4) = a4;
            float4 a5 = f4add(AV(5), f4add(AV(11), AV(12))); AV(5) = a5;
            float4 a6 = f4add(AV(6), f4add(AV(13), AV(14))); AV(6) = a6;
            float4 a1 = f4add(AV(1), f4add(a3, a4)); AV(1) = a1;
            float4 a2 = f4add(AV(2), f4add(a5, a6)); AV(2) = a2;
            AV(0) = f4add(AV(0), f4add(a1, a2));
            #undef AV
        }
        __syncthreads();

        // ---- fp32 -> fp16 A tile (single rounding) ----
        #pragma unroll
        for (int i = 0; i < 16; i++) {
            int idx = i * 512 + t;
            int row = idx >> 6, c2 = idx & 63;
            float2 v = *(const float2*)(stg + row * SP + c2 * 2);
            __half2 hh;
            hh.x = __float2half_rn(v.x);
            hh.y = __float2half_rn(v.y);
            *(__half2*)(base + K1_OFF_A + row * TP + c2 * 4) = hh;
        }
        __syncthreads();

        // ---- prefetch next tile's gather into (now free) stage ----
        int nxt = tile + 148;
        if (nxt < 2048) gather_pref(stg_u, emb, jpar ? tkA : tkB, t);
        if (nxt + 148 < 2048 && t < 128)
            (jpar ? tkB : tkA)[t] = toks_g[(nxt + 148) * 128 + t] + 1;

        // ---- GEMM (16 warps: wr x wc), 1-term fp16 ----
        float acc[8][4];
        #pragma unroll
        for (int n = 0; n < 8; n++)
            #pragma unroll
            for (int c = 0; c < 4; c++) acc[n][c] = 0.f;
        gemm_tile8_1t(alu + K1_OFF_A, alu + K1_OFF_B, wr, wc, lane, acc);

        // ---- shuffle epilogue: max over 32 nodes of acc + csz*bc, relu ----
        const int rr0 = (wr & 1) * 16 + (lane >> 2);
        const float cz0 = c_cszf[rr0], cz1 = c_cszf[rr0 + 8];
        #pragma unroll
        for (int nt = 0; nt < 8; nt++) {
            int c0 = 64 * wc + nt * 8 + 2 * (lane & 3);
            float b0 = bcs[c0], b1 = bcs[c0 + 1];
            float m0 = fmaxf(acc[nt][0] + cz0 * b0, acc[nt][2] + cz1 * b0);
            float m1 = fmaxf(acc[nt][1] + cz0 * b1, acc[nt][3] + cz1 * b1);
            #pragma unroll
            for (int o = 4; o <= 16; o <<= 1) {
                m0 = fmaxf(m0, __shfl_xor_sync(0xffffffffu, m0, o));
                m1 = fmaxf(m1, __shfl_xor_sync(0xffffffffu, m1, o));
            }
            if ((lane >> 2) == 0) { epi[wr * 128 + c0] = m0; epi[wr * 128 + c0 + 1] = m1; }
        }
        __syncthreads();
        {
            int st = t >> 7, col = t & 127;
            float m = fmaxf(fmaxf(epi[(2 * st) * 128 + col], epi[(2 * st + 1) * 128 + col]), 0.f);
            g_Af[(tile * 4 + st) * 128 + col] = __float2half_rn(m);
        }
        __syncthreads();
    }
}

// ---------------------------------------------------------------------------
// K1b: persistent gi GEMM (512 thr). 144 CTAs = (24 rb-groups x 6 gate-blocks).
//      B converted once from gmem; fp16 A double-buffered via cp.async.
//      Adds bih bias (pre-folded out of k2).
// ---------------------------------------------------------------------------
__device__ __forceinline__ void k1b_prefA(uint32_t dstA, int rb, int t){
    const float4* sa = (const float4*)(g_Af + rb * 16384);
    #pragma unroll
    for (int i = 0; i < 4; i++) {
        int idx = i * 512 + t, jj = idx >> 4, sg = idx & 15;
        cpa16(dstA + jj * TP + sg * 16, sa + idx);
    }
    CP_COMMIT();
}

__global__ __launch_bounds__(512) void k1b_gi(
    const float* __restrict__ Wih_f, const float* __restrict__ Wih_b,
    const float* __restrict__ bih_f, const float* __restrict__ bih_b)
{
    extern __shared__ char smraw[];
    __shared__ float bias_s[128];
    const int t = threadIdx.x, w = t >> 5, lane = t & 31;
    const int wr = w & 7, wc = w >> 3;
    const int by = blockIdx.x % 6, rb0 = blockIdx.x / 6;
    const uint32_t rawu = s2u(smraw);
    const uint32_t alu = (rawu + 1023u) & ~1023u;
    char* base = smraw + (alu - rawu);

    if (t < 128) bias_s[t] = (by < 3) ? bih_f[by * 128 + t] : bih_b[(by - 3) * 128 + t];

    k1b_prefA(alu + K1B_OFF_A0, rb0, t);

    // B gate-block once (converted in-CTA from gmem)
    {
        const float* Wsel = (by < 3) ? (Wih_f + (size_t)by * 128 * 128)
                                     : (Wih_b + (size_t)(by - 3) * 128 * 128);
        conv_w_tile(base + K1B_OFF_B, Wsel, t);
    }

    int pb = 0;
    for (int rb = rb0; rb < 64; rb += 24, pb ^= 1) {
        CP_WAIT0();
        __syncthreads();
        if (rb + 24 < 64)
            k1b_prefA(alu + (pb ? K1B_OFF_A0 : K1B_OFF_A1), rb + 24, t);

        float acc[8][4];
        #pragma unroll
        for (int n = 0; n < 8; n++)
            #pragma unroll
            for (int c = 0; c < 4; c++) acc[n][c] = 0.f;
        gemm_tile8_1t(alu + (pb ? K1B_OFF_A1 : K1B_OFF_A0),
                      alu + K1B_OFF_B, wr, wc, lane, acc);

        const int row = rb * 128 + 16 * wr + (lane >> 2);
        float* o0 = g_gi + (size_t)row * 768 + by * 128 + 64 * wc;
        float* o1 = o0 + 8 * 768;
        const int cb = (lane & 3) * 2;
        #pragma unroll
        for (int nt = 0; nt < 8; nt++) {
            float b0 = bias_s[64 * wc + nt * 8 + cb];
            float b1 = bias_s[64 * wc + nt * 8 + cb + 1];
            *(float2*)(o0 + nt * 8 + cb) = make_float2(acc[nt][0] + b0, acc[nt][1] + b1);
            *(float2*)(o1 + nt * 8 + cb) = make_float2(acc[nt][2] + b0, acc[nt][3] + b1);
        }
    }
}

// ---------------------------------------------------------------------------
__device__ __forceinline__ void ffma2(ull& d, ull a, ull b){
    asm("fma.rn.f32x2 %0, %1, %2, %0;" : "+l"(d) : "l"(a), "l"(b));
}
__device__ __forceinline__ float2 ull2f2(ull v){
    float2 f; asm("mov.b64 {%0, %1}, %2;" : "=f"(f.x), "=f"(f.y) : "l"(v)); return f;
}

// ---------------------------------------------------------------------------
// K2: GRU recurrence. 128 CTAs, one per (batch, dir). 384 threads: thread
//     (g, tt) owns rows 2tt, 2tt+1 for h-half g. gi read directly via LDG
//     by the gate threads at loop top (covered by the matvec).
// ---------------------------------------------------------------------------
__global__ __launch_bounds__(384) void k2_gru(
    const float* __restrict__ Whh_f, const float* __restrict__ bhh_f,
    const float* __restrict__ Whh_b, const float* __restrict__ bhh_b)
{
    __shared__ float h_s[128];
    __shared__ float part[768];              // [half][row]
    __shared__ float bhh_s[384];

    const int t = threadIdx.x;
    const int b = blockIdx.x >> 1, dir = blockIdx.x & 1;
    const float* Whh = dir ? Whh_b : Whh_f;
    const float* bhh = dir ? bhh_b : bhh_f;

    const int g  = (t < 192) ? 0 : 1;
    const int tt = (t < 192) ? t : t - 192;
    const int j0 = 2 * tt;                   // rows j0, j0+1

    ull w0[32], w1[32];                      // 2 rows x 64 cols fp32
    {
        const ulonglong2* p0 = (const ulonglong2*)(Whh + (size_t)j0 * 128 + g * 64);
        const ulonglong2* p1 = (const ulonglong2*)(Whh + (size_t)(j0 + 1) * 128 + g * 64);
        #pragma unroll
        for (int i = 0; i < 16; i++) {
            ulonglong2 v0 = p0[i]; w0[2*i] = v0.x; w0[2*i+1] = v0.y;
            ulonglong2 v1 = p1[i]; w1[2*i] = v1.x; w1[2*i+1] = v1.y;
        }
    }
    bhh_s[t] = bhh[t];
    if (t < 128) h_s[t] = 0.f;

    const float* gbase = g_gi + (size_t)(b * LL + (dir ? LL - 1 : 0)) * 768 + dir * 384;
    const int stp = dir ? -768 : 768;
    __syncthreads();

    float hmax = -3e38f;
    for (int l = 0; l < LL; l++) {
        float gr, gz, gn;
        if (t < 128) {
            const float* gp = gbase + (ptrdiff_t)l * stp;
            gr = __ldg(gp + t);
            gz = __ldg(gp + 128 + t);
            gn = __ldg(gp + 256 + t);
        }

        ull a00 = 0, a01 = 0, a10 = 0, a11 = 0;
        const ulonglong2* hp = (const ulonglong2*)(h_s + g * 64);
        #pragma unroll
        for (int i = 0; i < 16; i++) {
            ulonglong2 hv = hp[i];
            ffma2(a00, w0[2*i],     hv.x);
            ffma2(a01, w0[2*i + 1], hv.y);
            ffma2(a10, w1[2*i],     hv.x);
            ffma2(a11, w1[2*i + 1], hv.y);
        }
        float2 f00 = ull2f2(a00), f01 = ull2f2(a01);
        float2 f10 = ull2f2(a10), f11 = ull2f2(a11);
        *(float2*)(part + g * 384 + j0) = make_float2(
            (f00.x + f00.y) + (f01.x + f01.y),
            (f10.x + f10.y) + (f11.x + f11.y));
        __syncthreads();

        if (t < 128) {
            float ghr = part[t]       + part[384 + t] + bhh_s[t];
            float ghz = part[128 + t] + part[512 + t] + bhh_s[128 + t];
            float ghn = part[256 + t] + part[640 + t] + bhh_s[256 + t];
            float r = __fdividef(1.f, 1.f + __expf(-(gr + ghr)));
            float z = __fdividef(1.f, 1.f + __expf(-(gz + ghz)));
            float y = gn + r * ghn;
            float n = 1.f - __fdividef(2.f, __expf(2.f * y) + 1.f);
            float hnew = (1.f - z) * n + z * h_s[t];
            h_s[t] = hnew;
            hmax = fmaxf(hmax, hnew);
        }
        __syncthreads();
    }
    if (t < 128) g_pooled[b * 256 + dir * 128 + t] = hmax;
}

// ---------------------------------------------------------------------------
// K3: grid 128 = (batch, half). half 1: lvec only. half 0: doc attention with
//     Wb staged to smem concurrently with demb (one memory phase), warp-
//     parallel softmax.
// ---------------------------------------------------------------------------
__global__ __launch_bounds__(256) void k3_out(
    const float* __restrict__ emb, const float* __restrict__ Wb,
    const float* __restrict__ linW, const float* __restrict__ linb,
    const int* __restrict__ doc, float* __restrict__ out)
{
    extern __shared__ float Wbs[];           // 128*128 floats (rvec CTAs)
    __shared__ float demb[DLN * 128];
    __shared__ float h0[128];
    __shared__ float u[128];
    __shared__ float exs[32];
    __shared__ float inv_s;
    __shared__ float pool[256];
    __shared__ int dti[DLN];

    const int t = threadIdx.x, wid = t >> 5, lane = t & 31;
    const int b = blockIdx.x >> 1, half = blockIdx.x & 1;

    if (half) {
        // ---- lvec: pooled @ linW^T + linb ----
        pool[t] = g_pooled[b * 256 + t];
        __syncthreads();
        #pragma unroll
        for (int rr = 0; rr < 16; rr++) {
            int row = wid * 16 + rr;
            const float* wr = linW + row * 256;
            float s = 0.f;
            #pragma unroll
            for (int q = 0; q < 8; q++) s += wr[lane + 32 * q] * pool[lane + 32 * q];
            #pragma unroll
            for (int o = 16; o > 0; o >>= 1) s += __shfl_xor_sync(0xffffffffu, s, o);
            if (lane == 0) out[b * 128 + row] = s + linb[row];
        }
        return;
    }

    // ---- rvec: doc attention ----
    if (t < DLN) dti[t] = doc[b * DLN + t] + 1;
    __syncthreads();
    // one combined memory phase: Wb (64 KB) + demb (10 KB)
    #pragma unroll
    for (int i = 0; i < 16; i++) {
        int idx = i * 256 + t;
        *(float4*)(Wbs + idx * 4) = *(const float4*)(Wb + idx * 4);
    }
    #pragma unroll
    for (int i = 0; i < 3; i++) {
        int idx = i * 256 + t;
        if (idx < DLN * 32) {
            int l = idx >> 5, c4 = idx & 31;
            *(float4*)(demb + l * 128 + c4 * 4) =
                *(const float4*)(emb + (size_t)dti[l] * 128 + c4 * 4);
        }
    }
    __syncthreads();

    if (t < 128) {
        float s = 0.f;
        #pragma unroll
        for (int l = 0; l < DLN; l++) s += demb[l * 128 + t];
        h0[t] = s * (1.f / (float)DLN);
    }
    __syncthreads();

    // u = Wb @ h0 from smem (16 rows per warp)
    #pragma unroll
    for (int rr = 0; rr < 16; rr++) {
        int row = wid * 16 + rr;
        const float* wr = Wbs + row * 128;
        float s = wr[lane] * h0[lane] + wr[lane + 32] * h0[lane + 32]
                + wr[lane + 64] * h0[lane + 64] + wr[lane + 96] * h0[lane + 96];
        #pragma unroll
        for (int o = 16; o > 0; o >>= 1) s += __shfl_xor_sync(0xffffffffu, s, o);
        if (lane == 0) u[row] = s;
    }
    __syncthreads();

    // scores
    for (int l = wid; l < DLN; l += 8) {
        const float* dr = demb + l * 128;
        float s = dr[lane] * u[lane] + dr[lane + 32] * u[lane + 32]
                + dr[lane + 64] * u[lane + 64] + dr[lane + 96] * u[lane + 96];
        #pragma unroll
        for (int o = 16; o > 0; o >>= 1) s += __shfl_xor_sync(0xffffffffu, s, o);
        if (lane == 0) exs[l] = s;
    }
    __syncthreads();

    // warp-parallel softmax (warp 0)
    if (wid == 0) {
        float v = (lane < DLN) ? exs[lane] : -3e38f;
        float m = v;
        #pragma unroll
        for (int o = 16; o > 0; o >>= 1) m = fmaxf(m, __shfl_xor_sync(0xffffffffu, m, o));
        float e = (lane < DLN) ? expf(v - m) : 0.f;
        float ssum = e;
        #pragma unroll
        for (int o = 16; o > 0; o >>= 1) ssum += __shfl_xor_sync(0xffffffffu, ssum, o);
        if (lane < DLN) exs[lane] = e;
        if (lane == 0) inv_s = 1.f / ssum;
    }
    __syncthreads();

    if (t < 128) {
        float rv = 0.f;
        #pragma unroll
        for (int l = 0; l < DLN; l++) rv += exs[l] * demb[l * 128 + t];
        out[BB * 128 + b * 128 + t] = rv * inv_s;
    }
}

// ---------------------------------------------------------------------------
extern "C" void kernel_launch(void* const* d_in, const int* in_sizes, int n_in,
                              void* d_out, int out_size)
{
    const float* emb   = (const float*)d_in[0];
    const float* Wc    = (const float*)d_in[1];
    const float* bc    = (const float*)d_in[2];
    const float* Wb    = (const float*)d_in[3];
    const float* Wih_f = (const float*)d_in[4];
    const float* Whh_f = (const float*)d_in[5];
    const float* bih_f = (const float*)d_in[6];
    const float* bhh_f = (const float*)d_in[7];
    const float* Wih_b = (const float*)d_in[8];
    const float* Whh_b = (const float*)d_in[9];
    const float* bih_b = (const float*)d_in[10];
    const float* bhh_b = (const float*)d_in[11];
    const float* linW  = (const float*)d_in[12];
    const float* linb  = (const float*)d_in[13];
    const int* node_tokens = (const int*)d_in[14];
    const int* doc_tokens  = (const int*)d_in[15];
    float* out = (float*)d_out;

    cudaFuncSetAttribute(k1_stmt, cudaFuncAttributeMaxDynamicSharedMemorySize, K1_DYN);
    cudaFuncSetAttribute(k1b_gi,  cudaFuncAttributeMaxDynamicSharedMemorySize, K1B_DYN);
    cudaFuncSetAttribute(k3_out,  cudaFuncAttributeMaxDynamicSharedMemorySize, K3_DYN);

    k1_stmt<<<148, 512, K1_DYN>>>(emb, Wc, bc, node_tokens);
    k1b_gi<<<144, 512, K1B_DYN>>>(Wih_f, Wih_b, bih_f, bih_b);
    k2_gru<<<BB * 2, 384>>>(Whh_f, bhh_f, Whh_b, bhh_b);
    k3_out<<<BB * 2, 256, K3_DYN>>>(emb, Wb, linW, linb, doc_tokens, out);
}